// round 1
// baseline (speedup 1.0000x reference)
#include <cuda_runtime.h>
#include <math.h>

#define BB  4
#define CCH 256
#define CQ  32
#define NN  4096

// Scratch (device globals: no allocation allowed in kernel_launch)
__device__ float g_q[BB * NN * CQ];    // [b][m][32]
__device__ float g_k[BB * NN * CQ];    // [b][n][32]
__device__ float g_v[BB * NN * CCH];   // [b][n][256]
__device__ float g_o[BB * NN * CCH];   // [b][m][256]

// ---------------------------------------------------------------------------
// Kernel 1: fused QKV projection.
// Virtual weight matrix rows 0..319: [Wq(32); Wk(32); Wv(256)], K=256.
// Output tile 64(out) x 64(pix), 4x4 micro-tile per thread (256 threads).
// ---------------------------------------------------------------------------
__global__ __launch_bounds__(256) void qkv_kernel(
    const float* __restrict__ x,
    const float* __restrict__ Wq, const float* __restrict__ bq,
    const float* __restrict__ Wk, const float* __restrict__ bk,
    const float* __restrict__ Wv, const float* __restrict__ bv)
{
    __shared__ float Ws[32][68];
    __shared__ float Xs[32][68];

    const int b  = blockIdx.z;
    const int o0 = blockIdx.x * 64;   // 0..256 step 64 (5 tiles over 320)
    const int p0 = blockIdx.y * 64;
    const int t  = threadIdx.x;
    const int tx = t & 15, ty = t >> 4;

    const float* xb = x + (size_t)b * CCH * NN;

    float acc[4][4];
#pragma unroll
    for (int i = 0; i < 4; i++)
#pragma unroll
        for (int j = 0; j < 4; j++) acc[i][j] = 0.f;

    for (int kc = 0; kc < CCH; kc += 32) {
        // Load W tile (transposed into [k][o])
        {
            const int oo = t >> 2;            // 0..63
            const int kk = (t & 3) * 8;       // 0,8,16,24
            const int o  = o0 + oo;
            const float* wrow;
            if (o < 32)       wrow = Wq + (size_t)o * CCH;
            else if (o < 64)  wrow = Wk + (size_t)(o - 32) * CCH;
            else              wrow = Wv + (size_t)(o - 64) * CCH;
            float4 w0 = *(const float4*)(wrow + kc + kk);
            float4 w1 = *(const float4*)(wrow + kc + kk + 4);
            float w[8] = {w0.x, w0.y, w0.z, w0.w, w1.x, w1.y, w1.z, w1.w};
#pragma unroll
            for (int i = 0; i < 8; i++) Ws[kk + i][oo] = w[i];
        }
        // Load X tile ([k][p], source rows contiguous in p)
        {
            const int kk = t >> 3;            // 0..31
            const int pp = (t & 7) * 8;       // 0..56
            const float* xr = xb + (size_t)(kc + kk) * NN + p0 + pp;
            *(float4*)&Xs[kk][pp]     = *(const float4*)(xr);
            *(float4*)&Xs[kk][pp + 4] = *(const float4*)(xr + 4);
        }
        __syncthreads();

#pragma unroll
        for (int kk = 0; kk < 32; kk++) {
            float4 a4 = *(const float4*)&Ws[kk][ty * 4];
            float4 b4 = *(const float4*)&Xs[kk][tx * 4];
            float a[4] = {a4.x, a4.y, a4.z, a4.w};
            float bx[4] = {b4.x, b4.y, b4.z, b4.w};
#pragma unroll
            for (int i = 0; i < 4; i++)
#pragma unroll
                for (int j = 0; j < 4; j++) acc[i][j] += a[i] * bx[j];
        }
        __syncthreads();
    }

    // Epilogue: write [p][o] with float4 over o (o-base multiple of 4; the
    // q/k/v boundaries (32, 64) are multiples of 4, so a micro-column never
    // straddles regions).
    const int ov = o0 + ty * 4;
    float* base;
    int ld, oloc;
    float4 bias4;
    if (ov < 32) {
        base = g_q + (size_t)b * NN * CQ; ld = CQ; oloc = ov;
        bias4 = *(const float4*)(bq + ov);
    } else if (ov < 64) {
        base = g_k + (size_t)b * NN * CQ; ld = CQ; oloc = ov - 32;
        bias4 = *(const float4*)(bk + (ov - 32));
    } else {
        base = g_v + (size_t)b * NN * CCH; ld = CCH; oloc = ov - 64;
        bias4 = *(const float4*)(bv + (ov - 64));
    }
#pragma unroll
    for (int j = 0; j < 4; j++) {
        const int p = p0 + tx * 4 + j;
        float4 v;
        v.x = acc[0][j] + bias4.x;
        v.y = acc[1][j] + bias4.y;
        v.z = acc[2][j] + bias4.z;
        v.w = acc[3][j] + bias4.w;
        *(float4*)(base + (size_t)p * ld + oloc) = v;
    }
}

// ---------------------------------------------------------------------------
// Kernel 2: flash attention.  Block = 64 queries x full N loop (Tn=64).
// 256 threads = 8 warps.
//  Score phase mapping: tx = t&15 -> 4 n-cols, ty = t>>4 -> 4 m-rows.
//  PV mapping: warp w owns m-rows 8w..8w+7, lane l owns channels 8l..8l+7.
// Online softmax state (row max / row sum) replicated across the 16 threads
// of each row group; scale factors communicated via smem.
// ---------------------------------------------------------------------------
__global__ __launch_bounds__(256) void attn_kernel()
{
    extern __shared__ float sm[];
    float* qs  = sm;                    // [32][68]  (c-major, transposed)
    float* ks  = qs  + 32 * 68;         // [32][68]
    float* vsm = ks  + 32 * 68;         // [64][256]
    float* ps  = vsm + 64 * 256;        // [64][68]  P[n][m]
    float* rs  = ps  + 64 * 68;         // [64] row scale / inv-sum

    const int b    = blockIdx.y;
    const int m0   = blockIdx.x * 64;
    const int t    = threadIdx.x;
    const int lane = t & 31;
    const int wrp  = t >> 5;
    const int tx   = t & 15, ty = t >> 4;

    // Load Q tile transposed: qs[c][m]
    {
#pragma unroll
        for (int r = 0; r < 8; r++) {
            const int row = r * 8 + wrp;
            qs[lane * 68 + row] = g_q[((size_t)b * NN + m0 + row) * CQ + lane];
        }
    }

    float acc[8][8];
#pragma unroll
    for (int i = 0; i < 8; i++)
#pragma unroll
        for (int j = 0; j < 8; j++) acc[i][j] = 0.f;

    float rmax[4], rsum[4];
#pragma unroll
    for (int r = 0; r < 4; r++) { rmax[r] = -INFINITY; rsum[r] = 0.f; }

    for (int nt = 0; nt < 64; nt++) {
        const int n0 = nt * 64;
        // Load K tile transposed
#pragma unroll
        for (int r = 0; r < 8; r++) {
            const int row = r * 8 + wrp;
            ks[lane * 68 + row] = g_k[((size_t)b * NN + n0 + row) * CQ + lane];
        }
        // Load V tile (direct copy, rows contiguous)
        {
            const float4* src = (const float4*)(g_v + ((size_t)b * NN + n0) * CCH);
            float4* dst = (float4*)vsm;
#pragma unroll
            for (int r = 0; r < 16; r++) dst[r * 256 + t] = src[r * 256 + t];
        }
        __syncthreads();

        // --- Scores: 4x4 micro-tile, K-dim 32 ---
        float s[4][4];
#pragma unroll
        for (int i = 0; i < 4; i++)
#pragma unroll
            for (int j = 0; j < 4; j++) s[i][j] = 0.f;
#pragma unroll
        for (int c = 0; c < 32; c++) {
            float4 q4 = *(const float4*)(qs + c * 68 + ty * 4);
            float4 k4 = *(const float4*)(ks + c * 68 + tx * 4);
            float qa[4] = {q4.x, q4.y, q4.z, q4.w};
            float ka[4] = {k4.x, k4.y, k4.z, k4.w};
#pragma unroll
            for (int i = 0; i < 4; i++)
#pragma unroll
                for (int j = 0; j < 4; j++) s[i][j] += qa[i] * ka[j];
        }

        // --- Online softmax (per row group of 16 threads, same warp half) ---
#pragma unroll
        for (int r = 0; r < 4; r++) {
            float tm = fmaxf(fmaxf(s[r][0], s[r][1]), fmaxf(s[r][2], s[r][3]));
#pragma unroll
            for (int msk = 1; msk < 16; msk <<= 1)
                tm = fmaxf(tm, __shfl_xor_sync(0xffffffffu, tm, msk));
            const float nm = fmaxf(rmax[r], tm);
            const float sc = __expf(rmax[r] - nm);
            rmax[r] = nm;
            float p0 = __expf(s[r][0] - nm);
            float p1 = __expf(s[r][1] - nm);
            float p2 = __expf(s[r][2] - nm);
            float p3 = __expf(s[r][3] - nm);
            s[r][0] = p0; s[r][1] = p1; s[r][2] = p2; s[r][3] = p3;
            float tsum = p0 + p1 + p2 + p3;
#pragma unroll
            for (int msk = 1; msk < 16; msk <<= 1)
                tsum += __shfl_xor_sync(0xffffffffu, tsum, msk);
            rsum[r] = rsum[r] * sc + tsum;
            if (tx == 0) rs[ty * 4 + r] = sc;
        }
        // Write P transposed: ps[n][m]
#pragma unroll
        for (int j = 0; j < 4; j++) {
            float4 pv = make_float4(s[0][j], s[1][j], s[2][j], s[3][j]);
            *(float4*)(ps + (tx * 4 + j) * 68 + ty * 4) = pv;
        }
        __syncthreads();

        // --- PV accumulate: 8m x 8c per thread ---
        const int mb = wrp * 8;
#pragma unroll
        for (int i = 0; i < 8; i++) {
            const float sc = rs[mb + i];
#pragma unroll
            for (int j = 0; j < 8; j++) acc[i][j] *= sc;
        }
#pragma unroll 2
        for (int n = 0; n < 64; n++) {
            float4 pa = *(const float4*)(ps + n * 68 + mb);
            float4 pb = *(const float4*)(ps + n * 68 + mb + 4);
            float4 va = *(const float4*)(vsm + n * 256 + lane * 8);
            float4 vb = *(const float4*)(vsm + n * 256 + lane * 8 + 4);
            float pv[8] = {pa.x, pa.y, pa.z, pa.w, pb.x, pb.y, pb.z, pb.w};
            float vv[8] = {va.x, va.y, va.z, va.w, vb.x, vb.y, vb.z, vb.w};
#pragma unroll
            for (int i = 0; i < 8; i++)
#pragma unroll
                for (int j = 0; j < 8; j++) acc[i][j] += pv[i] * vv[j];
        }
        __syncthreads();
    }

    // Finalize: divide by row sums, write out
    if (tx == 0) {
#pragma unroll
        for (int r = 0; r < 4; r++) rs[ty * 4 + r] = 1.0f / rsum[r];
    }
    __syncthreads();
    const int mb = wrp * 8;
#pragma unroll
    for (int i = 0; i < 8; i++) {
        const float inv = rs[mb + i];
        float4 o0, o1;
        o0.x = acc[i][0] * inv; o0.y = acc[i][1] * inv;
        o0.z = acc[i][2] * inv; o0.w = acc[i][3] * inv;
        o1.x = acc[i][4] * inv; o1.y = acc[i][5] * inv;
        o1.z = acc[i][6] * inv; o1.w = acc[i][7] * inv;
        float* dst = g_o + ((size_t)b * NN + m0 + mb + i) * CCH + lane * 8;
        *(float4*)dst       = o0;
        *(float4*)(dst + 4) = o1;
    }
}

// ---------------------------------------------------------------------------
// Kernel 3: output projection y = Wo @ concat(attn_out, x) + bo.
// K = 512: first 256 from g_o ([m][c] layout -> transposed load),
// last 256 from x ([c][m] layout -> direct load).
// ---------------------------------------------------------------------------
__global__ __launch_bounds__(256) void outproj_kernel(
    const float* __restrict__ x,
    const float* __restrict__ Wo, const float* __restrict__ bo,
    float* __restrict__ y)
{
    __shared__ float Ws[32][68];
    __shared__ float Bs[32][68];

    const int b  = blockIdx.z;
    const int o0 = blockIdx.x * 64;
    const int m0 = blockIdx.y * 64;
    const int t  = threadIdx.x;
    const int tx = t & 15, ty = t >> 4;

    float acc[4][4];
#pragma unroll
    for (int i = 0; i < 4; i++)
#pragma unroll
        for (int j = 0; j < 4; j++) acc[i][j] = 0.f;

    for (int k0 = 0; k0 < 2 * CCH; k0 += 32) {
        // W tile
        {
            const int oo = t >> 2;
            const int kk = (t & 3) * 8;
            const float* wr = Wo + (size_t)(o0 + oo) * (2 * CCH) + k0 + kk;
            float4 w0 = *(const float4*)(wr);
            float4 w1 = *(const float4*)(wr + 4);
            float w[8] = {w0.x, w0.y, w0.z, w0.w, w1.x, w1.y, w1.z, w1.w};
#pragma unroll
            for (int i = 0; i < 8; i++) Ws[kk + i][oo] = w[i];
        }
        // B tile
        if (k0 < CCH) {
            const int mm = t >> 2;
            const int kk = (t & 3) * 8;
            const float* sr = g_o + ((size_t)b * NN + m0 + mm) * CCH + k0 + kk;
            float4 b0 = *(const float4*)(sr);
            float4 b1 = *(const float4*)(sr + 4);
            float w[8] = {b0.x, b0.y, b0.z, b0.w, b1.x, b1.y, b1.z, b1.w};
#pragma unroll
            for (int i = 0; i < 8; i++) Bs[kk + i][mm] = w[i];
        } else {
            const int kk = t >> 3;
            const int mm = (t & 7) * 8;
            const float* sr = x + ((size_t)b * CCH + (k0 - CCH + kk)) * NN + m0 + mm;
            *(float4*)&Bs[kk][mm]     = *(const float4*)(sr);
            *(float4*)&Bs[kk][mm + 4] = *(const float4*)(sr + 4);
        }
        __syncthreads();

#pragma unroll
        for (int kk = 0; kk < 32; kk++) {
            float4 a4 = *(const float4*)&Ws[kk][ty * 4];
            float4 b4 = *(const float4*)&Bs[kk][tx * 4];
            float a[4]  = {a4.x, a4.y, a4.z, a4.w};
            float bx[4] = {b4.x, b4.y, b4.z, b4.w};
#pragma unroll
            for (int i = 0; i < 4; i++)
#pragma unroll
                for (int j = 0; j < 4; j++) acc[i][j] += a[i] * bx[j];
        }
        __syncthreads();
    }

    const int ov = o0 + ty * 4;
    const int m  = m0 + tx * 4;
#pragma unroll
    for (int i = 0; i < 4; i++) {
        const float bias = bo[ov + i];
        float4 v;
        v.x = acc[i][0] + bias;
        v.y = acc[i][1] + bias;
        v.z = acc[i][2] + bias;
        v.w = acc[i][3] + bias;
        *(float4*)(y + ((size_t)b * CCH + ov + i) * NN + m) = v;
    }
}

// ---------------------------------------------------------------------------
static const int ATTN_SMEM_BYTES = (32 * 68 * 2 + 64 * 256 + 64 * 68 + 64) * 4;

extern "C" void kernel_launch(void* const* d_in, const int* in_sizes, int n_in,
                              void* d_out, int out_size)
{
    const float* x  = (const float*)d_in[0];
    const float* Wq = (const float*)d_in[1];
    const float* bq = (const float*)d_in[2];
    const float* Wk = (const float*)d_in[3];
    const float* bk = (const float*)d_in[4];
    const float* Wv = (const float*)d_in[5];
    const float* bv = (const float*)d_in[6];
    const float* Wo = (const float*)d_in[7];
    const float* bo = (const float*)d_in[8];
    float* y = (float*)d_out;

    cudaFuncSetAttribute(attn_kernel,
                         cudaFuncAttributeMaxDynamicSharedMemorySize,
                         ATTN_SMEM_BYTES);

    qkv_kernel<<<dim3(5, 64, BB), 256>>>(x, Wq, bq, Wk, bk, Wv, bv);
    attn_kernel<<<dim3(64, BB), 256, ATTN_SMEM_BYTES>>>();
    outproj_kernel<<<dim3(4, 64, BB), 256>>>(x, Wo, bo, y);
}

// round 3
// speedup vs baseline: 2.2568x; 2.2568x over previous
#include <cuda_runtime.h>
#include <cuda_fp16.h>
#include <cstdint>
#include <math.h>

#define BB  4
#define CCH 256
#define CQ  32
#define NN  4096

// Scratch (device globals: no allocation allowed)
__device__ float  g_q[BB * NN * CQ];           // [b][m][32] fp32
__device__ float  g_k[BB * NN * CQ];           // [b][n][32] fp32
__device__ __half g_vh[BB * NN * CCH];         // [b][n][256] fp16
__device__ __half g_cat[BB * NN * 2 * CCH];    // [b][n][512]: [0:256)=attn out, [256:512)=x^T
__device__ __half g_woh[CCH * 2 * CCH];        // Wo fp16 [o][512]

// ---------------- PTX helpers (mma.m16n8k16 f16 + ldmatrix) -----------------
__device__ __forceinline__ unsigned int smaddr(const void* p) {
    return (unsigned int)__cvta_generic_to_shared(p);
}
__device__ __forceinline__ void ldsm_x4(unsigned int& r0, unsigned int& r1,
                                        unsigned int& r2, unsigned int& r3,
                                        unsigned int a) {
    asm volatile("ldmatrix.sync.aligned.m8n8.x4.shared.b16 {%0,%1,%2,%3},[%4];\n"
                 : "=r"(r0), "=r"(r1), "=r"(r2), "=r"(r3) : "r"(a));
}
__device__ __forceinline__ void ldsm_x4t(unsigned int& r0, unsigned int& r1,
                                         unsigned int& r2, unsigned int& r3,
                                         unsigned int a) {
    asm volatile("ldmatrix.sync.aligned.m8n8.x4.trans.shared.b16 {%0,%1,%2,%3},[%4];\n"
                 : "=r"(r0), "=r"(r1), "=r"(r2), "=r"(r3) : "r"(a));
}
__device__ __forceinline__ void mma_f16(float* d, const unsigned int* a,
                                        unsigned int b0, unsigned int b1) {
    asm volatile("mma.sync.aligned.m16n8k16.row.col.f32.f16.f16.f32 "
                 "{%0,%1,%2,%3},{%4,%5,%6,%7},{%8,%9},{%0,%1,%2,%3};\n"
                 : "+f"(d[0]), "+f"(d[1]), "+f"(d[2]), "+f"(d[3])
                 : "r"(a[0]), "r"(a[1]), "r"(a[2]), "r"(a[3]), "r"(b0), "r"(b1));
}

// ---------------------------------------------------------------------------
// Kernel 0a: convert Wo -> fp16
// ---------------------------------------------------------------------------
__global__ void wconv_kernel(const float* __restrict__ Wo) {
    int i = blockIdx.x * blockDim.x + threadIdx.x;   // 131072 exact
    g_woh[i] = __float2half(Wo[i]);
}

// ---------------------------------------------------------------------------
// Kernel 0b: transpose-convert x [b][c][n] -> g_cat[b][n][256 + c] fp16
// ---------------------------------------------------------------------------
__global__ void xpose_kernel(const float* __restrict__ x) {
    __shared__ float ts[32][33];
    const int b = blockIdx.z, n0 = blockIdx.x * 32, c0 = blockIdx.y * 32;
    const int txi = threadIdx.x, tyi = threadIdx.y;   // 32 x 8
#pragma unroll
    for (int i = 0; i < 4; i++) {
        int c = c0 + tyi + i * 8;
        ts[tyi + i * 8][txi] = x[((size_t)b * CCH + c) * NN + n0 + txi];
    }
    __syncthreads();
#pragma unroll
    for (int i = 0; i < 4; i++) {
        int n = n0 + tyi + i * 8;
        g_cat[((size_t)b * NN + n) * 512 + 256 + c0 + txi] =
            __float2half(ts[txi][tyi + i * 8]);
    }
}

// ---------------------------------------------------------------------------
// Kernel 1: fused QKV projection (SIMT fp32; V emitted as fp16)
// ---------------------------------------------------------------------------
__global__ __launch_bounds__(256) void qkv_kernel(
    const float* __restrict__ x,
    const float* __restrict__ Wq, const float* __restrict__ bq,
    const float* __restrict__ Wk, const float* __restrict__ bk,
    const float* __restrict__ Wv, const float* __restrict__ bv)
{
    __shared__ float Ws[32][68];
    __shared__ float Xs[32][68];

    const int b  = blockIdx.z;
    const int o0 = blockIdx.x * 64;
    const int p0 = blockIdx.y * 64;
    const int t  = threadIdx.x;
    const int tx = t & 15, ty = t >> 4;

    const float* xb = x + (size_t)b * CCH * NN;

    float acc[4][4];
#pragma unroll
    for (int i = 0; i < 4; i++)
#pragma unroll
        for (int j = 0; j < 4; j++) acc[i][j] = 0.f;

    for (int kc = 0; kc < CCH; kc += 32) {
        {
            const int oo = t >> 2;
            const int kk = (t & 3) * 8;
            const int o  = o0 + oo;
            const float* wrow;
            if (o < 32)       wrow = Wq + (size_t)o * CCH;
            else if (o < 64)  wrow = Wk + (size_t)(o - 32) * CCH;
            else              wrow = Wv + (size_t)(o - 64) * CCH;
            float4 w0 = *(const float4*)(wrow + kc + kk);
            float4 w1 = *(const float4*)(wrow + kc + kk + 4);
            float w[8] = {w0.x, w0.y, w0.z, w0.w, w1.x, w1.y, w1.z, w1.w};
#pragma unroll
            for (int i = 0; i < 8; i++) Ws[kk + i][oo] = w[i];
        }
        {
            const int kk = t >> 3;
            const int pp = (t & 7) * 8;
            const float* xr = xb + (size_t)(kc + kk) * NN + p0 + pp;
            *(float4*)&Xs[kk][pp]     = *(const float4*)(xr);
            *(float4*)&Xs[kk][pp + 4] = *(const float4*)(xr + 4);
        }
        __syncthreads();

#pragma unroll
        for (int kk = 0; kk < 32; kk++) {
            float4 a4 = *(const float4*)&Ws[kk][ty * 4];
            float4 b4 = *(const float4*)&Xs[kk][tx * 4];
            float a[4]  = {a4.x, a4.y, a4.z, a4.w};
            float bx[4] = {b4.x, b4.y, b4.z, b4.w};
#pragma unroll
            for (int i = 0; i < 4; i++)
#pragma unroll
                for (int j = 0; j < 4; j++) acc[i][j] += a[i] * bx[j];
        }
        __syncthreads();
    }

    const int ov = o0 + ty * 4;
    if (ov < 64) {
        float* base; int oloc; float4 bias4;
        if (ov < 32) { base = g_q + (size_t)b * NN * CQ; oloc = ov;
                       bias4 = *(const float4*)(bq + ov); }
        else         { base = g_k + (size_t)b * NN * CQ; oloc = ov - 32;
                       bias4 = *(const float4*)(bk + (ov - 32)); }
#pragma unroll
        for (int j = 0; j < 4; j++) {
            const int p = p0 + tx * 4 + j;
            float4 v;
            v.x = acc[0][j] + bias4.x;
            v.y = acc[1][j] + bias4.y;
            v.z = acc[2][j] + bias4.z;
            v.w = acc[3][j] + bias4.w;
            *(float4*)(base + (size_t)p * CQ + oloc) = v;
        }
    } else {
        const int oloc = ov - 64;
        float4 bias4 = *(const float4*)(bv + oloc);
#pragma unroll
        for (int j = 0; j < 4; j++) {
            const int p = p0 + tx * 4 + j;
            __half* dst = g_vh + ((size_t)b * NN + p) * CCH + oloc;
            *(half2*)(dst)     = __floats2half2_rn(acc[0][j] + bias4.x, acc[1][j] + bias4.y);
            *(half2*)(dst + 2) = __floats2half2_rn(acc[2][j] + bias4.z, acc[3][j] + bias4.w);
        }
    }
}

// ---------------------------------------------------------------------------
// Kernel 2: flash attention. 64 queries/block, 512 threads = 16 warps.
// Scores+softmax SIMT fp32; P->fp16 smem; PV via mma.m16n8k16.
// smem: qs[32][68]f32 | ks[32][68]f32 | vh[64][264]h | ph[64][72]h | rs[64]f32
// ---------------------------------------------------------------------------
#define SM_QS  0
#define SM_KS  8704
#define SM_VH  17408
#define SM_PH  51200
#define SM_RS  60416
#define ATTN_SMEM 60672

__global__ __launch_bounds__(512) void attn_kernel()
{
    extern __shared__ char sm[];
    float*  qs = (float*)(sm + SM_QS);
    float*  ks = (float*)(sm + SM_KS);
    __half* vh = (__half*)(sm + SM_VH);
    __half* ph = (__half*)(sm + SM_PH);
    float*  rs = (float*)(sm + SM_RS);

    const int b    = blockIdx.y;
    const int m0   = blockIdx.x * 64;
    const int t    = threadIdx.x;
    const int lane = t & 31;
    const int wrp  = t >> 5;
    const int tx   = t & 15, ty = t >> 4;

    // Q tile transposed: qs[c][m]
#pragma unroll
    for (int r = 0; r < 4; r++) {
        const int row = wrp * 4 + r;
        qs[lane * 68 + row] = g_q[((size_t)b * NN + m0 + row) * CQ + lane];
    }

    float acc[8][4];
#pragma unroll
    for (int i = 0; i < 8; i++)
#pragma unroll
        for (int j = 0; j < 4; j++) acc[i][j] = 0.f;

    float rmax[2] = {-INFINITY, -INFINITY}, rsum[2] = {0.f, 0.f};

    const int mb = (wrp & 3) * 16;     // PV m-chunk
    const int cb = (wrp >> 2) * 64;    // PV c-quarter
    const int g  = lane >> 2;

    for (int nt = 0; nt < 64; nt++) {
        const int n0 = nt * 64;
        // K tile transposed
#pragma unroll
        for (int r = 0; r < 4; r++) {
            const int row = wrp * 4 + r;
            ks[lane * 68 + row] = g_k[((size_t)b * NN + n0 + row) * CQ + lane];
        }
        // V tile (fp16, padded rows of 264 halves = 33 uint4)
        {
            const uint4* src = (const uint4*)(g_vh + ((size_t)b * NN + n0) * CCH);
            uint4* dst = (uint4*)vh;
#pragma unroll
            for (int i = 0; i < 4; i++) {
                const int idx = t + i * 512;
                const int row = idx >> 5, c16 = idx & 31;
                dst[row * 33 + c16] = src[row * 32 + c16];
            }
        }
        __syncthreads();

        // --- scores: 2 rows x 4 cols per thread ---
        float s[2][4];
#pragma unroll
        for (int i = 0; i < 2; i++)
#pragma unroll
            for (int j = 0; j < 4; j++) s[i][j] = 0.f;
#pragma unroll
        for (int c = 0; c < 32; c++) {
            float2 q2 = *(const float2*)(qs + c * 68 + ty * 2);
            float4 k4 = *(const float4*)(ks + c * 68 + tx * 4);
            s[0][0] += q2.x * k4.x; s[0][1] += q2.x * k4.y;
            s[0][2] += q2.x * k4.z; s[0][3] += q2.x * k4.w;
            s[1][0] += q2.y * k4.x; s[1][1] += q2.y * k4.y;
            s[1][2] += q2.y * k4.z; s[1][3] += q2.y * k4.w;
        }

        // --- online softmax per row (16-thread groups) ---
#pragma unroll
        for (int r = 0; r < 2; r++) {
            float tm = fmaxf(fmaxf(s[r][0], s[r][1]), fmaxf(s[r][2], s[r][3]));
#pragma unroll
            for (int msk = 1; msk < 16; msk <<= 1)
                tm = fmaxf(tm, __shfl_xor_sync(0xffffffffu, tm, msk));
            const float nm = fmaxf(rmax[r], tm);
            const float sc = __expf(rmax[r] - nm);
            rmax[r] = nm;
            float p0 = __expf(s[r][0] - nm);
            float p1 = __expf(s[r][1] - nm);
            float p2 = __expf(s[r][2] - nm);
            float p3 = __expf(s[r][3] - nm);
            float tsum = p0 + p1 + p2 + p3;
#pragma unroll
            for (int msk = 1; msk < 16; msk <<= 1)
                tsum += __shfl_xor_sync(0xffffffffu, tsum, msk);
            rsum[r] = rsum[r] * sc + tsum;
            if (tx == 0) rs[ty * 2 + r] = sc;
            *(half2*)(ph + (ty * 2 + r) * 72 + tx * 4)     = __floats2half2_rn(p0, p1);
            *(half2*)(ph + (ty * 2 + r) * 72 + tx * 4 + 2) = __floats2half2_rn(p2, p3);
        }
        __syncthreads();

        // --- PV via tensor cores ---
        const float s0 = rs[mb + g], s1 = rs[mb + g + 8];
#pragma unroll
        for (int ch = 0; ch < 8; ch++) {
            acc[ch][0] *= s0; acc[ch][1] *= s0;
            acc[ch][2] *= s1; acc[ch][3] *= s1;
        }
        unsigned int af[4][4];
#pragma unroll
        for (int k4 = 0; k4 < 4; k4++) {
            unsigned int a = smaddr(ph + (mb + (lane & 15)) * 72 + k4 * 16 + (lane >> 4) * 8);
            ldsm_x4(af[k4][0], af[k4][1], af[k4][2], af[k4][3], a);
        }
#pragma unroll
        for (int pr = 0; pr < 4; pr++) {
#pragma unroll
            for (int k4 = 0; k4 < 4; k4++) {
                unsigned int b0, b1, b2, b3;
                unsigned int a = smaddr(vh + (k4 * 16 + (lane & 15)) * 264
                                           + cb + pr * 16 + (lane >> 4) * 8);
                ldsm_x4t(b0, b1, b2, b3, a);
                mma_f16(acc[pr * 2],     af[k4], b0, b1);
                mma_f16(acc[pr * 2 + 1], af[k4], b2, b3);
            }
        }
        __syncthreads();
    }

    if (tx == 0) {
        rs[ty * 2]     = 1.0f / rsum[0];
        rs[ty * 2 + 1] = 1.0f / rsum[1];
    }
    __syncthreads();
    const float i0 = rs[mb + g], i1 = rs[mb + g + 8];
    const int r0 = m0 + mb + g, r1 = r0 + 8;
#pragma unroll
    for (int ch = 0; ch < 8; ch++) {
        const int c = cb + ch * 8 + (lane & 3) * 2;
        *(half2*)(g_cat + ((size_t)b * NN + r0) * 512 + c) =
            __floats2half2_rn(acc[ch][0] * i0, acc[ch][1] * i0);
        *(half2*)(g_cat + ((size_t)b * NN + r1) * 512 + c) =
            __floats2half2_rn(acc[ch][2] * i1, acc[ch][3] * i1);
    }
}

// ---------------------------------------------------------------------------
// Kernel 3: output projection via mma. D[o][m] = Woh[o][k] @ cat[m][k]^T + bo
// Block: 64 o x 128 m, 256 threads (8 warps: 4 o-chunks x 2 m-halves).
// ---------------------------------------------------------------------------
__global__ __launch_bounds__(256) void outproj_kernel(
    const float* __restrict__ bo, float* __restrict__ y)
{
    __shared__ __align__(16) __half As[64 * 72];
    __shared__ __align__(16) __half Bs[128 * 72];

    const int b  = blockIdx.z;
    const int o0 = blockIdx.y * 64;
    const int m0 = blockIdx.x * 128;
    const int t  = threadIdx.x;
    const int lane = t & 31, wrp = t >> 5;
    const int ob = (wrp & 3) * 16;
    const int mh = (wrp >> 2) * 64;

    float acc[8][4];
#pragma unroll
    for (int i = 0; i < 8; i++)
#pragma unroll
        for (int j = 0; j < 4; j++) acc[i][j] = 0.f;

    for (int k0 = 0; k0 < 512; k0 += 64) {
#pragma unroll
        for (int i = 0; i < 2; i++) {
            const int idx = t + i * 256;
            const int row = idx >> 3, c16 = idx & 7;
            ((uint4*)As)[row * 9 + c16] =
                *((const uint4*)(g_woh + (size_t)(o0 + row) * 512 + k0) + c16);
        }
#pragma unroll
        for (int i = 0; i < 4; i++) {
            const int idx = t + i * 256;
            const int row = idx >> 3, c16 = idx & 7;
            ((uint4*)Bs)[row * 9 + c16] =
                *((const uint4*)(g_cat + ((size_t)b * NN + m0 + row) * 512 + k0) + c16);
        }
        __syncthreads();

        unsigned int af[4][4];
#pragma unroll
        for (int k4 = 0; k4 < 4; k4++) {
            unsigned int a = smaddr(As + (ob + (lane & 15)) * 72 + k4 * 16 + (lane >> 4) * 8);
            ldsm_x4(af[k4][0], af[k4][1], af[k4][2], af[k4][3], a);
        }
#pragma unroll
        for (int pr = 0; pr < 4; pr++) {
#pragma unroll
            for (int k4 = 0; k4 < 4; k4++) {
                unsigned int b0, b1, b2, b3;
                unsigned int a = smaddr(Bs + (mh + pr * 16 + (lane >> 4) * 8 + (lane & 7)) * 72
                                           + k4 * 16 + ((lane >> 3) & 1) * 8);
                ldsm_x4(b0, b1, b2, b3, a);
                mma_f16(acc[pr * 2],     af[k4], b0, b1);
                mma_f16(acc[pr * 2 + 1], af[k4], b2, b3);
            }
        }
        __syncthreads();
    }

    const int orow = o0 + ob + (lane >> 2);
    const float bi0 = bo[orow], bi1 = bo[orow + 8];
#pragma unroll
    for (int ch = 0; ch < 8; ch++) {
        const int m = m0 + mh + ch * 8 + (lane & 3) * 2;
        float2 v0, v1;
        v0.x = acc[ch][0] + bi0; v0.y = acc[ch][1] + bi0;
        v1.x = acc[ch][2] + bi1; v1.y = acc[ch][3] + bi1;
        *(float2*)(y + ((size_t)b * CCH + orow)     * NN + m) = v0;
        *(float2*)(y + ((size_t)b * CCH + orow + 8) * NN + m) = v1;
    }
}

// ---------------------------------------------------------------------------
extern "C" void kernel_launch(void* const* d_in, const int* in_sizes, int n_in,
                              void* d_out, int out_size)
{
    const float* x  = (const float*)d_in[0];
    const float* Wq = (const float*)d_in[1];
    const float* bq = (const float*)d_in[2];
    const float* Wk = (const float*)d_in[3];
    const float* bk = (const float*)d_in[4];
    const float* Wv = (const float*)d_in[5];
    const float* bv = (const float*)d_in[6];
    const float* Wo = (const float*)d_in[7];
    const float* bo = (const float*)d_in[8];
    float* y = (float*)d_out;

    cudaFuncSetAttribute(attn_kernel,
                         cudaFuncAttributeMaxDynamicSharedMemorySize,
                         ATTN_SMEM);

    wconv_kernel<<<512, 256>>>(Wo);
    xpose_kernel<<<dim3(128, 8, BB), dim3(32, 8)>>>(x);
    qkv_kernel<<<dim3(5, 64, BB), 256>>>(x, Wq, bq, Wk, bk, Wv, bv);
    attn_kernel<<<dim3(64, BB), 512, ATTN_SMEM>>>();
    outproj_kernel<<<dim3(32, 4, BB), 256>>>(bo, y);
}

// round 4
// speedup vs baseline: 2.3790x; 1.0542x over previous
#include <cuda_runtime.h>
#include <cuda_fp16.h>
#include <cstdint>
#include <math.h>

#define BB  4
#define CCH 256
#define CQ  32
#define NN  4096

// Scratch (device globals: no allocation allowed)
__device__ __half g_qhi[BB * NN * CQ];
__device__ __half g_qlo[BB * NN * CQ];
__device__ __half g_khi[BB * NN * CQ];
__device__ __half g_klo[BB * NN * CQ];
__device__ __half g_vh[BB * NN * CCH];         // [b][n][256] fp16
__device__ __half g_cat[BB * NN * 2 * CCH];    // [b][n][512]: [0:256)=attn, [256:512)=x^T
__device__ __half g_woh[CCH * 2 * CCH];        // Wo fp16 [o][512]

// ---------------- PTX helpers ----------------
__device__ __forceinline__ unsigned int smaddr(const void* p) {
    return (unsigned int)__cvta_generic_to_shared(p);
}
__device__ __forceinline__ void ldsm_x4(unsigned int& r0, unsigned int& r1,
                                        unsigned int& r2, unsigned int& r3,
                                        unsigned int a) {
    asm volatile("ldmatrix.sync.aligned.m8n8.x4.shared.b16 {%0,%1,%2,%3},[%4];\n"
                 : "=r"(r0), "=r"(r1), "=r"(r2), "=r"(r3) : "r"(a));
}
__device__ __forceinline__ void ldsm_x4t(unsigned int& r0, unsigned int& r1,
                                         unsigned int& r2, unsigned int& r3,
                                         unsigned int a) {
    asm volatile("ldmatrix.sync.aligned.m8n8.x4.trans.shared.b16 {%0,%1,%2,%3},[%4];\n"
                 : "=r"(r0), "=r"(r1), "=r"(r2), "=r"(r3) : "r"(a));
}
__device__ __forceinline__ void mma_f16(float* d, const unsigned int* a,
                                        unsigned int b0, unsigned int b1) {
    asm volatile("mma.sync.aligned.m16n8k16.row.col.f32.f16.f16.f32 "
                 "{%0,%1,%2,%3},{%4,%5,%6,%7},{%8,%9},{%0,%1,%2,%3};\n"
                 : "+f"(d[0]), "+f"(d[1]), "+f"(d[2]), "+f"(d[3])
                 : "r"(a[0]), "r"(a[1]), "r"(a[2]), "r"(a[3]), "r"(b0), "r"(b1));
}

// ---------------------------------------------------------------------------
// Kernel 0a: Wo -> fp16
// ---------------------------------------------------------------------------
__global__ void wconv_kernel(const float* __restrict__ Wo) {
    int i = blockIdx.x * blockDim.x + threadIdx.x;
    g_woh[i] = __float2half(Wo[i]);
}

// ---------------------------------------------------------------------------
// Kernel 0b: transpose-convert x -> g_cat[b][n][256+c]
// ---------------------------------------------------------------------------
__global__ void xpose_kernel(const float* __restrict__ x) {
    __shared__ float ts[32][33];
    const int b = blockIdx.z, n0 = blockIdx.x * 32, c0 = blockIdx.y * 32;
    const int txi = threadIdx.x, tyi = threadIdx.y;
#pragma unroll
    for (int i = 0; i < 4; i++) {
        int c = c0 + tyi + i * 8;
        ts[tyi + i * 8][txi] = x[((size_t)b * CCH + c) * NN + n0 + txi];
    }
    __syncthreads();
#pragma unroll
    for (int i = 0; i < 4; i++) {
        int n = n0 + tyi + i * 8;
        g_cat[((size_t)b * NN + n) * 512 + 256 + c0 + txi] =
            __float2half(ts[txi][tyi + i * 8]);
    }
}

// ---------------------------------------------------------------------------
// Kernel 1: fused QKV projection. q/k written as fp16 hi+lo split; v fp16.
// ---------------------------------------------------------------------------
__global__ __launch_bounds__(256) void qkv_kernel(
    const float* __restrict__ x,
    const float* __restrict__ Wq, const float* __restrict__ bq,
    const float* __restrict__ Wk, const float* __restrict__ bk,
    const float* __restrict__ Wv, const float* __restrict__ bv)
{
    __shared__ float Ws[32][68];
    __shared__ float Xs[32][68];

    const int b  = blockIdx.z;
    const int o0 = blockIdx.x * 64;
    const int p0 = blockIdx.y * 64;
    const int t  = threadIdx.x;
    const int tx = t & 15, ty = t >> 4;

    const float* xb = x + (size_t)b * CCH * NN;

    float acc[4][4];
#pragma unroll
    for (int i = 0; i < 4; i++)
#pragma unroll
        for (int j = 0; j < 4; j++) acc[i][j] = 0.f;

    for (int kc = 0; kc < CCH; kc += 32) {
        {
            const int oo = t >> 2;
            const int kk = (t & 3) * 8;
            const int o  = o0 + oo;
            const float* wrow;
            if (o < 32)       wrow = Wq + (size_t)o * CCH;
            else if (o < 64)  wrow = Wk + (size_t)(o - 32) * CCH;
            else              wrow = Wv + (size_t)(o - 64) * CCH;
            float4 w0 = *(const float4*)(wrow + kc + kk);
            float4 w1 = *(const float4*)(wrow + kc + kk + 4);
            float w[8] = {w0.x, w0.y, w0.z, w0.w, w1.x, w1.y, w1.z, w1.w};
#pragma unroll
            for (int i = 0; i < 8; i++) Ws[kk + i][oo] = w[i];
        }
        {
            const int kk = t >> 3;
            const int pp = (t & 7) * 8;
            const float* xr = xb + (size_t)(kc + kk) * NN + p0 + pp;
            *(float4*)&Xs[kk][pp]     = *(const float4*)(xr);
            *(float4*)&Xs[kk][pp + 4] = *(const float4*)(xr + 4);
        }
        __syncthreads();

#pragma unroll
        for (int kk = 0; kk < 32; kk++) {
            float4 a4 = *(const float4*)&Ws[kk][ty * 4];
            float4 b4 = *(const float4*)&Xs[kk][tx * 4];
            float a[4]  = {a4.x, a4.y, a4.z, a4.w};
            float bx[4] = {b4.x, b4.y, b4.z, b4.w};
#pragma unroll
            for (int i = 0; i < 4; i++)
#pragma unroll
                for (int j = 0; j < 4; j++) acc[i][j] += a[i] * bx[j];
        }
        __syncthreads();
    }

    const int ov = o0 + ty * 4;
    if (ov < 64) {
        __half *bhi, *blo; int oloc; float4 bias4;
        if (ov < 32) {
            bhi = g_qhi + (size_t)b * NN * CQ; blo = g_qlo + (size_t)b * NN * CQ;
            oloc = ov; bias4 = *(const float4*)(bq + ov);
        } else {
            bhi = g_khi + (size_t)b * NN * CQ; blo = g_klo + (size_t)b * NN * CQ;
            oloc = ov - 32; bias4 = *(const float4*)(bk + (ov - 32));
        }
#pragma unroll
        for (int j = 0; j < 4; j++) {
            const int p = p0 + tx * 4 + j;
            float v0 = acc[0][j] + bias4.x;
            float v1 = acc[1][j] + bias4.y;
            float v2 = acc[2][j] + bias4.z;
            float v3 = acc[3][j] + bias4.w;
            __half h0 = __float2half_rn(v0), h1 = __float2half_rn(v1);
            __half h2 = __float2half_rn(v2), h3 = __float2half_rn(v3);
            __half l0 = __float2half_rn(v0 - __half2float(h0));
            __half l1 = __float2half_rn(v1 - __half2float(h1));
            __half l2 = __float2half_rn(v2 - __half2float(h2));
            __half l3 = __float2half_rn(v3 - __half2float(h3));
            *(half2*)(bhi + (size_t)p * CQ + oloc)     = __halves2half2(h0, h1);
            *(half2*)(bhi + (size_t)p * CQ + oloc + 2) = __halves2half2(h2, h3);
            *(half2*)(blo + (size_t)p * CQ + oloc)     = __halves2half2(l0, l1);
            *(half2*)(blo + (size_t)p * CQ + oloc + 2) = __halves2half2(l2, l3);
        }
    } else {
        const int oloc = ov - 64;
        float4 bias4 = *(const float4*)(bv + oloc);
#pragma unroll
        for (int j = 0; j < 4; j++) {
            const int p = p0 + tx * 4 + j;
            __half* dst = g_vh + ((size_t)b * NN + p) * CCH + oloc;
            *(half2*)(dst)     = __floats2half2_rn(acc[0][j] + bias4.x, acc[1][j] + bias4.y);
            *(half2*)(dst + 2) = __floats2half2_rn(acc[2][j] + bias4.z, acc[3][j] + bias4.w);
        }
    }
}

// ---------------------------------------------------------------------------
// Kernel 2: flash attention, all tensor-core.
// 64q/block, 512 threads = 16 warps.
//  S phase: warps 0-3 (16q band each) fp16 hi/lo split mma + fragment softmax.
//  Loaders: warps 4-15 prefetch next K/V (double buffered).
//  PV: all 16 warps, band(2 x 32q) x cs(8 x 32c).
// ---------------------------------------------------------------------------
#define A_QHI 0
#define A_QLO 5120
#define A_KH0 10240
#define A_KL0 15360
#define A_KH1 20480
#define A_KL1 25600
#define A_VH0 30720
#define A_VH1 64512
#define A_PH  98304
#define A_RS  107520
#define ATTN_SMEM 107776

__global__ __launch_bounds__(512, 1) void attn_kernel()
{
    extern __shared__ char sm[];
    __half* ph = (__half*)(sm + A_PH);
    float*  rs = (float*)(sm + A_RS);

    const int b    = blockIdx.y;
    const int m0   = blockIdx.x * 64;
    const int t    = threadIdx.x;
    const int lane = t & 31;
    const int wrp  = t >> 5;

    // ---- prologue: stage q (hi/lo), K[0], V[0] ----
    {
        const int tt  = t & 255;
        const int row = tt >> 2, c4 = tt & 3;
        if (t < 256) {
            *((uint4*)(sm + A_QHI + row * 80) + c4) =
                *((const uint4*)(g_qhi + ((size_t)b * NN + m0 + row) * CQ) + c4);
            *((uint4*)(sm + A_KH0 + row * 80) + c4) =
                *((const uint4*)(g_khi + ((size_t)b * NN + row) * CQ) + c4);
        } else {
            *((uint4*)(sm + A_QLO + row * 80) + c4) =
                *((const uint4*)(g_qlo + ((size_t)b * NN + m0 + row) * CQ) + c4);
            *((uint4*)(sm + A_KL0 + row * 80) + c4) =
                *((const uint4*)(g_klo + ((size_t)b * NN + row) * CQ) + c4);
        }
#pragma unroll
        for (int i = t; i < 2048; i += 512) {
            const int vr = i >> 5, vc = i & 31;
            *((uint4*)(sm + A_VH0 + vr * 528) + vc) =
                *((const uint4*)(g_vh + ((size_t)b * NN + vr) * CCH) + vc);
        }
    }
    __syncthreads();

    // persistent q fragments (S warps only)
    unsigned ahi[2][4], alo[2][4];
    float rmax0 = -INFINITY, rmax1 = -INFINITY, rsum0 = 0.f, rsum1 = 0.f;
    int r0 = 0, r1 = 0;
    if (wrp < 4) {
        const int mb = wrp * 16;
        r0 = mb + (lane >> 2); r1 = r0 + 8;
#pragma unroll
        for (int ks = 0; ks < 2; ks++) {
            ldsm_x4(ahi[ks][0], ahi[ks][1], ahi[ks][2], ahi[ks][3],
                smaddr(sm + A_QHI + (mb + (lane & 15)) * 80 + ks * 32 + ((lane >> 4) << 4)));
            ldsm_x4(alo[ks][0], alo[ks][1], alo[ks][2], alo[ks][3],
                smaddr(sm + A_QLO + (mb + (lane & 15)) * 80 + ks * 32 + ((lane >> 4) << 4)));
        }
    }

    const int band = wrp & 1, cs = wrp >> 1;
    float acc[2][4][4];
#pragma unroll
    for (int ms = 0; ms < 2; ms++)
#pragma unroll
        for (int cb = 0; cb < 4; cb++)
#pragma unroll
            for (int j = 0; j < 4; j++) acc[ms][cb][j] = 0.f;

    int buf = 0;
    for (int nt = 0; nt < 64; nt++) {
        char* kh = sm + (buf ? A_KH1 : A_KH0);
        char* kl = sm + (buf ? A_KL1 : A_KL0);
        char* vb = sm + (buf ? A_VH1 : A_VH0);

        if (wrp < 4) {
            // ---- S = QK^T via hi/lo split mma ----
            float sacc[8][4];
#pragma unroll
            for (int n = 0; n < 8; n++)
#pragma unroll
                for (int j = 0; j < 4; j++) sacc[n][j] = 0.f;
#pragma unroll
            for (int np = 0; np < 4; np++) {
#pragma unroll
                for (int ks = 0; ks < 2; ks++) {
                    unsigned bh0, bh1, bh2, bh3, bl0, bl1, bl2, bl3;
                    const int roff = (np * 16 + ((lane >> 4) << 3) + (lane & 7)) * 80
                                   + ks * 32 + (((lane >> 3) & 1) << 4);
                    ldsm_x4(bh0, bh1, bh2, bh3, smaddr(kh + roff));
                    ldsm_x4(bl0, bl1, bl2, bl3, smaddr(kl + roff));
                    mma_f16(sacc[np * 2],     ahi[ks], bh0, bh1);
                    mma_f16(sacc[np * 2],     ahi[ks], bl0, bl1);
                    mma_f16(sacc[np * 2],     alo[ks], bh0, bh1);
                    mma_f16(sacc[np * 2 + 1], ahi[ks], bh2, bh3);
                    mma_f16(sacc[np * 2 + 1], ahi[ks], bl2, bl3);
                    mma_f16(sacc[np * 2 + 1], alo[ks], bh2, bh3);
                }
            }
            // ---- fragment softmax ----
            float tm0 = sacc[0][0], tm1 = sacc[0][2];
#pragma unroll
            for (int n = 0; n < 8; n++) {
                tm0 = fmaxf(tm0, fmaxf(sacc[n][0], sacc[n][1]));
                tm1 = fmaxf(tm1, fmaxf(sacc[n][2], sacc[n][3]));
            }
            tm0 = fmaxf(tm0, __shfl_xor_sync(0xffffffffu, tm0, 1));
            tm0 = fmaxf(tm0, __shfl_xor_sync(0xffffffffu, tm0, 2));
            tm1 = fmaxf(tm1, __shfl_xor_sync(0xffffffffu, tm1, 1));
            tm1 = fmaxf(tm1, __shfl_xor_sync(0xffffffffu, tm1, 2));
            const float nm0 = fmaxf(rmax0, tm0), nm1 = fmaxf(rmax1, tm1);
            const float sc0 = __expf(rmax0 - nm0), sc1 = __expf(rmax1 - nm1);
            rmax0 = nm0; rmax1 = nm1;
            float ts0 = 0.f, ts1 = 0.f;
#pragma unroll
            for (int n = 0; n < 8; n++) {
                float p0 = __expf(sacc[n][0] - nm0);
                float p1 = __expf(sacc[n][1] - nm0);
                float p2 = __expf(sacc[n][2] - nm1);
                float p3 = __expf(sacc[n][3] - nm1);
                ts0 += p0 + p1; ts1 += p2 + p3;
                *(half2*)(ph + r0 * 72 + n * 8 + 2 * (lane & 3)) = __floats2half2_rn(p0, p1);
                *(half2*)(ph + r1 * 72 + n * 8 + 2 * (lane & 3)) = __floats2half2_rn(p2, p3);
            }
            ts0 += __shfl_xor_sync(0xffffffffu, ts0, 1);
            ts0 += __shfl_xor_sync(0xffffffffu, ts0, 2);
            ts1 += __shfl_xor_sync(0xffffffffu, ts1, 1);
            ts1 += __shfl_xor_sync(0xffffffffu, ts1, 2);
            rsum0 = rsum0 * sc0 + ts0;
            rsum1 = rsum1 * sc1 + ts1;
            if ((lane & 3) == 0) { rs[r0] = sc0; rs[r1] = sc1; }
        } else if (nt < 63) {
            // ---- prefetch next K/V into buf^1 ----
            const int n1 = (nt + 1) * 64;
            char* dkh = sm + (buf ? A_KH0 : A_KH1);
            char* dkl = sm + (buf ? A_KL0 : A_KL1);
            char* dvb = sm + (buf ? A_VH0 : A_VH1);
            const int lt = t - 128;
            if (lt < 256) {
                const int row = lt >> 2, c4 = lt & 3;
                *((uint4*)(dkh + row * 80) + c4) =
                    *((const uint4*)(g_khi + ((size_t)b * NN + n1 + row) * CQ) + c4);
                *((uint4*)(dkl + row * 80) + c4) =
                    *((const uint4*)(g_klo + ((size_t)b * NN + n1 + row) * CQ) + c4);
            }
            for (int i = lt; i < 2048; i += 384) {
                const int vr = i >> 5, vc = i & 31;
                *((uint4*)(dvb + vr * 528) + vc) =
                    *((const uint4*)(g_vh + ((size_t)b * NN + n1 + vr) * CCH) + vc);
            }
        }
        __syncthreads();

        // ---- PV: all warps ----
        {
            const float s0a = rs[band * 32 + (lane >> 2)];
            const float s1a = rs[band * 32 + (lane >> 2) + 8];
            const float s0b = rs[band * 32 + 16 + (lane >> 2)];
            const float s1b = rs[band * 32 + 16 + (lane >> 2) + 8];
#pragma unroll
            for (int cb = 0; cb < 4; cb++) {
                acc[0][cb][0] *= s0a; acc[0][cb][1] *= s0a;
                acc[0][cb][2] *= s1a; acc[0][cb][3] *= s1a;
                acc[1][cb][0] *= s0b; acc[1][cb][1] *= s0b;
                acc[1][cb][2] *= s1b; acc[1][cb][3] *= s1b;
            }
            unsigned pf[2][4][4];
#pragma unroll
            for (int ms = 0; ms < 2; ms++)
#pragma unroll
                for (int ks = 0; ks < 4; ks++)
                    ldsm_x4(pf[ms][ks][0], pf[ms][ks][1], pf[ms][ks][2], pf[ms][ks][3],
                        smaddr((char*)ph + (band * 32 + ms * 16 + (lane & 15)) * 144
                               + ks * 32 + ((lane >> 4) << 4)));
#pragma unroll
            for (int cp = 0; cp < 2; cp++) {
#pragma unroll
                for (int ks = 0; ks < 4; ks++) {
                    unsigned v0, v1, v2, v3;
                    ldsm_x4t(v0, v1, v2, v3,
                        smaddr(vb + (ks * 16 + (lane & 15)) * 528
                               + cs * 64 + cp * 32 + ((lane >> 4) << 4)));
                    mma_f16(acc[0][cp * 2],     pf[0][ks], v0, v1);
                    mma_f16(acc[0][cp * 2 + 1], pf[0][ks], v2, v3);
                    mma_f16(acc[1][cp * 2],     pf[1][ks], v0, v1);
                    mma_f16(acc[1][cp * 2 + 1], pf[1][ks], v2, v3);
                }
            }
        }
        __syncthreads();
        buf ^= 1;
    }

    // ---- epilogue: normalize and write ----
    if (wrp < 4 && (lane & 3) == 0) {
        rs[r0] = 1.f / rsum0;
        rs[r1] = 1.f / rsum1;
    }
    __syncthreads();
    const float i0a = rs[band * 32 + (lane >> 2)];
    const float i1a = rs[band * 32 + (lane >> 2) + 8];
    const float i0b = rs[band * 32 + 16 + (lane >> 2)];
    const float i1b = rs[band * 32 + 16 + (lane >> 2) + 8];
    const int rowa = m0 + band * 32 + (lane >> 2);
    const int rowb = rowa + 16;
#pragma unroll
    for (int cb = 0; cb < 4; cb++) {
        const int col = cs * 32 + cb * 8 + 2 * (lane & 3);
        *(half2*)(g_cat + ((size_t)b * NN + rowa) * 512 + col) =
            __floats2half2_rn(acc[0][cb][0] * i0a, acc[0][cb][1] * i0a);
        *(half2*)(g_cat + ((size_t)b * NN + rowa + 8) * 512 + col) =
            __floats2half2_rn(acc[0][cb][2] * i1a, acc[0][cb][3] * i1a);
        *(half2*)(g_cat + ((size_t)b * NN + rowb) * 512 + col) =
            __floats2half2_rn(acc[1][cb][0] * i0b, acc[1][cb][1] * i0b);
        *(half2*)(g_cat + ((size_t)b * NN + rowb + 8) * 512 + col) =
            __floats2half2_rn(acc[1][cb][2] * i1b, acc[1][cb][3] * i1b);
    }
}

// ---------------------------------------------------------------------------
// Kernel 3: output projection via mma (unchanged from R3)
// ---------------------------------------------------------------------------
__global__ __launch_bounds__(256) void outproj_kernel(
    const float* __restrict__ bo, float* __restrict__ y)
{
    __shared__ __align__(16) __half As[64 * 72];
    __shared__ __align__(16) __half Bs[128 * 72];

    const int b  = blockIdx.z;
    const int o0 = blockIdx.y * 64;
    const int m0 = blockIdx.x * 128;
    const int t  = threadIdx.x;
    const int lane = t & 31, wrp = t >> 5;
    const int ob = (wrp & 3) * 16;
    const int mh = (wrp >> 2) * 64;

    float acc[8][4];
#pragma unroll
    for (int i = 0; i < 8; i++)
#pragma unroll
        for (int j = 0; j < 4; j++) acc[i][j] = 0.f;

    for (int k0 = 0; k0 < 512; k0 += 64) {
#pragma unroll
        for (int i = 0; i < 2; i++) {
            const int idx = t + i * 256;
            const int row = idx >> 3, c16 = idx & 7;
            ((uint4*)As)[row * 9 + c16] =
                *((const uint4*)(g_woh + (size_t)(o0 + row) * 512 + k0) + c16);
        }
#pragma unroll
        for (int i = 0; i < 4; i++) {
            const int idx = t + i * 256;
            const int row = idx >> 3, c16 = idx & 7;
            ((uint4*)Bs)[row * 9 + c16] =
                *((const uint4*)(g_cat + ((size_t)b * NN + m0 + row) * 512 + k0) + c16);
        }
        __syncthreads();

        unsigned int af[4][4];
#pragma unroll
        for (int k4 = 0; k4 < 4; k4++) {
            unsigned int a = smaddr(As + (ob + (lane & 15)) * 72 + k4 * 16 + (lane >> 4) * 8);
            ldsm_x4(af[k4][0], af[k4][1], af[k4][2], af[k4][3], a);
        }
#pragma unroll
        for (int pr = 0; pr < 4; pr++) {
#pragma unroll
            for (int k4 = 0; k4 < 4; k4++) {
                unsigned int b0, b1, b2, b3;
                unsigned int a = smaddr(Bs + (mh + pr * 16 + (lane >> 4) * 8 + (lane & 7)) * 72
                                           + k4 * 16 + ((lane >> 3) & 1) * 8);
                ldsm_x4(b0, b1, b2, b3, a);
                mma_f16(acc[pr * 2],     af[k4], b0, b1);
                mma_f16(acc[pr * 2 + 1], af[k4], b2, b3);
            }
        }
        __syncthreads();
    }

    const int orow = o0 + ob + (lane >> 2);
    const float bi0 = bo[orow], bi1 = bo[orow + 8];
#pragma unroll
    for (int ch = 0; ch < 8; ch++) {
        const int m = m0 + mh + ch * 8 + (lane & 3) * 2;
        float2 v0, v1;
        v0.x = acc[ch][0] + bi0; v0.y = acc[ch][1] + bi0;
        v1.x = acc[ch][2] + bi1; v1.y = acc[ch][3] + bi1;
        *(float2*)(y + ((size_t)b * CCH + orow)     * NN + m) = v0;
        *(float2*)(y + ((size_t)b * CCH + orow + 8) * NN + m) = v1;
    }
}

// ---------------------------------------------------------------------------
extern "C" void kernel_launch(void* const* d_in, const int* in_sizes, int n_in,
                              void* d_out, int out_size)
{
    const float* x  = (const float*)d_in[0];
    const float* Wq = (const float*)d_in[1];
    const float* bq = (const float*)d_in[2];
    const float* Wk = (const float*)d_in[3];
    const float* bk = (const float*)d_in[4];
    const float* Wv = (const float*)d_in[5];
    const float* bv = (const float*)d_in[6];
    const float* Wo = (const float*)d_in[7];
    const float* bo = (const float*)d_in[8];
    float* y = (float*)d_out;

    cudaFuncSetAttribute(attn_kernel,
                         cudaFuncAttributeMaxDynamicSharedMemorySize,
                         ATTN_SMEM);

    wconv_kernel<<<512, 256>>>(Wo);
    xpose_kernel<<<dim3(128, 8, BB), dim3(32, 8)>>>(x);
    qkv_kernel<<<dim3(5, 64, BB), 256>>>(x, Wq, bq, Wk, bk, Wv, bv);
    attn_kernel<<<dim3(64, BB), 512, ATTN_SMEM>>>();
    outproj_kernel<<<dim3(32, 4, BB), 256>>>(bo, y);
}

// round 5
// speedup vs baseline: 3.2417x; 1.3626x over previous
#include <cuda_runtime.h>
#include <cuda_fp16.h>
#include <cstdint>
#include <math.h>

#define BB  4
#define CCH 256
#define CQ  32
#define NN  4096
#define LOG2E 1.4426950408889634f

// Scratch (device globals: no allocation allowed)
__device__ __half g_qhi[BB * NN * CQ];         // q * log2e, hi
__device__ __half g_qlo[BB * NN * CQ];         // q * log2e, lo
__device__ __half g_khi[BB * NN * CQ];
__device__ __half g_klo[BB * NN * CQ];
__device__ __half g_vh[BB * NN * CCH];         // [b][n][256] fp16
__device__ __half g_cat[BB * NN * 2 * CCH];    // [b][n][512]: [0:256)=attn, [256:512)=x^T
__device__ __half g_woh[CCH * 2 * CCH];        // Wo fp16 [o][512]

// ---------------- PTX helpers ----------------
__device__ __forceinline__ unsigned int smaddr(const void* p) {
    return (unsigned int)__cvta_generic_to_shared(p);
}
__device__ __forceinline__ void ldsm_x4(unsigned int& r0, unsigned int& r1,
                                        unsigned int& r2, unsigned int& r3,
                                        unsigned int a) {
    asm volatile("ldmatrix.sync.aligned.m8n8.x4.shared.b16 {%0,%1,%2,%3},[%4];\n"
                 : "=r"(r0), "=r"(r1), "=r"(r2), "=r"(r3) : "r"(a));
}
__device__ __forceinline__ void ldsm_x4t(unsigned int& r0, unsigned int& r1,
                                         unsigned int& r2, unsigned int& r3,
                                         unsigned int a) {
    asm volatile("ldmatrix.sync.aligned.m8n8.x4.trans.shared.b16 {%0,%1,%2,%3},[%4];\n"
                 : "=r"(r0), "=r"(r1), "=r"(r2), "=r"(r3) : "r"(a));
}
__device__ __forceinline__ void mma_f16(float* d, const unsigned int* a,
                                        unsigned int b0, unsigned int b1) {
    asm volatile("mma.sync.aligned.m16n8k16.row.col.f32.f16.f16.f32 "
                 "{%0,%1,%2,%3},{%4,%5,%6,%7},{%8,%9},{%0,%1,%2,%3};\n"
                 : "+f"(d[0]), "+f"(d[1]), "+f"(d[2]), "+f"(d[3])
                 : "r"(a[0]), "r"(a[1]), "r"(a[2]), "r"(a[3]), "r"(b0), "r"(b1));
}
// exp2 of two floats -> packed fp16x2 (MUFU.EX2 f16x2)
__device__ __forceinline__ unsigned int ex2h2(float a, float b) {
    half2 h = __floats2half2_rn(a, b);
    unsigned int x = *(unsigned int*)&h, r;
    asm volatile("ex2.approx.f16x2 %0, %1;\n" : "=r"(r) : "r"(x));
    return r;
}
__device__ __forceinline__ half2 hu(unsigned int x) { return *(half2*)&x; }

// ---------------------------------------------------------------------------
// Kernel 0a: Wo -> fp16
// ---------------------------------------------------------------------------
__global__ void wconv_kernel(const float* __restrict__ Wo) {
    int i = blockIdx.x * blockDim.x + threadIdx.x;
    g_woh[i] = __float2half(Wo[i]);
}

// ---------------------------------------------------------------------------
// Kernel 0b: transpose-convert x -> g_cat[b][n][256+c]
// ---------------------------------------------------------------------------
__global__ void xpose_kernel(const float* __restrict__ x) {
    __shared__ float ts[32][33];
    const int b = blockIdx.z, n0 = blockIdx.x * 32, c0 = blockIdx.y * 32;
    const int txi = threadIdx.x, tyi = threadIdx.y;
#pragma unroll
    for (int i = 0; i < 4; i++) {
        int c = c0 + tyi + i * 8;
        ts[tyi + i * 8][txi] = x[((size_t)b * CCH + c) * NN + n0 + txi];
    }
    __syncthreads();
#pragma unroll
    for (int i = 0; i < 4; i++) {
        int n = n0 + tyi + i * 8;
        g_cat[((size_t)b * NN + n) * 512 + 256 + c0 + txi] =
            __float2half(ts[txi][tyi + i * 8]);
    }
}

// ---------------------------------------------------------------------------
// Kernel 1: fused QKV projection. q scaled by log2e; q/k hi+lo split; v fp16.
// ---------------------------------------------------------------------------
__global__ __launch_bounds__(256) void qkv_kernel(
    const float* __restrict__ x,
    const float* __restrict__ Wq, const float* __restrict__ bq,
    const float* __restrict__ Wk, const float* __restrict__ bk,
    const float* __restrict__ Wv, const float* __restrict__ bv)
{
    __shared__ float Ws[32][68];
    __shared__ float Xs[32][68];

    const int b  = blockIdx.z;
    const int o0 = blockIdx.x * 64;
    const int p0 = blockIdx.y * 64;
    const int t  = threadIdx.x;
    const int tx = t & 15, ty = t >> 4;

    const float* xb = x + (size_t)b * CCH * NN;

    float acc[4][4];
#pragma unroll
    for (int i = 0; i < 4; i++)
#pragma unroll
        for (int j = 0; j < 4; j++) acc[i][j] = 0.f;

    for (int kc = 0; kc < CCH; kc += 32) {
        {
            const int oo = t >> 2;
            const int kk = (t & 3) * 8;
            const int o  = o0 + oo;
            const float* wrow;
            if (o < 32)       wrow = Wq + (size_t)o * CCH;
            else if (o < 64)  wrow = Wk + (size_t)(o - 32) * CCH;
            else              wrow = Wv + (size_t)(o - 64) * CCH;
            float4 w0 = *(const float4*)(wrow + kc + kk);
            float4 w1 = *(const float4*)(wrow + kc + kk + 4);
            float w[8] = {w0.x, w0.y, w0.z, w0.w, w1.x, w1.y, w1.z, w1.w};
#pragma unroll
            for (int i = 0; i < 8; i++) Ws[kk + i][oo] = w[i];
        }
        {
            const int kk = t >> 3;
            const int pp = (t & 7) * 8;
            const float* xr = xb + (size_t)(kc + kk) * NN + p0 + pp;
            *(float4*)&Xs[kk][pp]     = *(const float4*)(xr);
            *(float4*)&Xs[kk][pp + 4] = *(const float4*)(xr + 4);
        }
        __syncthreads();

#pragma unroll
        for (int kk = 0; kk < 32; kk++) {
            float4 a4 = *(const float4*)&Ws[kk][ty * 4];
            float4 b4 = *(const float4*)&Xs[kk][tx * 4];
            float a[4]  = {a4.x, a4.y, a4.z, a4.w};
            float bx[4] = {b4.x, b4.y, b4.z, b4.w};
#pragma unroll
            for (int i = 0; i < 4; i++)
#pragma unroll
                for (int j = 0; j < 4; j++) acc[i][j] += a[i] * bx[j];
        }
        __syncthreads();
    }

    const int ov = o0 + ty * 4;
    if (ov < 64) {
        __half *bhi, *blo; int oloc; float4 bias4; float scl;
        if (ov < 32) {
            bhi = g_qhi + (size_t)b * NN * CQ; blo = g_qlo + (size_t)b * NN * CQ;
            oloc = ov; bias4 = *(const float4*)(bq + ov); scl = LOG2E;
        } else {
            bhi = g_khi + (size_t)b * NN * CQ; blo = g_klo + (size_t)b * NN * CQ;
            oloc = ov - 32; bias4 = *(const float4*)(bk + (ov - 32)); scl = 1.0f;
        }
#pragma unroll
        for (int j = 0; j < 4; j++) {
            const int p = p0 + tx * 4 + j;
            float v0 = (acc[0][j] + bias4.x) * scl;
            float v1 = (acc[1][j] + bias4.y) * scl;
            float v2 = (acc[2][j] + bias4.z) * scl;
            float v3 = (acc[3][j] + bias4.w) * scl;
            __half h0 = __float2half_rn(v0), h1 = __float2half_rn(v1);
            __half h2 = __float2half_rn(v2), h3 = __float2half_rn(v3);
            __half l0 = __float2half_rn(v0 - __half2float(h0));
            __half l1 = __float2half_rn(v1 - __half2float(h1));
            __half l2 = __float2half_rn(v2 - __half2float(h2));
            __half l3 = __float2half_rn(v3 - __half2float(h3));
            *(half2*)(bhi + (size_t)p * CQ + oloc)     = __halves2half2(h0, h1);
            *(half2*)(bhi + (size_t)p * CQ + oloc + 2) = __halves2half2(h2, h3);
            *(half2*)(blo + (size_t)p * CQ + oloc)     = __halves2half2(l0, l1);
            *(half2*)(blo + (size_t)p * CQ + oloc + 2) = __halves2half2(l2, l3);
        }
    } else {
        const int oloc = ov - 64;
        float4 bias4 = *(const float4*)(bv + oloc);
#pragma unroll
        for (int j = 0; j < 4; j++) {
            const int p = p0 + tx * 4 + j;
            __half* dst = g_vh + ((size_t)b * NN + p) * CCH + oloc;
            *(half2*)(dst)     = __floats2half2_rn(acc[0][j] + bias4.x, acc[1][j] + bias4.y);
            *(half2*)(dst + 2) = __floats2half2_rn(acc[2][j] + bias4.z, acc[3][j] + bias4.w);
        }
    }
}

// ---------------------------------------------------------------------------
// Kernel 2: flash attention (FA2 style, no warp specialization).
// 64q/block, 256 threads = 8 warps = 4 query-bands x 2 c-halves.
// Each warp: S (hi/lo split mma, its band) -> fragment softmax (ex2.f16x2)
//            -> register repack -> PV mma (its c-half). No P smem.
// smem: kh[64x32h s80B] | kl | v[64x256h s528B]   (Q staged in v area once)
// ---------------------------------------------------------------------------
#define A_KH 0
#define A_KL 5120
#define A_V  10240
#define ATTN_SMEM 44032

__global__ __launch_bounds__(256, 2) void attn_kernel()
{
    extern __shared__ char sm[];
    char* kh = sm + A_KH;
    char* kl = sm + A_KL;
    char* vb = sm + A_V;

    const int b    = blockIdx.y;
    const int m0   = blockIdx.x * 64;
    const int t    = threadIdx.x;
    const int lane = t & 31;
    const int wrp  = t >> 5;
    const int band = wrp & 3;        // 16-query band
    const int ch   = wrp >> 2;       // 128-col half

    const int row = t >> 2, c4 = t & 3;

    // ---- prologue: stage Q (hi/lo) in V area, grab fragments ----
    *((uint4*)(vb + row * 80) + c4) =
        *((const uint4*)(g_qhi + ((size_t)b * NN + m0 + row) * CQ) + c4);
    *((uint4*)(vb + 5120 + row * 80) + c4) =
        *((const uint4*)(g_qlo + ((size_t)b * NN + m0 + row) * CQ) + c4);
    __syncthreads();

    unsigned qh[2][4], ql[2][4];
    {
        const int mb = band * 16;
        const int aoff = (mb + (lane & 15)) * 80 + ((lane >> 4) << 4);
#pragma unroll
        for (int ks = 0; ks < 2; ks++) {
            ldsm_x4(qh[ks][0], qh[ks][1], qh[ks][2], qh[ks][3],
                    smaddr(vb + aoff + ks * 32));
            ldsm_x4(ql[ks][0], ql[ks][1], ql[ks][2], ql[ks][3],
                    smaddr(vb + 5120 + aoff + ks * 32));
        }
    }
    __syncthreads();

    float acc[16][4];
#pragma unroll
    for (int g = 0; g < 16; g++)
#pragma unroll
        for (int j = 0; j < 4; j++) acc[g][j] = 0.f;
    float rmax0 = -INFINITY, rmax1 = -INFINITY, rsum0 = 0.f, rsum1 = 0.f;

    for (int nt = 0; nt < 64; nt++) {
        const int n0 = nt * 64;
        // ---- load K(hi/lo) + V tile ----
        *((uint4*)(kh + row * 80) + c4) =
            *((const uint4*)(g_khi + ((size_t)b * NN + n0 + row) * CQ) + c4);
        *((uint4*)(kl + row * 80) + c4) =
            *((const uint4*)(g_klo + ((size_t)b * NN + n0 + row) * CQ) + c4);
#pragma unroll
        for (int i = 0; i < 8; i++) {
            const int idx = t + i * 256;
            const int vr = idx >> 5, vc = idx & 31;
            *((uint4*)(vb + vr * 528) + vc) =
                *((const uint4*)(g_vh + ((size_t)b * NN + n0 + vr) * CCH) + vc);
        }
        __syncthreads();

        // ---- S = Q·K^T (hi/lo split) ----
        float sacc[8][4];
#pragma unroll
        for (int n = 0; n < 8; n++)
#pragma unroll
            for (int j = 0; j < 4; j++) sacc[n][j] = 0.f;
#pragma unroll
        for (int np = 0; np < 4; np++) {
#pragma unroll
            for (int ks = 0; ks < 2; ks++) {
                unsigned bh0, bh1, bh2, bh3, bl0, bl1, bl2, bl3;
                const int roff = (np * 16 + ((lane >> 4) << 3) + (lane & 7)) * 80
                               + ks * 32 + (((lane >> 3) & 1) << 4);
                ldsm_x4(bh0, bh1, bh2, bh3, smaddr(kh + roff));
                ldsm_x4(bl0, bl1, bl2, bl3, smaddr(kl + roff));
                mma_f16(sacc[np * 2],     qh[ks], bh0, bh1);
                mma_f16(sacc[np * 2],     ql[ks], bh0, bh1);
                mma_f16(sacc[np * 2],     qh[ks], bl0, bl1);
                mma_f16(sacc[np * 2 + 1], qh[ks], bh2, bh3);
                mma_f16(sacc[np * 2 + 1], ql[ks], bh2, bh3);
                mma_f16(sacc[np * 2 + 1], qh[ks], bl2, bl3);
            }
        }

        // ---- fragment softmax (log2 domain) ----
        float tm0 = sacc[0][0], tm1 = sacc[0][2];
#pragma unroll
        for (int n = 0; n < 8; n++) {
            tm0 = fmaxf(tm0, fmaxf(sacc[n][0], sacc[n][1]));
            tm1 = fmaxf(tm1, fmaxf(sacc[n][2], sacc[n][3]));
        }
        tm0 = fmaxf(tm0, __shfl_xor_sync(0xffffffffu, tm0, 1));
        tm0 = fmaxf(tm0, __shfl_xor_sync(0xffffffffu, tm0, 2));
        tm1 = fmaxf(tm1, __shfl_xor_sync(0xffffffffu, tm1, 1));
        tm1 = fmaxf(tm1, __shfl_xor_sync(0xffffffffu, tm1, 2));
        const float nm0 = fmaxf(rmax0, tm0), nm1 = fmaxf(rmax1, tm1);
        const float sc0 = exp2f(rmax0 - nm0), sc1 = exp2f(rmax1 - nm1);
        rmax0 = nm0; rmax1 = nm1;
        if (sc0 < 1.f || sc1 < 1.f) {
#pragma unroll
            for (int g = 0; g < 16; g++) {
                acc[g][0] *= sc0; acc[g][1] *= sc0;
                acc[g][2] *= sc1; acc[g][3] *= sc1;
            }
        }
        rsum0 *= sc0; rsum1 *= sc1;

        // exp + pack directly into PV A-fragments
        unsigned pf[4][4];
#pragma unroll
        for (int j = 0; j < 4; j++) {
            pf[j][0] = ex2h2(sacc[2*j][0]   - nm0, sacc[2*j][1]   - nm0);
            pf[j][1] = ex2h2(sacc[2*j][2]   - nm1, sacc[2*j][3]   - nm1);
            pf[j][2] = ex2h2(sacc[2*j+1][0] - nm0, sacc[2*j+1][1] - nm0);
            pf[j][3] = ex2h2(sacc[2*j+1][2] - nm1, sacc[2*j+1][3] - nm1);
        }
        // partial row sums from the SAME fp16 values used in PV
        {
            half2 a0 = __hadd2(hu(pf[0][0]), hu(pf[0][2]));
            half2 a1 = __hadd2(hu(pf[1][0]), hu(pf[1][2]));
            half2 a2 = __hadd2(hu(pf[2][0]), hu(pf[2][2]));
            half2 a3 = __hadd2(hu(pf[3][0]), hu(pf[3][2]));
            float2 f0 = __half22float2(__hadd2(a0, a1));
            float2 f1 = __half22float2(__hadd2(a2, a3));
            rsum0 += (f0.x + f0.y) + (f1.x + f1.y);
            half2 b0 = __hadd2(hu(pf[0][1]), hu(pf[0][3]));
            half2 b1 = __hadd2(hu(pf[1][1]), hu(pf[1][3]));
            half2 b2 = __hadd2(hu(pf[2][1]), hu(pf[2][3]));
            half2 b3 = __hadd2(hu(pf[3][1]), hu(pf[3][3]));
            float2 g0 = __half22float2(__hadd2(b0, b1));
            float2 g1 = __half22float2(__hadd2(b2, b3));
            rsum1 += (g0.x + g0.y) + (g1.x + g1.y);
        }

        // ---- PV: 16 rows x 128 cols (this warp's c-half) ----
#pragma unroll
        for (int j = 0; j < 4; j++) {
            const int vrow = (j * 16 + (lane & 15)) * 528
                           + ch * 256 + ((lane >> 4) << 4);
#pragma unroll
            for (int cc = 0; cc < 8; cc++) {
                unsigned v0, v1, v2, v3;
                ldsm_x4t(v0, v1, v2, v3, smaddr(vb + vrow + cc * 32));
                mma_f16(acc[cc * 2],     pf[j], v0, v1);
                mma_f16(acc[cc * 2 + 1], pf[j], v2, v3);
            }
        }
        __syncthreads();
    }

    // ---- epilogue: quad-reduce sums, normalize, write ----
    rsum0 += __shfl_xor_sync(0xffffffffu, rsum0, 1);
    rsum0 += __shfl_xor_sync(0xffffffffu, rsum0, 2);
    rsum1 += __shfl_xor_sync(0xffffffffu, rsum1, 1);
    rsum1 += __shfl_xor_sync(0xffffffffu, rsum1, 2);
    const float inv0 = 1.f / rsum0, inv1 = 1.f / rsum1;
    const int rowa = m0 + band * 16 + (lane >> 2);
#pragma unroll
    for (int g = 0; g < 16; g++) {
        const int col = ch * 128 + g * 8 + 2 * (lane & 3);
        *(half2*)(g_cat + ((size_t)b * NN + rowa) * 512 + col) =
            __floats2half2_rn(acc[g][0] * inv0, acc[g][1] * inv0);
        *(half2*)(g_cat + ((size_t)b * NN + rowa + 8) * 512 + col) =
            __floats2half2_rn(acc[g][2] * inv1, acc[g][3] * inv1);
    }
}

// ---------------------------------------------------------------------------
// Kernel 3: output projection via mma
// ---------------------------------------------------------------------------
__global__ __launch_bounds__(256) void outproj_kernel(
    const float* __restrict__ bo, float* __restrict__ y)
{
    __shared__ __align__(16) __half As[64 * 72];
    __shared__ __align__(16) __half Bs[128 * 72];

    const int b  = blockIdx.z;
    const int o0 = blockIdx.y * 64;
    const int m0 = blockIdx.x * 128;
    const int t  = threadIdx.x;
    const int lane = t & 31, wrp = t >> 5;
    const int ob = (wrp & 3) * 16;
    const int mh = (wrp >> 2) * 64;

    float acc[8][4];
#pragma unroll
    for (int i = 0; i < 8; i++)
#pragma unroll
        for (int j = 0; j < 4; j++) acc[i][j] = 0.f;

    for (int k0 = 0; k0 < 512; k0 += 64) {
#pragma unroll
        for (int i = 0; i < 2; i++) {
            const int idx = t + i * 256;
            const int row = idx >> 3, c16 = idx & 7;
            ((uint4*)As)[row * 9 + c16] =
                *((const uint4*)(g_woh + (size_t)(o0 + row) * 512 + k0) + c16);
        }
#pragma unroll
        for (int i = 0; i < 4; i++) {
            const int idx = t + i * 256;
            const int row = idx >> 3, c16 = idx & 7;
            ((uint4*)Bs)[row * 9 + c16] =
                *((const uint4*)(g_cat + ((size_t)b * NN + m0 + row) * 512 + k0) + c16);
        }
        __syncthreads();

        unsigned int af[4][4];
#pragma unroll
        for (int k4 = 0; k4 < 4; k4++) {
            unsigned int a = smaddr(As + (ob + (lane & 15)) * 72 + k4 * 16 + (lane >> 4) * 8);
            ldsm_x4(af[k4][0], af[k4][1], af[k4][2], af[k4][3], a);
        }
#pragma unroll
        for (int pr = 0; pr < 4; pr++) {
#pragma unroll
            for (int k4 = 0; k4 < 4; k4++) {
                unsigned int b0, b1, b2, b3;
                unsigned int a = smaddr(Bs + (mh + pr * 16 + (lane >> 4) * 8 + (lane & 7)) * 72
                                           + k4 * 16 + ((lane >> 3) & 1) * 8);
                ldsm_x4(b0, b1, b2, b3, a);
                mma_f16(acc[pr * 2],     af[k4], b0, b1);
                mma_f16(acc[pr * 2 + 1], af[k4], b2, b3);
            }
        }
        __syncthreads();
    }

    const int orow = o0 + ob + (lane >> 2);
    const float bi0 = bo[orow], bi1 = bo[orow + 8];
#pragma unroll
    for (int ch = 0; ch < 8; ch++) {
        const int m = m0 + mh + ch * 8 + (lane & 3) * 2;
        float2 v0, v1;
        v0.x = acc[ch][0] + bi0; v0.y = acc[ch][1] + bi0;
        v1.x = acc[ch][2] + bi1; v1.y = acc[ch][3] + bi1;
        *(float2*)(y + ((size_t)b * CCH + orow)     * NN + m) = v0;
        *(float2*)(y + ((size_t)b * CCH + orow + 8) * NN + m) = v1;
    }
}

// ---------------------------------------------------------------------------
extern "C" void kernel_launch(void* const* d_in, const int* in_sizes, int n_in,
                              void* d_out, int out_size)
{
    const float* x  = (const float*)d_in[0];
    const float* Wq = (const float*)d_in[1];
    const float* bq = (const float*)d_in[2];
    const float* Wk = (const float*)d_in[3];
    const float* bk = (const float*)d_in[4];
    const float* Wv = (const float*)d_in[5];
    const float* bv = (const float*)d_in[6];
    const float* Wo = (const float*)d_in[7];
    const float* bo = (const float*)d_in[8];
    float* y = (float*)d_out;

    cudaFuncSetAttribute(attn_kernel,
                         cudaFuncAttributeMaxDynamicSharedMemorySize,
                         ATTN_SMEM);

    wconv_kernel<<<512, 256>>>(Wo);
    xpose_kernel<<<dim3(128, 8, BB), dim3(32, 8)>>>(x);
    qkv_kernel<<<dim3(5, 64, BB), 256>>>(x, Wq, bq, Wk, bk, Wv, bv);
    attn_kernel<<<dim3(64, BB), 256, ATTN_SMEM>>>();
    outproj_kernel<<<dim3(32, 4, BB), 256>>>(bo, y);
}

// round 6
// speedup vs baseline: 3.4812x; 1.0739x over previous
#include <cuda_runtime.h>
#include <cuda_fp16.h>
#include <cstdint>
#include <math.h>

#define BB  4
#define CCH 256
#define CQ  32
#define NN  4096
#define LOG2E 1.4426950408889634f

// Scratch (device globals: no allocation allowed)
__device__ __half g_qhi[BB * NN * CQ];         // q * log2e, hi
__device__ __half g_qlo[BB * NN * CQ];         // q * log2e, lo
__device__ __half g_khi[BB * NN * CQ];
__device__ __half g_klo[BB * NN * CQ];
__device__ __half g_vh[BB * NN * CCH];         // [b][n][256] fp16
__device__ __half g_cat[BB * NN * 2 * CCH];    // [b][n][512]: [0:256)=attn, [256:512)=x^T
__device__ __half g_woh[CCH * 2 * CCH];        // Wo fp16 [o][512]

// ---------------- PTX helpers ----------------
__device__ __forceinline__ unsigned int smaddr(const void* p) {
    return (unsigned int)__cvta_generic_to_shared(p);
}
__device__ __forceinline__ void ldsm_x4(unsigned int& r0, unsigned int& r1,
                                        unsigned int& r2, unsigned int& r3,
                                        unsigned int a) {
    asm volatile("ldmatrix.sync.aligned.m8n8.x4.shared.b16 {%0,%1,%2,%3},[%4];\n"
                 : "=r"(r0), "=r"(r1), "=r"(r2), "=r"(r3) : "r"(a));
}
__device__ __forceinline__ void ldsm_x4t(unsigned int& r0, unsigned int& r1,
                                         unsigned int& r2, unsigned int& r3,
                                         unsigned int a) {
    asm volatile("ldmatrix.sync.aligned.m8n8.x4.trans.shared.b16 {%0,%1,%2,%3},[%4];\n"
                 : "=r"(r0), "=r"(r1), "=r"(r2), "=r"(r3) : "r"(a));
}
__device__ __forceinline__ void mma_f16(float* d, const unsigned int* a,
                                        unsigned int b0, unsigned int b1) {
    asm volatile("mma.sync.aligned.m16n8k16.row.col.f32.f16.f16.f32 "
                 "{%0,%1,%2,%3},{%4,%5,%6,%7},{%8,%9},{%0,%1,%2,%3};\n"
                 : "+f"(d[0]), "+f"(d[1]), "+f"(d[2]), "+f"(d[3])
                 : "r"(a[0]), "r"(a[1]), "r"(a[2]), "r"(a[3]), "r"(b0), "r"(b1));
}
__device__ __forceinline__ unsigned int ex2h2(float a, float b) {
    half2 h = __floats2half2_rn(a, b);
    unsigned int x = *(unsigned int*)&h, r;
    asm volatile("ex2.approx.f16x2 %0, %1;\n" : "=r"(r) : "r"(x));
    return r;
}
__device__ __forceinline__ half2 hu(unsigned int x) { return *(half2*)&x; }
__device__ __forceinline__ void barw(int id) {
    asm volatile("bar.sync %0, 64;\n" :: "r"(id));
}

// ---------------------------------------------------------------------------
// Kernel 0a: Wo -> fp16
// ---------------------------------------------------------------------------
__global__ void wconv_kernel(const float* __restrict__ Wo) {
    int i = blockIdx.x * blockDim.x + threadIdx.x;
    g_woh[i] = __float2half(Wo[i]);
}

// ---------------------------------------------------------------------------
// Kernel 0b: transpose-convert x -> g_cat[b][n][256+c]
// ---------------------------------------------------------------------------
__global__ void xpose_kernel(const float* __restrict__ x) {
    __shared__ float ts[32][33];
    const int b = blockIdx.z, n0 = blockIdx.x * 32, c0 = blockIdx.y * 32;
    const int txi = threadIdx.x, tyi = threadIdx.y;
#pragma unroll
    for (int i = 0; i < 4; i++) {
        int c = c0 + tyi + i * 8;
        ts[tyi + i * 8][txi] = x[((size_t)b * CCH + c) * NN + n0 + txi];
    }
    __syncthreads();
#pragma unroll
    for (int i = 0; i < 4; i++) {
        int n = n0 + tyi + i * 8;
        g_cat[((size_t)b * NN + n) * 512 + 256 + c0 + txi] =
            __float2half(ts[txi][tyi + i * 8]);
    }
}

// ---------------------------------------------------------------------------
// Kernel 1: fused QKV projection. q scaled by log2e; q/k hi+lo split; v fp16.
// ---------------------------------------------------------------------------
__global__ __launch_bounds__(256) void qkv_kernel(
    const float* __restrict__ x,
    const float* __restrict__ Wq, const float* __restrict__ bq,
    const float* __restrict__ Wk, const float* __restrict__ bk,
    const float* __restrict__ Wv, const float* __restrict__ bv)
{
    __shared__ float Ws[32][68];
    __shared__ float Xs[32][68];

    const int b  = blockIdx.z;
    const int o0 = blockIdx.x * 64;
    const int p0 = blockIdx.y * 64;
    const int t  = threadIdx.x;
    const int tx = t & 15, ty = t >> 4;

    const float* xb = x + (size_t)b * CCH * NN;

    float acc[4][4];
#pragma unroll
    for (int i = 0; i < 4; i++)
#pragma unroll
        for (int j = 0; j < 4; j++) acc[i][j] = 0.f;

    for (int kc = 0; kc < CCH; kc += 32) {
        {
            const int oo = t >> 2;
            const int kk = (t & 3) * 8;
            const int o  = o0 + oo;
            const float* wrow;
            if (o < 32)       wrow = Wq + (size_t)o * CCH;
            else if (o < 64)  wrow = Wk + (size_t)(o - 32) * CCH;
            else              wrow = Wv + (size_t)(o - 64) * CCH;
            float4 w0 = *(const float4*)(wrow + kc + kk);
            float4 w1 = *(const float4*)(wrow + kc + kk + 4);
            float w[8] = {w0.x, w0.y, w0.z, w0.w, w1.x, w1.y, w1.z, w1.w};
#pragma unroll
            for (int i = 0; i < 8; i++) Ws[kk + i][oo] = w[i];
        }
        {
            const int kk = t >> 3;
            const int pp = (t & 7) * 8;
            const float* xr = xb + (size_t)(kc + kk) * NN + p0 + pp;
            *(float4*)&Xs[kk][pp]     = *(const float4*)(xr);
            *(float4*)&Xs[kk][pp + 4] = *(const float4*)(xr + 4);
        }
        __syncthreads();

#pragma unroll
        for (int kk = 0; kk < 32; kk++) {
            float4 a4 = *(const float4*)&Ws[kk][ty * 4];
            float4 b4 = *(const float4*)&Xs[kk][tx * 4];
            float a[4]  = {a4.x, a4.y, a4.z, a4.w};
            float bx[4] = {b4.x, b4.y, b4.z, b4.w};
#pragma unroll
            for (int i = 0; i < 4; i++)
#pragma unroll
                for (int j = 0; j < 4; j++) acc[i][j] += a[i] * bx[j];
        }
        __syncthreads();
    }

    const int ov = o0 + ty * 4;
    if (ov < 64) {
        __half *bhi, *blo; int oloc; float4 bias4; float scl;
        if (ov < 32) {
            bhi = g_qhi + (size_t)b * NN * CQ; blo = g_qlo + (size_t)b * NN * CQ;
            oloc = ov; bias4 = *(const float4*)(bq + ov); scl = LOG2E;
        } else {
            bhi = g_khi + (size_t)b * NN * CQ; blo = g_klo + (size_t)b * NN * CQ;
            oloc = ov - 32; bias4 = *(const float4*)(bk + (ov - 32)); scl = 1.0f;
        }
#pragma unroll
        for (int j = 0; j < 4; j++) {
            const int p = p0 + tx * 4 + j;
            float v0 = (acc[0][j] + bias4.x) * scl;
            float v1 = (acc[1][j] + bias4.y) * scl;
            float v2 = (acc[2][j] + bias4.z) * scl;
            float v3 = (acc[3][j] + bias4.w) * scl;
            __half h0 = __float2half_rn(v0), h1 = __float2half_rn(v1);
            __half h2 = __float2half_rn(v2), h3 = __float2half_rn(v3);
            __half l0 = __float2half_rn(v0 - __half2float(h0));
            __half l1 = __float2half_rn(v1 - __half2float(h1));
            __half l2 = __float2half_rn(v2 - __half2float(h2));
            __half l3 = __float2half_rn(v3 - __half2float(h3));
            *(half2*)(bhi + (size_t)p * CQ + oloc)     = __halves2half2(h0, h1);
            *(half2*)(bhi + (size_t)p * CQ + oloc + 2) = __halves2half2(h2, h3);
            *(half2*)(blo + (size_t)p * CQ + oloc)     = __halves2half2(l0, l1);
            *(half2*)(blo + (size_t)p * CQ + oloc + 2) = __halves2half2(l2, l3);
        }
    } else {
        const int oloc = ov - 64;
        float4 bias4 = *(const float4*)(bv + oloc);
#pragma unroll
        for (int j = 0; j < 4; j++) {
            const int p = p0 + tx * 4 + j;
            __half* dst = g_vh + ((size_t)b * NN + p) * CCH + oloc;
            *(half2*)(dst)     = __floats2half2_rn(acc[0][j] + bias4.x, acc[1][j] + bias4.y);
            *(half2*)(dst + 2) = __floats2half2_rn(acc[2][j] + bias4.z, acc[3][j] + bias4.w);
        }
    }
}

// ---------------------------------------------------------------------------
// Kernel 2: flash attention, FA2 + split-S.
// 64q/block, 256 threads = 8 warps = 4 query-bands x 2 c-halves.
// Each warp computes S for its (band x 32-col half) only; band pair exchanges
// row-max and P through smem with NAMED barriers (2 warps, id band+1).
// PV: A-fragments ldsm'd from P smem; each warp its (band x 128-ch half).
// ---------------------------------------------------------------------------
#define A_KH  0
#define A_KL  5120
#define A_V   10240
#define A_PH  44032
#define A_RSX 53248
#define ATTN_SMEM 53760

__global__ __launch_bounds__(256, 2) void attn_kernel()
{
    extern __shared__ char sm[];
    char*   kh  = sm + A_KH;
    char*   kl  = sm + A_KL;
    char*   vb  = sm + A_V;
    __half* ph  = (__half*)(sm + A_PH);
    float*  rsx = (float*)(sm + A_RSX);   // [2][64] partial max / partial sum

    const int b    = blockIdx.y;
    const int m0   = blockIdx.x * 64;
    const int t    = threadIdx.x;
    const int lane = t & 31;
    const int wrp  = t >> 5;
    const int band = wrp & 3;        // 16-query band
    const int ch   = wrp >> 2;       // half index (S: 32 cols; PV: 128 chans)
    const int bid  = band + 1;       // named barrier id

    const int row = t >> 2, c4 = t & 3;
    const int r0 = band * 16 + (lane >> 2), r1 = r0 + 8;

    // ---- prologue: stage Q (hi/lo) in V area, grab fragments ----
    *((uint4*)(vb + row * 80) + c4) =
        *((const uint4*)(g_qhi + ((size_t)b * NN + m0 + row) * CQ) + c4);
    *((uint4*)(vb + 5120 + row * 80) + c4) =
        *((const uint4*)(g_qlo + ((size_t)b * NN + m0 + row) * CQ) + c4);
    __syncthreads();

    unsigned qh[2][4], ql[2][4];
    {
        const int aoff = (band * 16 + (lane & 15)) * 80 + ((lane >> 4) << 4);
#pragma unroll
        for (int ks = 0; ks < 2; ks++) {
            ldsm_x4(qh[ks][0], qh[ks][1], qh[ks][2], qh[ks][3],
                    smaddr(vb + aoff + ks * 32));
            ldsm_x4(ql[ks][0], ql[ks][1], ql[ks][2], ql[ks][3],
                    smaddr(vb + 5120 + aoff + ks * 32));
        }
    }
    __syncthreads();

    float acc[16][4];
#pragma unroll
    for (int g = 0; g < 16; g++)
#pragma unroll
        for (int j = 0; j < 4; j++) acc[g][j] = 0.f;
    float rmax0 = -INFINITY, rmax1 = -INFINITY, rsum0 = 0.f, rsum1 = 0.f;

    for (int nt = 0; nt < 64; nt++) {
        const int n0 = nt * 64;
        // ---- cooperative load K(hi/lo) + V tile ----
        *((uint4*)(kh + row * 80) + c4) =
            *((const uint4*)(g_khi + ((size_t)b * NN + n0 + row) * CQ) + c4);
        *((uint4*)(kl + row * 80) + c4) =
            *((const uint4*)(g_klo + ((size_t)b * NN + n0 + row) * CQ) + c4);
#pragma unroll
        for (int i = 0; i < 8; i++) {
            const int idx = t + i * 256;
            const int vr = idx >> 5, vc = idx & 31;
            *((uint4*)(vb + vr * 528) + vc) =
                *((const uint4*)(g_vh + ((size_t)b * NN + n0 + vr) * CCH) + vc);
        }
        __syncthreads();

        // ---- S = Q.K^T for OWN 32-col half (hi/lo split) ----
        float sacc[4][4];
#pragma unroll
        for (int n = 0; n < 4; n++)
#pragma unroll
            for (int j = 0; j < 4; j++) sacc[n][j] = 0.f;
#pragma unroll
        for (int np = 0; np < 2; np++) {
#pragma unroll
            for (int ks = 0; ks < 2; ks++) {
                unsigned bh0, bh1, bh2, bh3, bl0, bl1, bl2, bl3;
                const int roff = (ch * 32 + np * 16 + ((lane >> 4) << 3) + (lane & 7)) * 80
                               + ks * 32 + (((lane >> 3) & 1) << 4);
                ldsm_x4(bh0, bh1, bh2, bh3, smaddr(kh + roff));
                ldsm_x4(bl0, bl1, bl2, bl3, smaddr(kl + roff));
                mma_f16(sacc[np * 2],     qh[ks], bh0, bh1);
                mma_f16(sacc[np * 2],     ql[ks], bh0, bh1);
                mma_f16(sacc[np * 2],     qh[ks], bl0, bl1);
                mma_f16(sacc[np * 2 + 1], qh[ks], bh2, bh3);
                mma_f16(sacc[np * 2 + 1], ql[ks], bh2, bh3);
                mma_f16(sacc[np * 2 + 1], qh[ks], bl2, bl3);
            }
        }

        // ---- partial row max + band-pair exchange ----
        float tm0 = fmaxf(fmaxf(sacc[0][0], sacc[0][1]), fmaxf(sacc[1][0], sacc[1][1]));
        float tm1 = fmaxf(fmaxf(sacc[0][2], sacc[0][3]), fmaxf(sacc[1][2], sacc[1][3]));
        tm0 = fmaxf(tm0, fmaxf(fmaxf(sacc[2][0], sacc[2][1]), fmaxf(sacc[3][0], sacc[3][1])));
        tm1 = fmaxf(tm1, fmaxf(fmaxf(sacc[2][2], sacc[2][3]), fmaxf(sacc[3][2], sacc[3][3])));
        tm0 = fmaxf(tm0, __shfl_xor_sync(0xffffffffu, tm0, 1));
        tm0 = fmaxf(tm0, __shfl_xor_sync(0xffffffffu, tm0, 2));
        tm1 = fmaxf(tm1, __shfl_xor_sync(0xffffffffu, tm1, 1));
        tm1 = fmaxf(tm1, __shfl_xor_sync(0xffffffffu, tm1, 2));
        if ((lane & 3) == 0) { rsx[ch * 64 + r0] = tm0; rsx[ch * 64 + r1] = tm1; }
        barw(bid);
        tm0 = fmaxf(tm0, rsx[(ch ^ 1) * 64 + r0]);
        tm1 = fmaxf(tm1, rsx[(ch ^ 1) * 64 + r1]);

        const float nm0 = fmaxf(rmax0, tm0), nm1 = fmaxf(rmax1, tm1);
        const float sc0 = exp2f(rmax0 - nm0), sc1 = exp2f(rmax1 - nm1);
        rmax0 = nm0; rmax1 = nm1;
        if (sc0 < 1.f || sc1 < 1.f) {
#pragma unroll
            for (int g = 0; g < 16; g++) {
                acc[g][0] *= sc0; acc[g][1] *= sc0;
                acc[g][2] *= sc1; acc[g][3] *= sc1;
            }
        }
        rsum0 *= sc0; rsum1 *= sc1;

        // ---- exp own half, write P to smem, accumulate partial sums ----
        unsigned pr0[4], pr1[4];
#pragma unroll
        for (int nj = 0; nj < 4; nj++) {
            pr0[nj] = ex2h2(sacc[nj][0] - nm0, sacc[nj][1] - nm0);
            pr1[nj] = ex2h2(sacc[nj][2] - nm1, sacc[nj][3] - nm1);
            const int col = ch * 32 + nj * 8 + 2 * (lane & 3);
            *(half2*)(ph + r0 * 72 + col) = hu(pr0[nj]);
            *(half2*)(ph + r1 * 72 + col) = hu(pr1[nj]);
        }
        {
            float2 f0 = __half22float2(__hadd2(__hadd2(hu(pr0[0]), hu(pr0[1])),
                                               __hadd2(hu(pr0[2]), hu(pr0[3]))));
            float2 f1 = __half22float2(__hadd2(__hadd2(hu(pr1[0]), hu(pr1[1])),
                                               __hadd2(hu(pr1[2]), hu(pr1[3]))));
            rsum0 += f0.x + f0.y;
            rsum1 += f1.x + f1.y;
        }
        barw(bid);   // band's full P (both halves) ready

        // ---- PV: P from smem as A-fragments, V ldsm.x4t, own 128-ch half ----
        unsigned pf[4][4];
#pragma unroll
        for (int ks = 0; ks < 4; ks++)
            ldsm_x4(pf[ks][0], pf[ks][1], pf[ks][2], pf[ks][3],
                smaddr((char*)ph + (band * 16 + (lane & 15)) * 144
                       + ks * 32 + ((lane >> 4) << 4)));
#pragma unroll
        for (int ks = 0; ks < 4; ks++) {
            const int vrow = (ks * 16 + (lane & 15)) * 528
                           + ch * 256 + ((lane >> 4) << 4);
#pragma unroll
            for (int cc = 0; cc < 8; cc++) {
                unsigned v0, v1, v2, v3;
                ldsm_x4t(v0, v1, v2, v3, smaddr(vb + vrow + cc * 32));
                mma_f16(acc[cc * 2],     pf[ks], v0, v1);
                mma_f16(acc[cc * 2 + 1], pf[ks], v2, v3);
            }
        }
        __syncthreads();
    }

    // ---- epilogue: combine partial sums across band pair, normalize ----
    rsum0 += __shfl_xor_sync(0xffffffffu, rsum0, 1);
    rsum0 += __shfl_xor_sync(0xffffffffu, rsum0, 2);
    rsum1 += __shfl_xor_sync(0xffffffffu, rsum1, 1);
    rsum1 += __shfl_xor_sync(0xffffffffu, rsum1, 2);
    if ((lane & 3) == 0) { rsx[ch * 64 + r0] = rsum0; rsx[ch * 64 + r1] = rsum1; }
    barw(bid);
    rsum0 += rsx[(ch ^ 1) * 64 + r0];
    rsum1 += rsx[(ch ^ 1) * 64 + r1];

    const float inv0 = 1.f / rsum0, inv1 = 1.f / rsum1;
    const int rowa = m0 + r0;
#pragma unroll
    for (int g = 0; g < 16; g++) {
        const int col = ch * 128 + g * 8 + 2 * (lane & 3);
        *(half2*)(g_cat + ((size_t)b * NN + rowa) * 512 + col) =
            __floats2half2_rn(acc[g][0] * inv0, acc[g][1] * inv0);
        *(half2*)(g_cat + ((size_t)b * NN + rowa + 8) * 512 + col) =
            __floats2half2_rn(acc[g][2] * inv1, acc[g][3] * inv1);
    }
}

// ---------------------------------------------------------------------------
// Kernel 3: output projection via mma
// ---------------------------------------------------------------------------
__global__ __launch_bounds__(256) void outproj_kernel(
    const float* __restrict__ bo, float* __restrict__ y)
{
    __shared__ __align__(16) __half As[64 * 72];
    __shared__ __align__(16) __half Bs[128 * 72];

    const int b  = blockIdx.z;
    const int o0 = blockIdx.y * 64;
    const int m0 = blockIdx.x * 128;
    const int t  = threadIdx.x;
    const int lane = t & 31, wrp = t >> 5;
    const int ob = (wrp & 3) * 16;
    const int mh = (wrp >> 2) * 64;

    float acc[8][4];
#pragma unroll
    for (int i = 0; i < 8; i++)
#pragma unroll
        for (int j = 0; j < 4; j++) acc[i][j] = 0.f;

    for (int k0 = 0; k0 < 512; k0 += 64) {
#pragma unroll
        for (int i = 0; i < 2; i++) {
            const int idx = t + i * 256;
            const int row = idx >> 3, c16 = idx & 7;
            ((uint4*)As)[row * 9 + c16] =
                *((const uint4*)(g_woh + (size_t)(o0 + row) * 512 + k0) + c16);
        }
#pragma unroll
        for (int i = 0; i < 4; i++) {
            const int idx = t + i * 256;
            const int row = idx >> 3, c16 = idx & 7;
            ((uint4*)Bs)[row * 9 + c16] =
                *((const uint4*)(g_cat + ((size_t)b * NN + m0 + row) * 512 + k0) + c16);
        }
        __syncthreads();

        unsigned int af[4][4];
#pragma unroll
        for (int k4 = 0; k4 < 4; k4++) {
            unsigned int a = smaddr(As + (ob + (lane & 15)) * 72 + k4 * 16 + (lane >> 4) * 8);
            ldsm_x4(af[k4][0], af[k4][1], af[k4][2], af[k4][3], a);
        }
#pragma unroll
        for (int pr = 0; pr < 4; pr++) {
#pragma unroll
            for (int k4 = 0; k4 < 4; k4++) {
                unsigned int b0, b1, b2, b3;
                unsigned int a = smaddr(Bs + (mh + pr * 16 + (lane >> 4) * 8 + (lane & 7)) * 72
                                           + k4 * 16 + ((lane >> 3) & 1) * 8);
                ldsm_x4(b0, b1, b2, b3, a);
                mma_f16(acc[pr * 2],     af[k4], b0, b1);
                mma_f16(acc[pr * 2 + 1], af[k4], b2, b3);
            }
        }
        __syncthreads();
    }

    const int orow = o0 + ob + (lane >> 2);
    const float bi0 = bo[orow], bi1 = bo[orow + 8];
#pragma unroll
    for (int ch = 0; ch < 8; ch++) {
        const int m = m0 + mh + ch * 8 + (lane & 3) * 2;
        float2 v0, v1;
        v0.x = acc[ch][0] + bi0; v0.y = acc[ch][1] + bi0;
        v1.x = acc[ch][2] + bi1; v1.y = acc[ch][3] + bi1;
        *(float2*)(y + ((size_t)b * CCH + orow)     * NN + m) = v0;
        *(float2*)(y + ((size_t)b * CCH + orow + 8) * NN + m) = v1;
    }
}

// ---------------------------------------------------------------------------
extern "C" void kernel_launch(void* const* d_in, const int* in_sizes, int n_in,
                              void* d_out, int out_size)
{
    const float* x  = (const float*)d_in[0];
    const float* Wq = (const float*)d_in[1];
    const float* bq = (const float*)d_in[2];
    const float* Wk = (const float*)d_in[3];
    const float* bk = (const float*)d_in[4];
    const float* Wv = (const float*)d_in[5];
    const float* bv = (const float*)d_in[6];
    const float* Wo = (const float*)d_in[7];
    const float* bo = (const float*)d_in[8];
    float* y = (float*)d_out;

    cudaFuncSetAttribute(attn_kernel,
                         cudaFuncAttributeMaxDynamicSharedMemorySize,
                         ATTN_SMEM);

    wconv_kernel<<<512, 256>>>(Wo);
    xpose_kernel<<<dim3(128, 8, BB), dim3(32, 8)>>>(x);
    qkv_kernel<<<dim3(5, 64, BB), 256>>>(x, Wq, bq, Wk, bk, Wv, bv);
    attn_kernel<<<dim3(64, BB), 256, ATTN_SMEM>>>();
    outproj_kernel<<<dim3(32, 4, BB), 256>>>(bo, y);
}

// round 8
// speedup vs baseline: 3.6460x; 1.0473x over previous
#include <cuda_runtime.h>
#include <cuda_fp16.h>
#include <cstdint>
#include <math.h>

#define BB  4
#define CCH 256
#define CQ  32
#define NN  4096
#define LOG2E 1.4426950408889634f

// Scratch (device globals: no allocation allowed)
__device__ __half g_qhi[BB * NN * CQ];         // q * log2e, hi
__device__ __half g_qlo[BB * NN * CQ];         // q * log2e, lo
__device__ __half g_khi[BB * NN * CQ];
__device__ __half g_klo[BB * NN * CQ];
__device__ __half g_vh[BB * NN * CCH];         // [b][n][256] fp16
__device__ __half g_cat[BB * NN * 2 * CCH];    // [b][n][512]: [0:256)=attn, [256:512)=x^T
__device__ __half g_woh[CCH * 2 * CCH];        // Wo fp16 [o][512]

// ---------------- PTX helpers ----------------
__device__ __forceinline__ unsigned int smaddr(const void* p) {
    return (unsigned int)__cvta_generic_to_shared(p);
}
__device__ __forceinline__ void ldsm_x4(unsigned int& r0, unsigned int& r1,
                                        unsigned int& r2, unsigned int& r3,
                                        unsigned int a) {
    asm volatile("ldmatrix.sync.aligned.m8n8.x4.shared.b16 {%0,%1,%2,%3},[%4];\n"
                 : "=r"(r0), "=r"(r1), "=r"(r2), "=r"(r3) : "r"(a));
}
__device__ __forceinline__ void ldsm_x4t(unsigned int& r0, unsigned int& r1,
                                         unsigned int& r2, unsigned int& r3,
                                         unsigned int a) {
    asm volatile("ldmatrix.sync.aligned.m8n8.x4.trans.shared.b16 {%0,%1,%2,%3},[%4];\n"
                 : "=r"(r0), "=r"(r1), "=r"(r2), "=r"(r3) : "r"(a));
}
__device__ __forceinline__ void mma_f16(float* d, const unsigned int* a,
                                        unsigned int b0, unsigned int b1) {
    asm volatile("mma.sync.aligned.m16n8k16.row.col.f32.f16.f16.f32 "
                 "{%0,%1,%2,%3},{%4,%5,%6,%7},{%8,%9},{%0,%1,%2,%3};\n"
                 : "+f"(d[0]), "+f"(d[1]), "+f"(d[2]), "+f"(d[3])
                 : "r"(a[0]), "r"(a[1]), "r"(a[2]), "r"(a[3]), "r"(b0), "r"(b1));
}
__device__ __forceinline__ unsigned int ex2h2(float a, float b) {
    half2 h = __floats2half2_rn(a, b);
    unsigned int x = *(unsigned int*)&h, r;
    asm volatile("ex2.approx.f16x2 %0, %1;\n" : "=r"(r) : "r"(x));
    return r;
}
__device__ __forceinline__ half2 hu(unsigned int x) { return *(half2*)&x; }
__device__ __forceinline__ void barw(int id) {
    asm volatile("bar.sync %0, 64;\n" :: "r"(id));
}
__device__ __forceinline__ void cpa16(unsigned int dst, const void* src) {
    asm volatile("cp.async.cg.shared.global [%0], [%1], 16;\n" :: "r"(dst), "l"(src));
}
__device__ __forceinline__ void cpa_commit() {
    asm volatile("cp.async.commit_group;\n");
}
__device__ __forceinline__ void cpa_wait0() {
    asm volatile("cp.async.wait_group 0;\n");
}

// ---------------------------------------------------------------------------
// Kernel 0a: Wo -> fp16
// ---------------------------------------------------------------------------
__global__ void wconv_kernel(const float* __restrict__ Wo) {
    int i = blockIdx.x * blockDim.x + threadIdx.x;
    g_woh[i] = __float2half(Wo[i]);
}

// ---------------------------------------------------------------------------
// Kernel 0b: transpose-convert x -> g_cat[b][n][256+c]
// ---------------------------------------------------------------------------
__global__ void xpose_kernel(const float* __restrict__ x) {
    __shared__ float ts[32][33];
    const int b = blockIdx.z, n0 = blockIdx.x * 32, c0 = blockIdx.y * 32;
    const int txi = threadIdx.x, tyi = threadIdx.y;
#pragma unroll
    for (int i = 0; i < 4; i++) {
        int c = c0 + tyi + i * 8;
        ts[tyi + i * 8][txi] = x[((size_t)b * CCH + c) * NN + n0 + txi];
    }
    __syncthreads();
#pragma unroll
    for (int i = 0; i < 4; i++) {
        int n = n0 + tyi + i * 8;
        g_cat[((size_t)b * NN + n) * 512 + 256 + c0 + txi] =
            __float2half(ts[txi][tyi + i * 8]);
    }
}

// ---------------------------------------------------------------------------
// Kernel 1: fused QKV projection. q scaled by log2e; q/k hi+lo split; v fp16.
// ---------------------------------------------------------------------------
__global__ __launch_bounds__(256) void qkv_kernel(
    const float* __restrict__ x,
    const float* __restrict__ Wq, const float* __restrict__ bq,
    const float* __restrict__ Wk, const float* __restrict__ bk,
    const float* __restrict__ Wv, const float* __restrict__ bv)
{
    __shared__ float Ws[32][68];
    __shared__ float Xs[32][68];

    const int b  = blockIdx.z;
    const int o0 = blockIdx.x * 64;
    const int p0 = blockIdx.y * 64;
    const int t  = threadIdx.x;
    const int tx = t & 15, ty = t >> 4;

    const float* xb = x + (size_t)b * CCH * NN;

    float acc[4][4];
#pragma unroll
    for (int i = 0; i < 4; i++)
#pragma unroll
        for (int j = 0; j < 4; j++) acc[i][j] = 0.f;

    for (int kc = 0; kc < CCH; kc += 32) {
        {
            const int oo = t >> 2;
            const int kk = (t & 3) * 8;
            const int o  = o0 + oo;
            const float* wrow;
            if (o < 32)       wrow = Wq + (size_t)o * CCH;
            else if (o < 64)  wrow = Wk + (size_t)(o - 32) * CCH;
            else              wrow = Wv + (size_t)(o - 64) * CCH;
            float4 w0 = *(const float4*)(wrow + kc + kk);
            float4 w1 = *(const float4*)(wrow + kc + kk + 4);
            float w[8] = {w0.x, w0.y, w0.z, w0.w, w1.x, w1.y, w1.z, w1.w};
#pragma unroll
            for (int i = 0; i < 8; i++) Ws[kk + i][oo] = w[i];
        }
        {
            const int kk = t >> 3;
            const int pp = (t & 7) * 8;
            const float* xr = xb + (size_t)(kc + kk) * NN + p0 + pp;
            *(float4*)&Xs[kk][pp]     = *(const float4*)(xr);
            *(float4*)&Xs[kk][pp + 4] = *(const float4*)(xr + 4);
        }
        __syncthreads();

#pragma unroll
        for (int kk = 0; kk < 32; kk++) {
            float4 a4 = *(const float4*)&Ws[kk][ty * 4];
            float4 b4 = *(const float4*)&Xs[kk][tx * 4];
            float a[4]  = {a4.x, a4.y, a4.z, a4.w};
            float bx[4] = {b4.x, b4.y, b4.z, b4.w};
#pragma unroll
            for (int i = 0; i < 4; i++)
#pragma unroll
                for (int j = 0; j < 4; j++) acc[i][j] += a[i] * bx[j];
        }
        __syncthreads();
    }

    const int ov = o0 + ty * 4;
    if (ov < 64) {
        __half *bhi, *blo; int oloc; float4 bias4; float scl;
        if (ov < 32) {
            bhi = g_qhi + (size_t)b * NN * CQ; blo = g_qlo + (size_t)b * NN * CQ;
            oloc = ov; bias4 = *(const float4*)(bq + ov); scl = LOG2E;
        } else {
            bhi = g_khi + (size_t)b * NN * CQ; blo = g_klo + (size_t)b * NN * CQ;
            oloc = ov - 32; bias4 = *(const float4*)(bk + (ov - 32)); scl = 1.0f;
        }
#pragma unroll
        for (int j = 0; j < 4; j++) {
            const int p = p0 + tx * 4 + j;
            float v0 = (acc[0][j] + bias4.x) * scl;
            float v1 = (acc[1][j] + bias4.y) * scl;
            float v2 = (acc[2][j] + bias4.z) * scl;
            float v3 = (acc[3][j] + bias4.w) * scl;
            __half h0 = __float2half_rn(v0), h1 = __float2half_rn(v1);
            __half h2 = __float2half_rn(v2), h3 = __float2half_rn(v3);
            __half l0 = __float2half_rn(v0 - __half2float(h0));
            __half l1 = __float2half_rn(v1 - __half2float(h1));
            __half l2 = __float2half_rn(v2 - __half2float(h2));
            __half l3 = __float2half_rn(v3 - __half2float(h3));
            *(half2*)(bhi + (size_t)p * CQ + oloc)     = __halves2half2(h0, h1);
            *(half2*)(bhi + (size_t)p * CQ + oloc + 2) = __halves2half2(h2, h3);
            *(half2*)(blo + (size_t)p * CQ + oloc)     = __halves2half2(l0, l1);
            *(half2*)(blo + (size_t)p * CQ + oloc + 2) = __halves2half2(l2, l3);
        }
    } else {
        const int oloc = ov - 64;
        float4 bias4 = *(const float4*)(bv + oloc);
#pragma unroll
        for (int j = 0; j < 4; j++) {
            const int p = p0 + tx * 4 + j;
            __half* dst = g_vh + ((size_t)b * NN + p) * CCH + oloc;
            *(half2*)(dst)     = __floats2half2_rn(acc[0][j] + bias4.x, acc[1][j] + bias4.y);
            *(half2*)(dst + 2) = __floats2half2_rn(acc[2][j] + bias4.z, acc[3][j] + bias4.w);
        }
    }
}

// ---------------------------------------------------------------------------
// Kernel 2: flash attention. 64q/block, 256 threads = 8 warps.
//  S phase:  warp = (band = wrp&3) x (n-half = wrp>>2): 16q x 32n, hi/lo mma.
//  PV phase: warp = (qg = wrp&1) x (cq = wrp>>1): 32q x 64c  -> each V ldsm
//            feeds 4 mma (2 m-tiles). K/V staged via cp.async.
// ---------------------------------------------------------------------------
#define A_KH  0
#define A_KL  5120
#define A_V   10240
#define A_PH  44032
#define A_RSX 53248
#define A_SCB 53760
#define ATTN_SMEM 54016

__global__ __launch_bounds__(256, 2) void attn_kernel()
{
    extern __shared__ char sm[];
    char*   kh  = sm + A_KH;
    char*   kl  = sm + A_KL;
    char*   vb  = sm + A_V;
    __half* ph  = (__half*)(sm + A_PH);
    float*  rsx = (float*)(sm + A_RSX);   // [2][64] partial max / partial sum
    float*  scb = (float*)(sm + A_SCB);   // [64] per-row scale / inv-sum

    const int b    = blockIdx.y;
    const int m0   = blockIdx.x * 64;
    const int t    = threadIdx.x;
    const int lane = t & 31;
    const int wrp  = t >> 5;
    const int band = wrp & 3;        // S: 16-query band
    const int ch   = wrp >> 2;       // S: 32-col half
    const int bid  = band + 1;       // named barrier id
    const int qg   = wrp & 1;        // PV: 32-query group
    const int cq   = wrp >> 1;       // PV: 64-chan quarter

    const int row = t >> 2, c4 = t & 3;
    const int r0 = band * 16 + (lane >> 2), r1 = r0 + 8;

    // ---- prologue: stage Q (hi/lo) in V area, grab fragments ----
    *((uint4*)(vb + row * 80) + c4) =
        *((const uint4*)(g_qhi + ((size_t)b * NN + m0 + row) * CQ) + c4);
    *((uint4*)(vb + 5120 + row * 80) + c4) =
        *((const uint4*)(g_qlo + ((size_t)b * NN + m0 + row) * CQ) + c4);
    __syncthreads();

    unsigned qh[2][4], ql[2][4];
    {
        const int aoff = (band * 16 + (lane & 15)) * 80 + ((lane >> 4) << 4);
#pragma unroll
        for (int ks = 0; ks < 2; ks++) {
            ldsm_x4(qh[ks][0], qh[ks][1], qh[ks][2], qh[ks][3],
                    smaddr(vb + aoff + ks * 32));
            ldsm_x4(ql[ks][0], ql[ks][1], ql[ks][2], ql[ks][3],
                    smaddr(vb + 5120 + aoff + ks * 32));
        }
    }
    __syncthreads();

    float acc[16][4];
#pragma unroll
    for (int g = 0; g < 16; g++)
#pragma unroll
        for (int j = 0; j < 4; j++) acc[g][j] = 0.f;
    float rmax0 = -INFINITY, rmax1 = -INFINITY, rsum0 = 0.f, rsum1 = 0.f;

    for (int nt = 0; nt < 64; nt++) {
        const int n0 = nt * 64;
        // ---- cp.async loads: K hi/lo + V tile ----
        cpa16(smaddr(kh + row * 80 + c4 * 16),
              g_khi + ((size_t)b * NN + n0 + row) * CQ + c4 * 8);
        cpa16(smaddr(kl + row * 80 + c4 * 16),
              g_klo + ((size_t)b * NN + n0 + row) * CQ + c4 * 8);
        const __half* vsrc = g_vh + ((size_t)b * NN + n0) * CCH;
#pragma unroll
        for (int i = 0; i < 8; i++) {
            const int idx = t + i * 256;
            const int vr = idx >> 5, vc = idx & 31;
            cpa16(smaddr(vb + vr * 528 + vc * 16), vsrc + vr * CCH + vc * 8);
        }
        cpa_commit();
        cpa_wait0();
        __syncthreads();

        // ---- S = Q.K^T for OWN 32-col half (hi/lo split) ----
        float sacc[4][4];
#pragma unroll
        for (int n = 0; n < 4; n++)
#pragma unroll
            for (int j = 0; j < 4; j++) sacc[n][j] = 0.f;
#pragma unroll
        for (int np = 0; np < 2; np++) {
#pragma unroll
            for (int ks = 0; ks < 2; ks++) {
                unsigned bh0, bh1, bh2, bh3, bl0, bl1, bl2, bl3;
                const int roff = (ch * 32 + np * 16 + ((lane >> 4) << 3) + (lane & 7)) * 80
                               + ks * 32 + (((lane >> 3) & 1) << 4);
                ldsm_x4(bh0, bh1, bh2, bh3, smaddr(kh + roff));
                ldsm_x4(bl0, bl1, bl2, bl3, smaddr(kl + roff));
                mma_f16(sacc[np * 2],     qh[ks], bh0, bh1);
                mma_f16(sacc[np * 2],     ql[ks], bh0, bh1);
                mma_f16(sacc[np * 2],     qh[ks], bl0, bl1);
                mma_f16(sacc[np * 2 + 1], qh[ks], bh2, bh3);
                mma_f16(sacc[np * 2 + 1], ql[ks], bh2, bh3);
                mma_f16(sacc[np * 2 + 1], qh[ks], bl2, bl3);
            }
        }

        // ---- partial row max + band-pair exchange ----
        float tm0 = fmaxf(fmaxf(sacc[0][0], sacc[0][1]), fmaxf(sacc[1][0], sacc[1][1]));
        float tm1 = fmaxf(fmaxf(sacc[0][2], sacc[0][3]), fmaxf(sacc[1][2], sacc[1][3]));
        tm0 = fmaxf(tm0, fmaxf(fmaxf(sacc[2][0], sacc[2][1]), fmaxf(sacc[3][0], sacc[3][1])));
        tm1 = fmaxf(tm1, fmaxf(fmaxf(sacc[2][2], sacc[2][3]), fmaxf(sacc[3][2], sacc[3][3])));
        tm0 = fmaxf(tm0, __shfl_xor_sync(0xffffffffu, tm0, 1));
        tm0 = fmaxf(tm0, __shfl_xor_sync(0xffffffffu, tm0, 2));
        tm1 = fmaxf(tm1, __shfl_xor_sync(0xffffffffu, tm1, 1));
        tm1 = fmaxf(tm1, __shfl_xor_sync(0xffffffffu, tm1, 2));
        if ((lane & 3) == 0) { rsx[ch * 64 + r0] = tm0; rsx[ch * 64 + r1] = tm1; }
        barw(bid);
        tm0 = fmaxf(tm0, rsx[(ch ^ 1) * 64 + r0]);
        tm1 = fmaxf(tm1, rsx[(ch ^ 1) * 64 + r1]);

        const float nm0 = fmaxf(rmax0, tm0), nm1 = fmaxf(rmax1, tm1);
        const float sc0 = exp2f(rmax0 - nm0), sc1 = exp2f(rmax1 - nm1);
        rmax0 = nm0; rmax1 = nm1;
        rsum0 *= sc0; rsum1 *= sc1;
        if (ch == 0 && (lane & 3) == 0) { scb[r0] = sc0; scb[r1] = sc1; }

        // ---- exp own half, write P to smem, accumulate partial sums ----
        unsigned pr0[4], pr1[4];
#pragma unroll
        for (int nj = 0; nj < 4; nj++) {
            pr0[nj] = ex2h2(sacc[nj][0] - nm0, sacc[nj][1] - nm0);
            pr1[nj] = ex2h2(sacc[nj][2] - nm1, sacc[nj][3] - nm1);
            const int col = ch * 32 + nj * 8 + 2 * (lane & 3);
            *(half2*)(ph + r0 * 72 + col) = hu(pr0[nj]);
            *(half2*)(ph + r1 * 72 + col) = hu(pr1[nj]);
        }
        {
            float2 f0 = __half22float2(__hadd2(__hadd2(hu(pr0[0]), hu(pr0[1])),
                                               __hadd2(hu(pr0[2]), hu(pr0[3]))));
            float2 f1 = __half22float2(__hadd2(__hadd2(hu(pr1[0]), hu(pr1[1])),
                                               __hadd2(hu(pr1[2]), hu(pr1[3]))));
            rsum0 += f0.x + f0.y;
            rsum1 += f1.x + f1.y;
        }
        __syncthreads();   // P + scb ready block-wide

        // ---- PV: warp = 32q (qg) x 64c (cq) ----
        {
            const int rb = qg * 32 + (lane >> 2);
            const float s0 = scb[rb],      s1 = scb[rb + 8];
            const float s2 = scb[rb + 16], s3 = scb[rb + 24];
            const bool skip = __all_sync(0xffffffffu,
                (s0 == 1.f) && (s1 == 1.f) && (s2 == 1.f) && (s3 == 1.f));
            if (!skip) {
#pragma unroll
                for (int nj = 0; nj < 8; nj++) {
                    acc[nj][0] *= s0; acc[nj][1] *= s0;
                    acc[nj][2] *= s1; acc[nj][3] *= s1;
                    acc[8 + nj][0] *= s2; acc[8 + nj][1] *= s2;
                    acc[8 + nj][2] *= s3; acc[8 + nj][3] *= s3;
                }
            }
#pragma unroll
            for (int ks = 0; ks < 4; ks++) {
                unsigned pf0[4], pf1[4];
                const int pcol = ks * 32 + ((lane >> 4) << 4);
                ldsm_x4(pf0[0], pf0[1], pf0[2], pf0[3],
                    smaddr((char*)ph + (qg * 32 + (lane & 15)) * 144 + pcol));
                ldsm_x4(pf1[0], pf1[1], pf1[2], pf1[3],
                    smaddr((char*)ph + (qg * 32 + 16 + (lane & 15)) * 144 + pcol));
                const int vrow = (ks * 16 + (lane & 15)) * 528
                               + cq * 128 + ((lane >> 4) << 4);
#pragma unroll
                for (int cc = 0; cc < 4; cc++) {
                    unsigned v0, v1, v2, v3;
                    ldsm_x4t(v0, v1, v2, v3, smaddr(vb + vrow + cc * 32));
                    mma_f16(acc[cc * 2],         pf0, v0, v1);
                    mma_f16(acc[cc * 2 + 1],     pf0, v2, v3);
                    mma_f16(acc[8 + cc * 2],     pf1, v0, v1);
                    mma_f16(acc[8 + cc * 2 + 1], pf1, v2, v3);
                }
            }
        }
        __syncthreads();   // safe to overwrite K/V/P next tile
    }

    // ---- epilogue: combine partial sums, compute inv, normalize, write ----
    rsum0 += __shfl_xor_sync(0xffffffffu, rsum0, 1);
    rsum0 += __shfl_xor_sync(0xffffffffu, rsum0, 2);
    rsum1 += __shfl_xor_sync(0xffffffffu, rsum1, 1);
    rsum1 += __shfl_xor_sync(0xffffffffu, rsum1, 2);
    if ((lane & 3) == 0) { rsx[ch * 64 + r0] = rsum0; rsx[ch * 64 + r1] = rsum1; }
    __syncthreads();
    if (ch == 0 && (lane & 3) == 0) {
        scb[r0] = 1.f / (rsum0 + rsx[64 + r0]);
        scb[r1] = 1.f / (rsum1 + rsx[64 + r1]);
    }
    __syncthreads();

    const int rb = qg * 32 + (lane >> 2);
    const float i0 = scb[rb],      i1 = scb[rb + 8];
    const float i2 = scb[rb + 16], i3 = scb[rb + 24];
#pragma unroll
    for (int nj = 0; nj < 8; nj++) {
        const int col = cq * 64 + nj * 8 + 2 * (lane & 3);
        *(half2*)(g_cat + ((size_t)b * NN + m0 + rb) * 512 + col) =
            __floats2half2_rn(acc[nj][0] * i0, acc[nj][1] * i0);
        *(half2*)(g_cat + ((size_t)b * NN + m0 + rb + 8) * 512 + col) =
            __floats2half2_rn(acc[nj][2] * i1, acc[nj][3] * i1);
        *(half2*)(g_cat + ((size_t)b * NN + m0 + rb + 16) * 512 + col) =
            __floats2half2_rn(acc[8 + nj][0] * i2, acc[8 + nj][1] * i2);
        *(half2*)(g_cat + ((size_t)b * NN + m0 + rb + 24) * 512 + col) =
            __floats2half2_rn(acc[8 + nj][2] * i3, acc[8 + nj][3] * i3);
    }
}

// ---------------------------------------------------------------------------
// Kernel 3: output projection via mma
// ---------------------------------------------------------------------------
__global__ __launch_bounds__(256) void outproj_kernel(
    const float* __restrict__ bo, float* __restrict__ y)
{
    __shared__ __align__(16) __half As[64 * 72];
    __shared__ __align__(16) __half Bs[128 * 72];

    const int b  = blockIdx.z;
    const int o0 = blockIdx.y * 64;
    const int m0 = blockIdx.x * 128;
    const int t  = threadIdx.x;
    const int lane = t & 31, wrp = t >> 5;
    const int ob = (wrp & 3) * 16;
    const int mh = (wrp >> 2) * 64;

    float acc[8][4];
#pragma unroll
    for (int i = 0; i < 8; i++)
#pragma unroll
        for (int j = 0; j < 4; j++) acc[i][j] = 0.f;

    for (int k0 = 0; k0 < 512; k0 += 64) {
#pragma unroll
        for (int i = 0; i < 2; i++) {
            const int idx = t + i * 256;
            const int row = idx >> 3, c16 = idx & 7;
            ((uint4*)As)[row * 9 + c16] =
                *((const uint4*)(g_woh + (size_t)(o0 + row) * 512 + k0) + c16);
        }
#pragma unroll
        for (int i = 0; i < 4; i++) {
            const int idx = t + i * 256;
            const int row = idx >> 3, c16 = idx & 7;
            ((uint4*)Bs)[row * 9 + c16] =
                *((const uint4*)(g_cat + ((size_t)b * NN + m0 + row) * 512 + k0) + c16);
        }
        __syncthreads();

        unsigned int af[4][4];
#pragma unroll
        for (int k4 = 0; k4 < 4; k4++) {
            unsigned int a = smaddr(As + (ob + (lane & 15)) * 72 + k4 * 16 + (lane >> 4) * 8);
            ldsm_x4(af[k4][0], af[k4][1], af[k4][2], af[k4][3], a);
        }
#pragma unroll
        for (int pr = 0; pr < 4; pr++) {
#pragma unroll
            for (int k4 = 0; k4 < 4; k4++) {
                unsigned int b0, b1, b2, b3;
                unsigned int a = smaddr(Bs + (mh + pr * 16 + (lane >> 4) * 8 + (lane & 7)) * 72
                                           + k4 * 16 + ((lane >> 3) & 1) * 8);
                ldsm_x4(b0, b1, b2, b3, a);
                mma_f16(acc[pr * 2],     af[k4], b0, b1);
                mma_f16(acc[pr * 2 + 1], af[k4], b2, b3);
            }
        }
        __syncthreads();
    }

    const int orow = o0 + ob + (lane >> 2);
    const float bi0 = bo[orow], bi1 = bo[orow + 8];
#pragma unroll
    for (int ch = 0; ch < 8; ch++) {
        const int m = m0 + mh + ch * 8 + (lane & 3) * 2;
        float2 v0, v1;
        v0.x = acc[ch][0] + bi0; v0.y = acc[ch][1] + bi0;
        v1.x = acc[ch][2] + bi1; v1.y = acc[ch][3] + bi1;
        *(float2*)(y + ((size_t)b * CCH + orow)     * NN + m) = v0;
        *(float2*)(y + ((size_t)b * CCH + orow + 8) * NN + m) = v1;
    }
}

// ---------------------------------------------------------------------------
extern "C" void kernel_launch(void* const* d_in, const int* in_sizes, int n_in,
                              void* d_out, int out_size)
{
    const float* x  = (const float*)d_in[0];
    const float* Wq = (const float*)d_in[1];
    const float* bq = (const float*)d_in[2];
    const float* Wk = (const float*)d_in[3];
    const float* bk = (const float*)d_in[4];
    const float* Wv = (const float*)d_in[5];
    const float* bv = (const float*)d_in[6];
    const float* Wo = (const float*)d_in[7];
    const float* bo = (const float*)d_in[8];
    float* y = (float*)d_out;

    cudaFuncSetAttribute(attn_kernel,
                         cudaFuncAttributeMaxDynamicSharedMemorySize,
                         ATTN_SMEM);

    wconv_kernel<<<512, 256>>>(Wo);
    xpose_kernel<<<dim3(128, 8, BB), dim3(32, 8)>>>(x);
    qkv_kernel<<<dim3(5, 64, BB), 256>>>(x, Wq, bq, Wk, bk, Wv, bv);
    attn_kernel<<<dim3(64, BB), 256, ATTN_SMEM>>>();
    outproj_kernel<<<dim3(32, 4, BB), 256>>>(bo, y);
}

// round 9
// speedup vs baseline: 3.7294x; 1.0229x over previous
#include <cuda_runtime.h>
#include <cuda_fp16.h>
#include <cstdint>
#include <math.h>

#define BB  4
#define CCH 256
#define CQ  32
#define NN  4096
#define LOG2E 1.4426950408889634f

// Scratch (device globals: no allocation allowed)
__device__ __half g_qhi[BB * NN * CQ];         // q * log2e, hi
__device__ __half g_qlo[BB * NN * CQ];         // q * log2e, lo
__device__ __half g_khi[BB * NN * CQ];
__device__ __half g_klo[BB * NN * CQ];
__device__ __half g_vh[BB * NN * CCH];         // [b][n][256] fp16
__device__ __half g_cat[BB * NN * 2 * CCH];    // [b][n][512]: [0:256)=attn, [256:512)=x^T
__device__ __half g_woh[CCH * 2 * CCH];        // Wo fp16 [o][512]

// ---------------- PTX helpers ----------------
__device__ __forceinline__ unsigned int smaddr(const void* p) {
    return (unsigned int)__cvta_generic_to_shared(p);
}
__device__ __forceinline__ void ldsm_x4(unsigned int& r0, unsigned int& r1,
                                        unsigned int& r2, unsigned int& r3,
                                        unsigned int a) {
    asm volatile("ldmatrix.sync.aligned.m8n8.x4.shared.b16 {%0,%1,%2,%3},[%4];\n"
                 : "=r"(r0), "=r"(r1), "=r"(r2), "=r"(r3) : "r"(a));
}
__device__ __forceinline__ void ldsm_x4t(unsigned int& r0, unsigned int& r1,
                                         unsigned int& r2, unsigned int& r3,
                                         unsigned int a) {
    asm volatile("ldmatrix.sync.aligned.m8n8.x4.trans.shared.b16 {%0,%1,%2,%3},[%4];\n"
                 : "=r"(r0), "=r"(r1), "=r"(r2), "=r"(r3) : "r"(a));
}
__device__ __forceinline__ void mma_f16(float* d, const unsigned int* a,
                                        unsigned int b0, unsigned int b1) {
    asm volatile("mma.sync.aligned.m16n8k16.row.col.f32.f16.f16.f32 "
                 "{%0,%1,%2,%3},{%4,%5,%6,%7},{%8,%9},{%0,%1,%2,%3};\n"
                 : "+f"(d[0]), "+f"(d[1]), "+f"(d[2]), "+f"(d[3])
                 : "r"(a[0]), "r"(a[1]), "r"(a[2]), "r"(a[3]), "r"(b0), "r"(b1));
}
__device__ __forceinline__ unsigned int ex2h2(float a, float b) {
    half2 h = __floats2half2_rn(a, b);
    unsigned int x = *(unsigned int*)&h, r;
    asm volatile("ex2.approx.f16x2 %0, %1;\n" : "=r"(r) : "r"(x));
    return r;
}
__device__ __forceinline__ half2 hu(unsigned int x) { return *(half2*)&x; }
__device__ __forceinline__ void barw(int id) {
    asm volatile("bar.sync %0, 64;\n" :: "r"(id));
}
__device__ __forceinline__ void cpa16(unsigned int dst, const void* src) {
    asm volatile("cp.async.cg.shared.global [%0], [%1], 16;\n" :: "r"(dst), "l"(src));
}
__device__ __forceinline__ void cpa_commit() {
    asm volatile("cp.async.commit_group;\n");
}
__device__ __forceinline__ void cpa_wait0() {
    asm volatile("cp.async.wait_group 0;\n");
}
__device__ __forceinline__ void cpa_wait1() {
    asm volatile("cp.async.wait_group 1;\n");
}

// ---------------------------------------------------------------------------
// Kernel 0a: Wo -> fp16
// ---------------------------------------------------------------------------
__global__ void wconv_kernel(const float* __restrict__ Wo) {
    int i = blockIdx.x * blockDim.x + threadIdx.x;
    g_woh[i] = __float2half(Wo[i]);
}

// ---------------------------------------------------------------------------
// Kernel 0b: transpose-convert x -> g_cat[b][n][256+c]
// ---------------------------------------------------------------------------
__global__ void xpose_kernel(const float* __restrict__ x) {
    __shared__ float ts[32][33];
    const int b = blockIdx.z, n0 = blockIdx.x * 32, c0 = blockIdx.y * 32;
    const int txi = threadIdx.x, tyi = threadIdx.y;
#pragma unroll
    for (int i = 0; i < 4; i++) {
        int c = c0 + tyi + i * 8;
        ts[tyi + i * 8][txi] = x[((size_t)b * CCH + c) * NN + n0 + txi];
    }
    __syncthreads();
#pragma unroll
    for (int i = 0; i < 4; i++) {
        int n = n0 + tyi + i * 8;
        g_cat[((size_t)b * NN + n) * 512 + 256 + c0 + txi] =
            __float2half(ts[txi][tyi + i * 8]);
    }
}

// ---------------------------------------------------------------------------
// Kernel 1: fused QKV projection. q scaled by log2e; q/k hi+lo split; v fp16.
// ---------------------------------------------------------------------------
__global__ __launch_bounds__(256) void qkv_kernel(
    const float* __restrict__ x,
    const float* __restrict__ Wq, const float* __restrict__ bq,
    const float* __restrict__ Wk, const float* __restrict__ bk,
    const float* __restrict__ Wv, const float* __restrict__ bv)
{
    __shared__ float Ws[32][68];
    __shared__ float Xs[32][68];

    const int b  = blockIdx.z;
    const int o0 = blockIdx.x * 64;
    const int p0 = blockIdx.y * 64;
    const int t  = threadIdx.x;
    const int tx = t & 15, ty = t >> 4;

    const float* xb = x + (size_t)b * CCH * NN;

    float acc[4][4];
#pragma unroll
    for (int i = 0; i < 4; i++)
#pragma unroll
        for (int j = 0; j < 4; j++) acc[i][j] = 0.f;

    for (int kc = 0; kc < CCH; kc += 32) {
        {
            const int oo = t >> 2;
            const int kk = (t & 3) * 8;
            const int o  = o0 + oo;
            const float* wrow;
            if (o < 32)       wrow = Wq + (size_t)o * CCH;
            else if (o < 64)  wrow = Wk + (size_t)(o - 32) * CCH;
            else              wrow = Wv + (size_t)(o - 64) * CCH;
            float4 w0 = *(const float4*)(wrow + kc + kk);
            float4 w1 = *(const float4*)(wrow + kc + kk + 4);
            float w[8] = {w0.x, w0.y, w0.z, w0.w, w1.x, w1.y, w1.z, w1.w};
#pragma unroll
            for (int i = 0; i < 8; i++) Ws[kk + i][oo] = w[i];
        }
        {
            const int kk = t >> 3;
            const int pp = (t & 7) * 8;
            const float* xr = xb + (size_t)(kc + kk) * NN + p0 + pp;
            *(float4*)&Xs[kk][pp]     = *(const float4*)(xr);
            *(float4*)&Xs[kk][pp + 4] = *(const float4*)(xr + 4);
        }
        __syncthreads();

#pragma unroll
        for (int kk = 0; kk < 32; kk++) {
            float4 a4 = *(const float4*)&Ws[kk][ty * 4];
            float4 b4 = *(const float4*)&Xs[kk][tx * 4];
            float a[4]  = {a4.x, a4.y, a4.z, a4.w};
            float bx[4] = {b4.x, b4.y, b4.z, b4.w};
#pragma unroll
            for (int i = 0; i < 4; i++)
#pragma unroll
                for (int j = 0; j < 4; j++) acc[i][j] += a[i] * bx[j];
        }
        __syncthreads();
    }

    const int ov = o0 + ty * 4;
    if (ov < 64) {
        __half *bhi, *blo; int oloc; float4 bias4; float scl;
        if (ov < 32) {
            bhi = g_qhi + (size_t)b * NN * CQ; blo = g_qlo + (size_t)b * NN * CQ;
            oloc = ov; bias4 = *(const float4*)(bq + ov); scl = LOG2E;
        } else {
            bhi = g_khi + (size_t)b * NN * CQ; blo = g_klo + (size_t)b * NN * CQ;
            oloc = ov - 32; bias4 = *(const float4*)(bk + (ov - 32)); scl = 1.0f;
        }
#pragma unroll
        for (int j = 0; j < 4; j++) {
            const int p = p0 + tx * 4 + j;
            float v0 = (acc[0][j] + bias4.x) * scl;
            float v1 = (acc[1][j] + bias4.y) * scl;
            float v2 = (acc[2][j] + bias4.z) * scl;
            float v3 = (acc[3][j] + bias4.w) * scl;
            __half h0 = __float2half_rn(v0), h1 = __float2half_rn(v1);
            __half h2 = __float2half_rn(v2), h3 = __float2half_rn(v3);
            __half l0 = __float2half_rn(v0 - __half2float(h0));
            __half l1 = __float2half_rn(v1 - __half2float(h1));
            __half l2 = __float2half_rn(v2 - __half2float(h2));
            __half l3 = __float2half_rn(v3 - __half2float(h3));
            *(half2*)(bhi + (size_t)p * CQ + oloc)     = __halves2half2(h0, h1);
            *(half2*)(bhi + (size_t)p * CQ + oloc + 2) = __halves2half2(h2, h3);
            *(half2*)(blo + (size_t)p * CQ + oloc)     = __halves2half2(l0, l1);
            *(half2*)(blo + (size_t)p * CQ + oloc + 2) = __halves2half2(l2, l3);
        }
    } else {
        const int oloc = ov - 64;
        float4 bias4 = *(const float4*)(bv + oloc);
#pragma unroll
        for (int j = 0; j < 4; j++) {
            const int p = p0 + tx * 4 + j;
            __half* dst = g_vh + ((size_t)b * NN + p) * CCH + oloc;
            *(half2*)(dst)     = __floats2half2_rn(acc[0][j] + bias4.x, acc[1][j] + bias4.y);
            *(half2*)(dst + 2) = __floats2half2_rn(acc[2][j] + bias4.z, acc[3][j] + bias4.w);
        }
    }
}

// ---------------------------------------------------------------------------
// Kernel 2: flash attention. 64q/block, 256 threads = 8 warps.
//  Double-buffered cp.async pipeline: tile nt+1 prefetches during tile nt's
//  S + softmax + PV. S: (band x 32n); PV: (32q x 64c).
// smem per buffer: kh 5120 | kl 5120 | v 33792  -> stride 44032, x2 buffers.
// ---------------------------------------------------------------------------
#define A_BUF   44032
#define A_PH    88064
#define A_RSX   97280
#define A_SCB   97792
#define ATTN_SMEM 98048

__global__ __launch_bounds__(256, 2) void attn_kernel()
{
    extern __shared__ char sm[];
    __half* ph  = (__half*)(sm + A_PH);
    float*  rsx = (float*)(sm + A_RSX);   // [2][64] partial max / partial sum
    float*  scb = (float*)(sm + A_SCB);   // [64] per-row scale / inv-sum

    const int b    = blockIdx.y;
    const int m0   = blockIdx.x * 64;
    const int t    = threadIdx.x;
    const int lane = t & 31;
    const int wrp  = t >> 5;
    const int band = wrp & 3;        // S: 16-query band
    const int ch   = wrp >> 2;       // S: 32-col half
    const int bid  = band + 1;       // named barrier id
    const int qg   = wrp & 1;        // PV: 32-query group
    const int cq   = wrp >> 1;       // PV: 64-chan quarter

    const int row = t >> 2, c4 = t & 3;
    const int r0 = band * 16 + (lane >> 2), r1 = r0 + 8;

    // ---- prologue ----
    // Stage Q (hi/lo) in buf1's V area (not touched until iter0 prefetches
    // tile1). Meanwhile kick off tile0's cp.async into buf0.
    {
        char* qa = sm + A_BUF + 10240;
        *((uint4*)(qa + row * 80) + c4) =
            *((const uint4*)(g_qhi + ((size_t)b * NN + m0 + row) * CQ) + c4);
        *((uint4*)(qa + 5120 + row * 80) + c4) =
            *((const uint4*)(g_qlo + ((size_t)b * NN + m0 + row) * CQ) + c4);

        cpa16(smaddr(sm + row * 80 + c4 * 16),
              g_khi + ((size_t)b * NN + row) * CQ + c4 * 8);
        cpa16(smaddr(sm + 5120 + row * 80 + c4 * 16),
              g_klo + ((size_t)b * NN + row) * CQ + c4 * 8);
        const __half* vsrc = g_vh + (size_t)b * NN * CCH;
#pragma unroll
        for (int i = 0; i < 8; i++) {
            const int idx = t + i * 256;
            const int vr = idx >> 5, vc = idx & 31;
            cpa16(smaddr(sm + 10240 + vr * 528 + vc * 16), vsrc + vr * CCH + vc * 8);
        }
        cpa_commit();
    }
    __syncthreads();

    unsigned qh[2][4], ql[2][4];
    {
        char* qa = sm + A_BUF + 10240;
        const int aoff = (band * 16 + (lane & 15)) * 80 + ((lane >> 4) << 4);
#pragma unroll
        for (int ks = 0; ks < 2; ks++) {
            ldsm_x4(qh[ks][0], qh[ks][1], qh[ks][2], qh[ks][3],
                    smaddr(qa + aoff + ks * 32));
            ldsm_x4(ql[ks][0], ql[ks][1], ql[ks][2], ql[ks][3],
                    smaddr(qa + 5120 + aoff + ks * 32));
        }
    }
    __syncthreads();   // Q fragments extracted before iter0 prefetch hits buf1

    float acc[16][4];
#pragma unroll
    for (int g = 0; g < 16; g++)
#pragma unroll
        for (int j = 0; j < 4; j++) acc[g][j] = 0.f;
    float rmax0 = -INFINITY, rmax1 = -INFINITY, rsum0 = 0.f, rsum1 = 0.f;

    for (int nt = 0; nt < 64; nt++) {
        char* buf = sm + (nt & 1) * A_BUF;
        char* kh  = buf;
        char* kl  = buf + 5120;
        char* vb  = buf + 10240;

        // ---- prefetch tile nt+1 into the other buffer ----
        if (nt < 63) {
            char* nb = sm + ((nt + 1) & 1) * A_BUF;
            const int n1 = (nt + 1) * 64;
            cpa16(smaddr(nb + row * 80 + c4 * 16),
                  g_khi + ((size_t)b * NN + n1 + row) * CQ + c4 * 8);
            cpa16(smaddr(nb + 5120 + row * 80 + c4 * 16),
                  g_klo + ((size_t)b * NN + n1 + row) * CQ + c4 * 8);
            const __half* vsrc = g_vh + ((size_t)b * NN + n1) * CCH;
#pragma unroll
            for (int i = 0; i < 8; i++) {
                const int idx = t + i * 256;
                const int vr = idx >> 5, vc = idx & 31;
                cpa16(smaddr(nb + 10240 + vr * 528 + vc * 16),
                      vsrc + vr * CCH + vc * 8);
            }
            cpa_commit();
            cpa_wait1();   // tile nt complete; nt+1 still in flight
        } else {
            cpa_wait0();
        }
        __syncthreads();

        // ---- S = Q.K^T for OWN 32-col half (hi/lo split) ----
        float sacc[4][4];
#pragma unroll
        for (int n = 0; n < 4; n++)
#pragma unroll
            for (int j = 0; j < 4; j++) sacc[n][j] = 0.f;
#pragma unroll
        for (int np = 0; np < 2; np++) {
#pragma unroll
            for (int ks = 0; ks < 2; ks++) {
                unsigned bh0, bh1, bh2, bh3, bl0, bl1, bl2, bl3;
                const int roff = (ch * 32 + np * 16 + ((lane >> 4) << 3) + (lane & 7)) * 80
                               + ks * 32 + (((lane >> 3) & 1) << 4);
                ldsm_x4(bh0, bh1, bh2, bh3, smaddr(kh + roff));
                ldsm_x4(bl0, bl1, bl2, bl3, smaddr(kl + roff));
                mma_f16(sacc[np * 2],     qh[ks], bh0, bh1);
                mma_f16(sacc[np * 2],     ql[ks], bh0, bh1);
                mma_f16(sacc[np * 2],     qh[ks], bl0, bl1);
                mma_f16(sacc[np * 2 + 1], qh[ks], bh2, bh3);
                mma_f16(sacc[np * 2 + 1], ql[ks], bh2, bh3);
                mma_f16(sacc[np * 2 + 1], qh[ks], bl2, bl3);
            }
        }

        // ---- partial row max + band-pair exchange ----
        float tm0 = fmaxf(fmaxf(sacc[0][0], sacc[0][1]), fmaxf(sacc[1][0], sacc[1][1]));
        float tm1 = fmaxf(fmaxf(sacc[0][2], sacc[0][3]), fmaxf(sacc[1][2], sacc[1][3]));
        tm0 = fmaxf(tm0, fmaxf(fmaxf(sacc[2][0], sacc[2][1]), fmaxf(sacc[3][0], sacc[3][1])));
        tm1 = fmaxf(tm1, fmaxf(fmaxf(sacc[2][2], sacc[2][3]), fmaxf(sacc[3][2], sacc[3][3])));
        tm0 = fmaxf(tm0, __shfl_xor_sync(0xffffffffu, tm0, 1));
        tm0 = fmaxf(tm0, __shfl_xor_sync(0xffffffffu, tm0, 2));
        tm1 = fmaxf(tm1, __shfl_xor_sync(0xffffffffu, tm1, 1));
        tm1 = fmaxf(tm1, __shfl_xor_sync(0xffffffffu, tm1, 2));
        if ((lane & 3) == 0) { rsx[ch * 64 + r0] = tm0; rsx[ch * 64 + r1] = tm1; }
        barw(bid);
        tm0 = fmaxf(tm0, rsx[(ch ^ 1) * 64 + r0]);
        tm1 = fmaxf(tm1, rsx[(ch ^ 1) * 64 + r1]);

        const float nm0 = fmaxf(rmax0, tm0), nm1 = fmaxf(rmax1, tm1);
        const float sc0 = exp2f(rmax0 - nm0), sc1 = exp2f(rmax1 - nm1);
        rmax0 = nm0; rmax1 = nm1;
        rsum0 *= sc0; rsum1 *= sc1;
        if (ch == 0 && (lane & 3) == 0) { scb[r0] = sc0; scb[r1] = sc1; }

        // ---- exp own half, write P to smem, accumulate partial sums ----
        unsigned pr0[4], pr1[4];
#pragma unroll
        for (int nj = 0; nj < 4; nj++) {
            pr0[nj] = ex2h2(sacc[nj][0] - nm0, sacc[nj][1] - nm0);
            pr1[nj] = ex2h2(sacc[nj][2] - nm1, sacc[nj][3] - nm1);
            const int col = ch * 32 + nj * 8 + 2 * (lane & 3);
            *(half2*)(ph + r0 * 72 + col) = hu(pr0[nj]);
            *(half2*)(ph + r1 * 72 + col) = hu(pr1[nj]);
        }
        {
            float2 f0 = __half22float2(__hadd2(__hadd2(hu(pr0[0]), hu(pr0[1])),
                                               __hadd2(hu(pr0[2]), hu(pr0[3]))));
            float2 f1 = __half22float2(__hadd2(__hadd2(hu(pr1[0]), hu(pr1[1])),
                                               __hadd2(hu(pr1[2]), hu(pr1[3]))));
            rsum0 += f0.x + f0.y;
            rsum1 += f1.x + f1.y;
        }
        __syncthreads();   // P + scb ready block-wide

        // ---- PV: warp = 32q (qg) x 64c (cq) ----
        {
            const int rb = qg * 32 + (lane >> 2);
            const float s0 = scb[rb],      s1 = scb[rb + 8];
            const float s2 = scb[rb + 16], s3 = scb[rb + 24];
            const bool skip = __all_sync(0xffffffffu,
                (s0 == 1.f) && (s1 == 1.f) && (s2 == 1.f) && (s3 == 1.f));
            if (!skip) {
#pragma unroll
                for (int nj = 0; nj < 8; nj++) {
                    acc[nj][0] *= s0; acc[nj][1] *= s0;
                    acc[nj][2] *= s1; acc[nj][3] *= s1;
                    acc[8 + nj][0] *= s2; acc[8 + nj][1] *= s2;
                    acc[8 + nj][2] *= s3; acc[8 + nj][3] *= s3;
                }
            }
#pragma unroll
            for (int ks = 0; ks < 4; ks++) {
                unsigned pf0[4], pf1[4];
                const int pcol = ks * 32 + ((lane >> 4) << 4);
                ldsm_x4(pf0[0], pf0[1], pf0[2], pf0[3],
                    smaddr((char*)ph + (qg * 32 + (lane & 15)) * 144 + pcol));
                ldsm_x4(pf1[0], pf1[1], pf1[2], pf1[3],
                    smaddr((char*)ph + (qg * 32 + 16 + (lane & 15)) * 144 + pcol));
                const int vrow = (ks * 16 + (lane & 15)) * 528
                               + cq * 128 + ((lane >> 4) << 4);
#pragma unroll
                for (int cc = 0; cc < 4; cc++) {
                    unsigned v0, v1, v2, v3;
                    ldsm_x4t(v0, v1, v2, v3, smaddr(vb + vrow + cc * 32));
                    mma_f16(acc[cc * 2],         pf0, v0, v1);
                    mma_f16(acc[cc * 2 + 1],     pf0, v2, v3);
                    mma_f16(acc[8 + cc * 2],     pf1, v0, v1);
                    mma_f16(acc[8 + cc * 2 + 1], pf1, v2, v3);
                }
            }
        }
        __syncthreads();   // done reading this buffer + P; safe for reuse
    }

    // ---- epilogue: combine partial sums, compute inv, normalize, write ----
    rsum0 += __shfl_xor_sync(0xffffffffu, rsum0, 1);
    rsum0 += __shfl_xor_sync(0xffffffffu, rsum0, 2);
    rsum1 += __shfl_xor_sync(0xffffffffu, rsum1, 1);
    rsum1 += __shfl_xor_sync(0xffffffffu, rsum1, 2);
    if ((lane & 3) == 0) { rsx[ch * 64 + r0] = rsum0; rsx[ch * 64 + r1] = rsum1; }
    __syncthreads();
    if (ch == 0 && (lane & 3) == 0) {
        scb[r0] = 1.f / (rsum0 + rsx[64 + r0]);
        scb[r1] = 1.f / (rsum1 + rsx[64 + r1]);
    }
    __syncthreads();

    const int rb = qg * 32 + (lane >> 2);
    const float i0 = scb[rb],      i1 = scb[rb + 8];
    const float i2 = scb[rb + 16], i3 = scb[rb + 24];
#pragma unroll
    for (int nj = 0; nj < 8; nj++) {
        const int col = cq * 64 + nj * 8 + 2 * (lane & 3);
        *(half2*)(g_cat + ((size_t)b * NN + m0 + rb) * 512 + col) =
            __floats2half2_rn(acc[nj][0] * i0, acc[nj][1] * i0);
        *(half2*)(g_cat + ((size_t)b * NN + m0 + rb + 8) * 512 + col) =
            __floats2half2_rn(acc[nj][2] * i1, acc[nj][3] * i1);
        *(half2*)(g_cat + ((size_t)b * NN + m0 + rb + 16) * 512 + col) =
            __floats2half2_rn(acc[8 + nj][0] * i2, acc[8 + nj][1] * i2);
        *(half2*)(g_cat + ((size_t)b * NN + m0 + rb + 24) * 512 + col) =
            __floats2half2_rn(acc[8 + nj][2] * i3, acc[8 + nj][3] * i3);
    }
}

// ---------------------------------------------------------------------------
// Kernel 3: output projection via mma
// ---------------------------------------------------------------------------
__global__ __launch_bounds__(256) void outproj_kernel(
    const float* __restrict__ bo, float* __restrict__ y)
{
    __shared__ __align__(16) __half As[64 * 72];
    __shared__ __align__(16) __half Bs[128 * 72];

    const int b  = blockIdx.z;
    const int o0 = blockIdx.y * 64;
    const int m0 = blockIdx.x * 128;
    const int t  = threadIdx.x;
    const int lane = t & 31, wrp = t >> 5;
    const int ob = (wrp & 3) * 16;
    const int mh = (wrp >> 2) * 64;

    float acc[8][4];
#pragma unroll
    for (int i = 0; i < 8; i++)
#pragma unroll
        for (int j = 0; j < 4; j++) acc[i][j] = 0.f;

    for (int k0 = 0; k0 < 512; k0 += 64) {
#pragma unroll
        for (int i = 0; i < 2; i++) {
            const int idx = t + i * 256;
            const int row = idx >> 3, c16 = idx & 7;
            ((uint4*)As)[row * 9 + c16] =
                *((const uint4*)(g_woh + (size_t)(o0 + row) * 512 + k0) + c16);
        }
#pragma unroll
        for (int i = 0; i < 4; i++) {
            const int idx = t + i * 256;
            const int row = idx >> 3, c16 = idx & 7;
            ((uint4*)Bs)[row * 9 + c16] =
                *((const uint4*)(g_cat + ((size_t)b * NN + m0 + row) * 512 + k0) + c16);
        }
        __syncthreads();

        unsigned int af[4][4];
#pragma unroll
        for (int k4 = 0; k4 < 4; k4++) {
            unsigned int a = smaddr(As + (ob + (lane & 15)) * 72 + k4 * 16 + (lane >> 4) * 8);
            ldsm_x4(af[k4][0], af[k4][1], af[k4][2], af[k4][3], a);
        }
#pragma unroll
        for (int pr = 0; pr < 4; pr++) {
#pragma unroll
            for (int k4 = 0; k4 < 4; k4++) {
                unsigned int b0, b1, b2, b3;
                unsigned int a = smaddr(Bs + (mh + pr * 16 + (lane >> 4) * 8 + (lane & 7)) * 72
                                           + k4 * 16 + ((lane >> 3) & 1) * 8);
                ldsm_x4(b0, b1, b2, b3, a);
                mma_f16(acc[pr * 2],     af[k4], b0, b1);
                mma_f16(acc[pr * 2 + 1], af[k4], b2, b3);
            }
        }
        __syncthreads();
    }

    const int orow = o0 + ob + (lane >> 2);
    const float bi0 = bo[orow], bi1 = bo[orow + 8];
#pragma unroll
    for (int ch = 0; ch < 8; ch++) {
        const int m = m0 + mh + ch * 8 + (lane & 3) * 2;
        float2 v0, v1;
        v0.x = acc[ch][0] + bi0; v0.y = acc[ch][1] + bi0;
        v1.x = acc[ch][2] + bi1; v1.y = acc[ch][3] + bi1;
        *(float2*)(y + ((size_t)b * CCH + orow)     * NN + m) = v0;
        *(float2*)(y + ((size_t)b * CCH + orow + 8) * NN + m) = v1;
    }
}

// ---------------------------------------------------------------------------
extern "C" void kernel_launch(void* const* d_in, const int* in_sizes, int n_in,
                              void* d_out, int out_size)
{
    const float* x  = (const float*)d_in[0];
    const float* Wq = (const float*)d_in[1];
    const float* bq = (const float*)d_in[2];
    const float* Wk = (const float*)d_in[3];
    const float* bk = (const float*)d_in[4];
    const float* Wv = (const float*)d_in[5];
    const float* bv = (const float*)d_in[6];
    const float* Wo = (const float*)d_in[7];
    const float* bo = (const float*)d_in[8];
    float* y = (float*)d_out;

    cudaFuncSetAttribute(attn_kernel,
                         cudaFuncAttributeMaxDynamicSharedMemorySize,
                         ATTN_SMEM);

    wconv_kernel<<<512, 256>>>(Wo);
    xpose_kernel<<<dim3(128, 8, BB), dim3(32, 8)>>>(x);
    qkv_kernel<<<dim3(5, 64, BB), 256>>>(x, Wq, bq, Wk, bk, Wv, bv);
    attn_kernel<<<dim3(64, BB), 256, ATTN_SMEM>>>();
    outproj_kernel<<<dim3(32, 4, BB), 256>>>(bo, y);
}

// round 10
// speedup vs baseline: 4.3369x; 1.1629x over previous
#include <cuda_runtime.h>
#include <cuda_fp16.h>
#include <cstdint>
#include <math.h>

#define BB  4
#define CCH 256
#define CQ  32
#define NN  4096
#define LOG2E 1.4426950408889634f

// Scratch (device globals: no allocation allowed)
__device__ __half g_qhi[BB * NN * CQ];         // q * log2e, hi
__device__ __half g_qlo[BB * NN * CQ];         // q * log2e, lo
__device__ __half g_khi[BB * NN * CQ];
__device__ __half g_klo[BB * NN * CQ];
__device__ __half g_vh[BB * NN * CCH];         // [b][n][256] fp16
__device__ __half g_cat[BB * NN * 2 * CCH];    // [b][n][512]: [0:256)=attn, [256:512)=x^T
__device__ __half g_woh[CCH * 2 * CCH];        // Wo fp16 [o][512]
__device__ __half g_whi[320 * CCH];            // fused QKV weight hi (q rows * log2e)
__device__ __half g_wlo[320 * CCH];            // fused QKV weight lo
__device__ float  g_bias[320];                 // fused QKV bias (q rows * log2e)

// ---------------- PTX helpers ----------------
__device__ __forceinline__ unsigned int smaddr(const void* p) {
    return (unsigned int)__cvta_generic_to_shared(p);
}
__device__ __forceinline__ void ldsm_x4(unsigned int& r0, unsigned int& r1,
                                        unsigned int& r2, unsigned int& r3,
                                        unsigned int a) {
    asm volatile("ldmatrix.sync.aligned.m8n8.x4.shared.b16 {%0,%1,%2,%3},[%4];\n"
                 : "=r"(r0), "=r"(r1), "=r"(r2), "=r"(r3) : "r"(a));
}
__device__ __forceinline__ void ldsm_x4t(unsigned int& r0, unsigned int& r1,
                                         unsigned int& r2, unsigned int& r3,
                                         unsigned int a) {
    asm volatile("ldmatrix.sync.aligned.m8n8.x4.trans.shared.b16 {%0,%1,%2,%3},[%4];\n"
                 : "=r"(r0), "=r"(r1), "=r"(r2), "=r"(r3) : "r"(a));
}
__device__ __forceinline__ void mma_f16(float* d, const unsigned int* a,
                                        unsigned int b0, unsigned int b1) {
    asm volatile("mma.sync.aligned.m16n8k16.row.col.f32.f16.f16.f32 "
                 "{%0,%1,%2,%3},{%4,%5,%6,%7},{%8,%9},{%0,%1,%2,%3};\n"
                 : "+f"(d[0]), "+f"(d[1]), "+f"(d[2]), "+f"(d[3])
                 : "r"(a[0]), "r"(a[1]), "r"(a[2]), "r"(a[3]), "r"(b0), "r"(b1));
}
__device__ __forceinline__ unsigned int ex2h2(float a, float b) {
    half2 h = __floats2half2_rn(a, b);
    unsigned int x = *(unsigned int*)&h, r;
    asm volatile("ex2.approx.f16x2 %0, %1;\n" : "=r"(r) : "r"(x));
    return r;
}
__device__ __forceinline__ half2 hu(unsigned int x) { return *(half2*)&x; }
__device__ __forceinline__ unsigned int pack2(float a, float b) {
    half2 h = __floats2half2_rn(a, b);
    return *(unsigned int*)&h;
}
__device__ __forceinline__ void barw(int id) {
    asm volatile("bar.sync %0, 64;\n" :: "r"(id));
}
__device__ __forceinline__ void cpa16(unsigned int dst, const void* src) {
    asm volatile("cp.async.cg.shared.global [%0], [%1], 16;\n" :: "r"(dst), "l"(src));
}
__device__ __forceinline__ void cpa_commit() {
    asm volatile("cp.async.commit_group;\n");
}
__device__ __forceinline__ void cpa_wait0() {
    asm volatile("cp.async.wait_group 0;\n");
}
__device__ __forceinline__ void cpa_wait1() {
    asm volatile("cp.async.wait_group 1;\n");
}

// ---------------------------------------------------------------------------
// Kernel 0a: Wo -> fp16
// ---------------------------------------------------------------------------
__global__ void wconv_kernel(const float* __restrict__ Wo) {
    int i = blockIdx.x * blockDim.x + threadIdx.x;
    g_woh[i] = __float2half(Wo[i]);
}

// ---------------------------------------------------------------------------
// Kernel 0b: split fused QKV weight to hi/lo fp16 (+ bias). q rows * log2e.
// ---------------------------------------------------------------------------
__global__ void wsplit_kernel(
    const float* __restrict__ Wq, const float* __restrict__ bq,
    const float* __restrict__ Wk, const float* __restrict__ bk,
    const float* __restrict__ Wv, const float* __restrict__ bv)
{
    int i = blockIdx.x * 256 + threadIdx.x;   // 81920 exact (320 blocks)
    int rowi = i >> 8, col = i & 255;
    float w;
    if (rowi < 32)      w = Wq[rowi * 256 + col] * LOG2E;
    else if (rowi < 64) w = Wk[(rowi - 32) * 256 + col];
    else                w = Wv[(rowi - 64) * 256 + col];
    __half h = __float2half_rn(w);
    g_whi[i] = h;
    g_wlo[i] = __float2half_rn(w - __half2float(h));
    if (i < 320) {
        float bb;
        if (i < 32)      bb = bq[i] * LOG2E;
        else if (i < 64) bb = bk[i - 32];
        else             bb = bv[i - 64];
        g_bias[i] = bb;
    }
}

// ---------------------------------------------------------------------------
// Kernel 0c: transpose-convert x -> g_cat[b][n][256+c]
// ---------------------------------------------------------------------------
__global__ void xpose_kernel(const float* __restrict__ x) {
    __shared__ float ts[32][33];
    const int b = blockIdx.z, n0 = blockIdx.x * 32, c0 = blockIdx.y * 32;
    const int txi = threadIdx.x, tyi = threadIdx.y;
#pragma unroll
    for (int i = 0; i < 4; i++) {
        int c = c0 + tyi + i * 8;
        ts[tyi + i * 8][txi] = x[((size_t)b * CCH + c) * NN + n0 + txi];
    }
    __syncthreads();
#pragma unroll
    for (int i = 0; i < 4; i++) {
        int n = n0 + tyi + i * 8;
        g_cat[((size_t)b * NN + n) * 512 + 256 + c0 + txi] =
            __float2half(ts[txi][tyi + i * 8]);
    }
}

// ---------------------------------------------------------------------------
// Kernel 1: QKV projection via tensor cores (hi/lo split, fp32-equivalent).
// D[out 64][pix 128] per block; A = W hi/lo (ldsm), B = x hi/lo (ldsm.trans).
// 8 warps = 4 out-bands(16) x 2 pix-halves(64). K-loop 256 in chunks of 32.
// smem: xhi[32][136h] 8704 | xlo 8704 | whi[64][40h] 5120 | wlo 5120 = 27648
// Epilogue stages fp32 [64][132] = 33792 (reuses whole buffer).
// ---------------------------------------------------------------------------
__global__ __launch_bounds__(256) void qkv_mma_kernel(const float* __restrict__ x)
{
    __shared__ __align__(16) char sm[33792];
    char* xhi = sm;
    char* xlo = sm + 8704;
    char* whi = sm + 17408;
    char* wlo = sm + 22528;

    const int b  = blockIdx.z;
    const int o0 = blockIdx.y * 64;
    const int p0 = blockIdx.x * 128;
    const int t  = threadIdx.x;
    const int lane = t & 31, wrp = t >> 5;
    const int ob  = wrp & 3;     // 16-row out band
    const int ph2 = wrp >> 2;    // 64-pix half

    float acc[8][4];
#pragma unroll
    for (int i = 0; i < 8; i++)
#pragma unroll
        for (int j = 0; j < 4; j++) acc[i][j] = 0.f;

    for (int kc = 0; kc < 256; kc += 32) {
        // W tiles via cp.async
        {
            const int rowi = t >> 2, seg = t & 3;
            cpa16(smaddr(whi + rowi * 80 + seg * 16),
                  g_whi + (size_t)(o0 + rowi) * 256 + kc + seg * 8);
            cpa16(smaddr(wlo + rowi * 80 + seg * 16),
                  g_wlo + (size_t)(o0 + rowi) * 256 + kc + seg * 8);
            cpa_commit();
        }
        // x tile: load fp32, convert to hi/lo fp16
        {
            const int cr = t >> 3, ps = (t & 7) * 16;
            const float* xr = x + ((size_t)b * CCH + kc + cr) * NN + p0 + ps;
            float f[16];
            *(float4*)(f)      = ((const float4*)xr)[0];
            *(float4*)(f + 4)  = ((const float4*)xr)[1];
            *(float4*)(f + 8)  = ((const float4*)xr)[2];
            *(float4*)(f + 12) = ((const float4*)xr)[3];
            unsigned hi[8], lo[8];
#pragma unroll
            for (int i = 0; i < 8; i++) {
                float a = f[2 * i], c = f[2 * i + 1];
                half2 h = __floats2half2_rn(a, c);
                float2 hf = __half22float2(h);
                half2 l = __floats2half2_rn(a - hf.x, c - hf.y);
                hi[i] = *(unsigned*)&h;
                lo[i] = *(unsigned*)&l;
            }
            *(uint4*)(xhi + cr * 272 + ps * 2)      = make_uint4(hi[0], hi[1], hi[2], hi[3]);
            *(uint4*)(xhi + cr * 272 + ps * 2 + 16) = make_uint4(hi[4], hi[5], hi[6], hi[7]);
            *(uint4*)(xlo + cr * 272 + ps * 2)      = make_uint4(lo[0], lo[1], lo[2], lo[3]);
            *(uint4*)(xlo + cr * 272 + ps * 2 + 16) = make_uint4(lo[4], lo[5], lo[6], lo[7]);
        }
        cpa_wait0();
        __syncthreads();

        unsigned awh[2][4], awl[2][4];
#pragma unroll
        for (int ks = 0; ks < 2; ks++) {
            const int woff = (ob * 16 + (lane & 15)) * 80 + ks * 32 + ((lane >> 4) << 4);
            ldsm_x4(awh[ks][0], awh[ks][1], awh[ks][2], awh[ks][3], smaddr(whi + woff));
            ldsm_x4(awl[ks][0], awl[ks][1], awl[ks][2], awl[ks][3], smaddr(wlo + woff));
        }
#pragma unroll
        for (int ks = 0; ks < 2; ks++) {
#pragma unroll
            for (int ng = 0; ng < 4; ng++) {
                unsigned bh0, bh1, bh2, bh3, bl0, bl1, bl2, bl3;
                const int xoff = (ks * 16 + (lane & 15)) * 272
                               + ph2 * 128 + ng * 32 + ((lane >> 4) << 4);
                ldsm_x4t(bh0, bh1, bh2, bh3, smaddr(xhi + xoff));
                ldsm_x4t(bl0, bl1, bl2, bl3, smaddr(xlo + xoff));
                mma_f16(acc[ng * 2],     awh[ks], bh0, bh1);
                mma_f16(acc[ng * 2],     awl[ks], bh0, bh1);
                mma_f16(acc[ng * 2],     awh[ks], bl0, bl1);
                mma_f16(acc[ng * 2 + 1], awh[ks], bh2, bh3);
                mma_f16(acc[ng * 2 + 1], awl[ks], bh2, bh3);
                mma_f16(acc[ng * 2 + 1], awh[ks], bl2, bl3);
            }
        }
        __syncthreads();
    }

    // ---- epilogue: bias, stage fp32, re-read transposed, write outputs ----
    float* stg = (float*)sm;   // [64][132]
    const int r0o = ob * 16 + (lane >> 2);
    const float b0 = g_bias[o0 + r0o], b1 = g_bias[o0 + r0o + 8];
#pragma unroll
    for (int j = 0; j < 8; j++) {
        const int pcol = ph2 * 64 + j * 8 + 2 * (lane & 3);
        float2 v0, v1;
        v0.x = acc[j][0] + b0; v0.y = acc[j][1] + b0;
        v1.x = acc[j][2] + b1; v1.y = acc[j][3] + b1;
        *(float2*)&stg[r0o * 132 + pcol]       = v0;
        *(float2*)&stg[(r0o + 8) * 132 + pcol] = v1;
    }
    __syncthreads();

    const int p  = t >> 1, hf = t & 1;
    const int pg = p0 + p;
    if (o0 == 0) {
        // hf=0 -> q (rows 0..31), hf=1 -> k (rows 32..63); hi/lo split out
        unsigned uh[16], ul[16];
#pragma unroll
        for (int i = 0; i < 16; i++) {
            float a = stg[(hf * 32 + 2 * i) * 132 + p];
            float c = stg[(hf * 32 + 2 * i + 1) * 132 + p];
            half2 h = __floats2half2_rn(a, c);
            float2 hfv = __half22float2(h);
            half2 l = __floats2half2_rn(a - hfv.x, c - hfv.y);
            uh[i] = *(unsigned*)&h;
            ul[i] = *(unsigned*)&l;
        }
        __half* dh = (hf ? g_khi : g_qhi) + ((size_t)b * NN + pg) * CQ;
        __half* dl = (hf ? g_klo : g_qlo) + ((size_t)b * NN + pg) * CQ;
#pragma unroll
        for (int i = 0; i < 4; i++) {
            ((uint4*)dh)[i] = make_uint4(uh[4*i], uh[4*i+1], uh[4*i+2], uh[4*i+3]);
            ((uint4*)dl)[i] = make_uint4(ul[4*i], ul[4*i+1], ul[4*i+2], ul[4*i+3]);
        }
    } else {
        unsigned uh[16];
#pragma unroll
        for (int i = 0; i < 16; i++) {
            float a = stg[(hf * 32 + 2 * i) * 132 + p];
            float c = stg[(hf * 32 + 2 * i + 1) * 132 + p];
            uh[i] = pack2(a, c);
        }
        __half* dv = g_vh + ((size_t)b * NN + pg) * CCH + (o0 - 64) + hf * 32;
#pragma unroll
        for (int i = 0; i < 4; i++)
            ((uint4*)dv)[i] = make_uint4(uh[4*i], uh[4*i+1], uh[4*i+2], uh[4*i+3]);
    }
}

// ---------------------------------------------------------------------------
// Kernel 2: flash attention (unchanged from R9: double-buffered cp.async).
// ---------------------------------------------------------------------------
#define A_BUF   44032
#define A_PH    88064
#define A_RSX   97280
#define A_SCB   97792
#define ATTN_SMEM 98048

__global__ __launch_bounds__(256, 2) void attn_kernel()
{
    extern __shared__ char smd[];
    __half* ph  = (__half*)(smd + A_PH);
    float*  rsx = (float*)(smd + A_RSX);
    float*  scb = (float*)(smd + A_SCB);

    const int b    = blockIdx.y;
    const int m0   = blockIdx.x * 64;
    const int t    = threadIdx.x;
    const int lane = t & 31;
    const int wrp  = t >> 5;
    const int band = wrp & 3;
    const int ch   = wrp >> 2;
    const int bid  = band + 1;
    const int qg   = wrp & 1;
    const int cq   = wrp >> 1;

    const int row = t >> 2, c4 = t & 3;
    const int r0 = band * 16 + (lane >> 2), r1 = r0 + 8;

    {
        char* qa = smd + A_BUF + 10240;
        *((uint4*)(qa + row * 80) + c4) =
            *((const uint4*)(g_qhi + ((size_t)b * NN + m0 + row) * CQ) + c4);
        *((uint4*)(qa + 5120 + row * 80) + c4) =
            *((const uint4*)(g_qlo + ((size_t)b * NN + m0 + row) * CQ) + c4);

        cpa16(smaddr(smd + row * 80 + c4 * 16),
              g_khi + ((size_t)b * NN + row) * CQ + c4 * 8);
        cpa16(smaddr(smd + 5120 + row * 80 + c4 * 16),
              g_klo + ((size_t)b * NN + row) * CQ + c4 * 8);
        const __half* vsrc = g_vh + (size_t)b * NN * CCH;
#pragma unroll
        for (int i = 0; i < 8; i++) {
            const int idx = t + i * 256;
            const int vr = idx >> 5, vc = idx & 31;
            cpa16(smaddr(smd + 10240 + vr * 528 + vc * 16), vsrc + vr * CCH + vc * 8);
        }
        cpa_commit();
    }
    __syncthreads();

    unsigned qh[2][4], ql[2][4];
    {
        char* qa = smd + A_BUF + 10240;
        const int aoff = (band * 16 + (lane & 15)) * 80 + ((lane >> 4) << 4);
#pragma unroll
        for (int ks = 0; ks < 2; ks++) {
            ldsm_x4(qh[ks][0], qh[ks][1], qh[ks][2], qh[ks][3],
                    smaddr(qa + aoff + ks * 32));
            ldsm_x4(ql[ks][0], ql[ks][1], ql[ks][2], ql[ks][3],
                    smaddr(qa + 5120 + aoff + ks * 32));
        }
    }
    __syncthreads();

    float acc[16][4];
#pragma unroll
    for (int g = 0; g < 16; g++)
#pragma unroll
        for (int j = 0; j < 4; j++) acc[g][j] = 0.f;
    float rmax0 = -INFINITY, rmax1 = -INFINITY, rsum0 = 0.f, rsum1 = 0.f;

    for (int nt = 0; nt < 64; nt++) {
        char* buf = smd + (nt & 1) * A_BUF;
        char* kh  = buf;
        char* kl  = buf + 5120;
        char* vb  = buf + 10240;

        if (nt < 63) {
            char* nb = smd + ((nt + 1) & 1) * A_BUF;
            const int n1 = (nt + 1) * 64;
            cpa16(smaddr(nb + row * 80 + c4 * 16),
                  g_khi + ((size_t)b * NN + n1 + row) * CQ + c4 * 8);
            cpa16(smaddr(nb + 5120 + row * 80 + c4 * 16),
                  g_klo + ((size_t)b * NN + n1 + row) * CQ + c4 * 8);
            const __half* vsrc = g_vh + ((size_t)b * NN + n1) * CCH;
#pragma unroll
            for (int i = 0; i < 8; i++) {
                const int idx = t + i * 256;
                const int vr = idx >> 5, vc = idx & 31;
                cpa16(smaddr(nb + 10240 + vr * 528 + vc * 16),
                      vsrc + vr * CCH + vc * 8);
            }
            cpa_commit();
            cpa_wait1();
        } else {
            cpa_wait0();
        }
        __syncthreads();

        float sacc[4][4];
#pragma unroll
        for (int n = 0; n < 4; n++)
#pragma unroll
            for (int j = 0; j < 4; j++) sacc[n][j] = 0.f;
#pragma unroll
        for (int np = 0; np < 2; np++) {
#pragma unroll
            for (int ks = 0; ks < 2; ks++) {
                unsigned bh0, bh1, bh2, bh3, bl0, bl1, bl2, bl3;
                const int roff = (ch * 32 + np * 16 + ((lane >> 4) << 3) + (lane & 7)) * 80
                               + ks * 32 + (((lane >> 3) & 1) << 4);
                ldsm_x4(bh0, bh1, bh2, bh3, smaddr(kh + roff));
                ldsm_x4(bl0, bl1, bl2, bl3, smaddr(kl + roff));
                mma_f16(sacc[np * 2],     qh[ks], bh0, bh1);
                mma_f16(sacc[np * 2],     ql[ks], bh0, bh1);
                mma_f16(sacc[np * 2],     qh[ks], bl0, bl1);
                mma_f16(sacc[np * 2 + 1], qh[ks], bh2, bh3);
                mma_f16(sacc[np * 2 + 1], ql[ks], bh2, bh3);
                mma_f16(sacc[np * 2 + 1], qh[ks], bl2, bl3);
            }
        }

        float tm0 = fmaxf(fmaxf(sacc[0][0], sacc[0][1]), fmaxf(sacc[1][0], sacc[1][1]));
        float tm1 = fmaxf(fmaxf(sacc[0][2], sacc[0][3]), fmaxf(sacc[1][2], sacc[1][3]));
        tm0 = fmaxf(tm0, fmaxf(fmaxf(sacc[2][0], sacc[2][1]), fmaxf(sacc[3][0], sacc[3][1])));
        tm1 = fmaxf(tm1, fmaxf(fmaxf(sacc[2][2], sacc[2][3]), fmaxf(sacc[3][2], sacc[3][3])));
        tm0 = fmaxf(tm0, __shfl_xor_sync(0xffffffffu, tm0, 1));
        tm0 = fmaxf(tm0, __shfl_xor_sync(0xffffffffu, tm0, 2));
        tm1 = fmaxf(tm1, __shfl_xor_sync(0xffffffffu, tm1, 1));
        tm1 = fmaxf(tm1, __shfl_xor_sync(0xffffffffu, tm1, 2));
        if ((lane & 3) == 0) { rsx[ch * 64 + r0] = tm0; rsx[ch * 64 + r1] = tm1; }
        barw(bid);
        tm0 = fmaxf(tm0, rsx[(ch ^ 1) * 64 + r0]);
        tm1 = fmaxf(tm1, rsx[(ch ^ 1) * 64 + r1]);

        const float nm0 = fmaxf(rmax0, tm0), nm1 = fmaxf(rmax1, tm1);
        const float sc0 = exp2f(rmax0 - nm0), sc1 = exp2f(rmax1 - nm1);
        rmax0 = nm0; rmax1 = nm1;
        rsum0 *= sc0; rsum1 *= sc1;
        if (ch == 0 && (lane & 3) == 0) { scb[r0] = sc0; scb[r1] = sc1; }

        unsigned pr0[4], pr1[4];
#pragma unroll
        for (int nj = 0; nj < 4; nj++) {
            pr0[nj] = ex2h2(sacc[nj][0] - nm0, sacc[nj][1] - nm0);
            pr1[nj] = ex2h2(sacc[nj][2] - nm1, sacc[nj][3] - nm1);
            const int col = ch * 32 + nj * 8 + 2 * (lane & 3);
            *(half2*)(ph + r0 * 72 + col) = hu(pr0[nj]);
            *(half2*)(ph + r1 * 72 + col) = hu(pr1[nj]);
        }
        {
            float2 f0 = __half22float2(__hadd2(__hadd2(hu(pr0[0]), hu(pr0[1])),
                                               __hadd2(hu(pr0[2]), hu(pr0[3]))));
            float2 f1 = __half22float2(__hadd2(__hadd2(hu(pr1[0]), hu(pr1[1])),
                                               __hadd2(hu(pr1[2]), hu(pr1[3]))));
            rsum0 += f0.x + f0.y;
            rsum1 += f1.x + f1.y;
        }
        __syncthreads();

        {
            const int rb = qg * 32 + (lane >> 2);
            const float s0 = scb[rb],      s1 = scb[rb + 8];
            const float s2 = scb[rb + 16], s3 = scb[rb + 24];
            const bool skip = __all_sync(0xffffffffu,
                (s0 == 1.f) && (s1 == 1.f) && (s2 == 1.f) && (s3 == 1.f));
            if (!skip) {
#pragma unroll
                for (int nj = 0; nj < 8; nj++) {
                    acc[nj][0] *= s0; acc[nj][1] *= s0;
                    acc[nj][2] *= s1; acc[nj][3] *= s1;
                    acc[8 + nj][0] *= s2; acc[8 + nj][1] *= s2;
                    acc[8 + nj][2] *= s3; acc[8 + nj][3] *= s3;
                }
            }
#pragma unroll
            for (int ks = 0; ks < 4; ks++) {
                unsigned pf0[4], pf1[4];
                const int pcol = ks * 32 + ((lane >> 4) << 4);
                ldsm_x4(pf0[0], pf0[1], pf0[2], pf0[3],
                    smaddr((char*)ph + (qg * 32 + (lane & 15)) * 144 + pcol));
                ldsm_x4(pf1[0], pf1[1], pf1[2], pf1[3],
                    smaddr((char*)ph + (qg * 32 + 16 + (lane & 15)) * 144 + pcol));
                const int vrow = (ks * 16 + (lane & 15)) * 528
                               + cq * 128 + ((lane >> 4) << 4);
#pragma unroll
                for (int cc = 0; cc < 4; cc++) {
                    unsigned v0, v1, v2, v3;
                    ldsm_x4t(v0, v1, v2, v3, smaddr(vb + vrow + cc * 32));
                    mma_f16(acc[cc * 2],         pf0, v0, v1);
                    mma_f16(acc[cc * 2 + 1],     pf0, v2, v3);
                    mma_f16(acc[8 + cc * 2],     pf1, v0, v1);
                    mma_f16(acc[8 + cc * 2 + 1], pf1, v2, v3);
                }
            }
        }
        __syncthreads();
    }

    rsum0 += __shfl_xor_sync(0xffffffffu, rsum0, 1);
    rsum0 += __shfl_xor_sync(0xffffffffu, rsum0, 2);
    rsum1 += __shfl_xor_sync(0xffffffffu, rsum1, 1);
    rsum1 += __shfl_xor_sync(0xffffffffu, rsum1, 2);
    if ((lane & 3) == 0) { rsx[ch * 64 + r0] = rsum0; rsx[ch * 64 + r1] = rsum1; }
    __syncthreads();
    if (ch == 0 && (lane & 3) == 0) {
        scb[r0] = 1.f / (rsum0 + rsx[64 + r0]);
        scb[r1] = 1.f / (rsum1 + rsx[64 + r1]);
    }
    __syncthreads();

    const int rb = qg * 32 + (lane >> 2);
    const float i0 = scb[rb],      i1 = scb[rb + 8];
    const float i2 = scb[rb + 16], i3 = scb[rb + 24];
#pragma unroll
    for (int nj = 0; nj < 8; nj++) {
        const int col = cq * 64 + nj * 8 + 2 * (lane & 3);
        *(half2*)(g_cat + ((size_t)b * NN + m0 + rb) * 512 + col) =
            __floats2half2_rn(acc[nj][0] * i0, acc[nj][1] * i0);
        *(half2*)(g_cat + ((size_t)b * NN + m0 + rb + 8) * 512 + col) =
            __floats2half2_rn(acc[nj][2] * i1, acc[nj][3] * i1);
        *(half2*)(g_cat + ((size_t)b * NN + m0 + rb + 16) * 512 + col) =
            __floats2half2_rn(acc[8 + nj][0] * i2, acc[8 + nj][1] * i2);
        *(half2*)(g_cat + ((size_t)b * NN + m0 + rb + 24) * 512 + col) =
            __floats2half2_rn(acc[8 + nj][2] * i3, acc[8 + nj][3] * i3);
    }
}

// ---------------------------------------------------------------------------
// Kernel 3: output projection via mma
// ---------------------------------------------------------------------------
__global__ __launch_bounds__(256) void outproj_kernel(
    const float* __restrict__ bo, float* __restrict__ y)
{
    __shared__ __align__(16) __half As[64 * 72];
    __shared__ __align__(16) __half Bs[128 * 72];

    const int b  = blockIdx.z;
    const int o0 = blockIdx.y * 64;
    const int m0 = blockIdx.x * 128;
    const int t  = threadIdx.x;
    const int lane = t & 31, wrp = t >> 5;
    const int ob = (wrp & 3) * 16;
    const int mh = (wrp >> 2) * 64;

    float acc[8][4];
#pragma unroll
    for (int i = 0; i < 8; i++)
#pragma unroll
        for (int j = 0; j < 4; j++) acc[i][j] = 0.f;

    for (int k0 = 0; k0 < 512; k0 += 64) {
#pragma unroll
        for (int i = 0; i < 2; i++) {
            const int idx = t + i * 256;
            const int rowi = idx >> 3, c16 = idx & 7;
            ((uint4*)As)[rowi * 9 + c16] =
                *((const uint4*)(g_woh + (size_t)(o0 + rowi) * 512 + k0) + c16);
        }
#pragma unroll
        for (int i = 0; i < 4; i++) {
            const int idx = t + i * 256;
            const int rowi = idx >> 3, c16 = idx & 7;
            ((uint4*)Bs)[rowi * 9 + c16] =
                *((const uint4*)(g_cat + ((size_t)b * NN + m0 + rowi) * 512 + k0) + c16);
        }
        __syncthreads();

        unsigned int af[4][4];
#pragma unroll
        for (int k4 = 0; k4 < 4; k4++) {
            unsigned int a = smaddr(As + (ob + (lane & 15)) * 72 + k4 * 16 + (lane >> 4) * 8);
            ldsm_x4(af[k4][0], af[k4][1], af[k4][2], af[k4][3], a);
        }
#pragma unroll
        for (int pr = 0; pr < 4; pr++) {
#pragma unroll
            for (int k4 = 0; k4 < 4; k4++) {
                unsigned int b0, b1, b2, b3;
                unsigned int a = smaddr(Bs + (mh + pr * 16 + (lane >> 4) * 8 + (lane & 7)) * 72
                                           + k4 * 16 + ((lane >> 3) & 1) * 8);
                ldsm_x4(b0, b1, b2, b3, a);
                mma_f16(acc[pr * 2],     af[k4], b0, b1);
                mma_f16(acc[pr * 2 + 1], af[k4], b2, b3);
            }
        }
        __syncthreads();
    }

    const int orow = o0 + ob + (lane >> 2);
    const float bi0 = bo[orow], bi1 = bo[orow + 8];
#pragma unroll
    for (int chn = 0; chn < 8; chn++) {
        const int m = m0 + mh + chn * 8 + (lane & 3) * 2;
        float2 v0, v1;
        v0.x = acc[chn][0] + bi0; v0.y = acc[chn][1] + bi0;
        v1.x = acc[chn][2] + bi1; v1.y = acc[chn][3] + bi1;
        *(float2*)(y + ((size_t)b * CCH + orow)     * NN + m) = v0;
        *(float2*)(y + ((size_t)b * CCH + orow + 8) * NN + m) = v1;
    }
}

// ---------------------------------------------------------------------------
extern "C" void kernel_launch(void* const* d_in, const int* in_sizes, int n_in,
                              void* d_out, int out_size)
{
    const float* x  = (const float*)d_in[0];
    const float* Wq = (const float*)d_in[1];
    const float* bq = (const float*)d_in[2];
    const float* Wk = (const float*)d_in[3];
    const float* bk = (const float*)d_in[4];
    const float* Wv = (const float*)d_in[5];
    const float* bv = (const float*)d_in[6];
    const float* Wo = (const float*)d_in[7];
    const float* bo = (const float*)d_in[8];
    float* y = (float*)d_out;

    cudaFuncSetAttribute(attn_kernel,
                         cudaFuncAttributeMaxDynamicSharedMemorySize,
                         ATTN_SMEM);

    wconv_kernel<<<512, 256>>>(Wo);
    wsplit_kernel<<<320, 256>>>(Wq, bq, Wk, bk, Wv, bv);
    xpose_kernel<<<dim3(128, 8, BB), dim3(32, 8)>>>(x);
    qkv_mma_kernel<<<dim3(32, 5, BB), 256>>>(x);
    attn_kernel<<<dim3(64, BB), 256, ATTN_SMEM>>>();
    outproj_kernel<<<dim3(32, 4, BB), 256>>>(bo, y);
}

// round 11
// speedup vs baseline: 4.4324x; 1.0220x over previous
#include <cuda_runtime.h>
#include <cuda_fp16.h>
#include <cstdint>
#include <math.h>

#define BB  4
#define CCH 256
#define CQ  32
#define NN  4096
#define LOG2E 1.4426950408889634f

// Scratch (device globals: no allocation allowed)
__device__ __half g_qhi[BB * NN * CQ];         // q * log2e, hi
__device__ __half g_qlo[BB * NN * CQ];         // q * log2e, lo
__device__ __half g_khi[BB * NN * CQ];
__device__ __half g_klo[BB * NN * CQ];
__device__ __half g_vh[BB * NN * CCH];         // [b][n][256] fp16
__device__ __half g_cat[BB * NN * 2 * CCH];    // [b][n][512]: [0:256)=attn, [256:512)=x^T
__device__ __half g_woh[CCH * 2 * CCH];        // Wo fp16 [o][512]
__device__ __half g_whi[320 * CCH];            // fused QKV weight hi (q rows * log2e)
__device__ __half g_wlo[320 * CCH];            // fused QKV weight lo
__device__ float  g_bias[320];                 // fused QKV bias (q rows * log2e)
__device__ __half g_xhi[BB * CCH * NN];        // x hi fp16, [b][c][n]
__device__ __half g_xlo[BB * CCH * NN];        // x lo fp16, [b][c][n]

// ---------------- PTX helpers ----------------
__device__ __forceinline__ unsigned int smaddr(const void* p) {
    return (unsigned int)__cvta_generic_to_shared(p);
}
__device__ __forceinline__ void ldsm_x4(unsigned int& r0, unsigned int& r1,
                                        unsigned int& r2, unsigned int& r3,
                                        unsigned int a) {
    asm volatile("ldmatrix.sync.aligned.m8n8.x4.shared.b16 {%0,%1,%2,%3},[%4];\n"
                 : "=r"(r0), "=r"(r1), "=r"(r2), "=r"(r3) : "r"(a));
}
__device__ __forceinline__ void ldsm_x4t(unsigned int& r0, unsigned int& r1,
                                         unsigned int& r2, unsigned int& r3,
                                         unsigned int a) {
    asm volatile("ldmatrix.sync.aligned.m8n8.x4.trans.shared.b16 {%0,%1,%2,%3},[%4];\n"
                 : "=r"(r0), "=r"(r1), "=r"(r2), "=r"(r3) : "r"(a));
}
__device__ __forceinline__ void mma_f16(float* d, const unsigned int* a,
                                        unsigned int b0, unsigned int b1) {
    asm volatile("mma.sync.aligned.m16n8k16.row.col.f32.f16.f16.f32 "
                 "{%0,%1,%2,%3},{%4,%5,%6,%7},{%8,%9},{%0,%1,%2,%3};\n"
                 : "+f"(d[0]), "+f"(d[1]), "+f"(d[2]), "+f"(d[3])
                 : "r"(a[0]), "r"(a[1]), "r"(a[2]), "r"(a[3]), "r"(b0), "r"(b1));
}
__device__ __forceinline__ unsigned int ex2h2(float a, float b) {
    half2 h = __floats2half2_rn(a, b);
    unsigned int x = *(unsigned int*)&h, r;
    asm volatile("ex2.approx.f16x2 %0, %1;\n" : "=r"(r) : "r"(x));
    return r;
}
__device__ __forceinline__ half2 hu(unsigned int x) { return *(half2*)&x; }
__device__ __forceinline__ unsigned int pack2(float a, float b) {
    half2 h = __floats2half2_rn(a, b);
    return *(unsigned int*)&h;
}
__device__ __forceinline__ void barw(int id) {
    asm volatile("bar.sync %0, 64;\n" :: "r"(id));
}
__device__ __forceinline__ void cpa16(unsigned int dst, const void* src) {
    asm volatile("cp.async.cg.shared.global [%0], [%1], 16;\n" :: "r"(dst), "l"(src));
}
__device__ __forceinline__ void cpa_commit() {
    asm volatile("cp.async.commit_group;\n");
}
__device__ __forceinline__ void cpa_wait0() {
    asm volatile("cp.async.wait_group 0;\n");
}

// ---------------------------------------------------------------------------
// Kernel 0a: Wo -> fp16
// ---------------------------------------------------------------------------
__global__ void wconv_kernel(const float* __restrict__ Wo) {
    int i = blockIdx.x * blockDim.x + threadIdx.x;
    g_woh[i] = __float2half(Wo[i]);
}

// ---------------------------------------------------------------------------
// Kernel 0b: split fused QKV weight to hi/lo fp16 (+ bias). q rows * log2e.
// ---------------------------------------------------------------------------
__global__ void wsplit_kernel(
    const float* __restrict__ Wq, const float* __restrict__ bq,
    const float* __restrict__ Wk, const float* __restrict__ bk,
    const float* __restrict__ Wv, const float* __restrict__ bv)
{
    int i = blockIdx.x * 256 + threadIdx.x;   // 81920 exact (320 blocks)
    int rowi = i >> 8, col = i & 255;
    float w;
    if (rowi < 32)      w = Wq[rowi * 256 + col] * LOG2E;
    else if (rowi < 64) w = Wk[(rowi - 32) * 256 + col];
    else                w = Wv[(rowi - 64) * 256 + col];
    __half h = __float2half_rn(w);
    g_whi[i] = h;
    g_wlo[i] = __float2half_rn(w - __half2float(h));
    if (i < 320) {
        float bb;
        if (i < 32)      bb = bq[i] * LOG2E;
        else if (i < 64) bb = bk[i - 32];
        else             bb = bv[i - 64];
        g_bias[i] = bb;
    }
}

// ---------------------------------------------------------------------------
// Kernel 0c: x -> cat (transposed fp16) AND x -> hi/lo fp16 (same layout)
// ---------------------------------------------------------------------------
__global__ void xpose_kernel(const float* __restrict__ x) {
    __shared__ float ts[32][33];
    const int b = blockIdx.z, n0 = blockIdx.x * 32, c0 = blockIdx.y * 32;
    const int txi = threadIdx.x, tyi = threadIdx.y;
#pragma unroll
    for (int i = 0; i < 4; i++) {
        int c = c0 + tyi + i * 8;
        const size_t off = ((size_t)b * CCH + c) * NN + n0 + txi;
        float v = x[off];
        ts[tyi + i * 8][txi] = v;
        __half h = __float2half_rn(v);
        g_xhi[off] = h;
        g_xlo[off] = __float2half_rn(v - __half2float(h));
    }
    __syncthreads();
#pragma unroll
    for (int i = 0; i < 4; i++) {
        int n = n0 + tyi + i * 8;
        g_cat[((size_t)b * NN + n) * 512 + 256 + c0 + txi] =
            __float2half(ts[txi][tyi + i * 8]);
    }
}

// ---------------------------------------------------------------------------
// Kernel 1: QKV projection via tensor cores (hi/lo split, fp32-equivalent).
// All four operand tiles (W hi/lo, x hi/lo) staged via cp.async; no in-kernel
// conversion. D[out 64][pix 128]; 8 warps = 4 out-bands x 2 pix-halves.
// smem: xhi[32][136h] 8704 | xlo 8704 | whi[64][40h] 5120 | wlo 5120 = 27648
// Epilogue stages fp32 [64][132] = 33792 (reuses whole buffer).
// ---------------------------------------------------------------------------
__global__ __launch_bounds__(256) void qkv_mma_kernel()
{
    __shared__ __align__(16) char sm[33792];
    char* xhi = sm;
    char* xlo = sm + 8704;
    char* whi = sm + 17408;
    char* wlo = sm + 22528;

    const int b  = blockIdx.z;
    const int o0 = blockIdx.y * 64;
    const int p0 = blockIdx.x * 128;
    const int t  = threadIdx.x;
    const int lane = t & 31, wrp = t >> 5;
    const int ob  = wrp & 3;     // 16-row out band
    const int ph2 = wrp >> 2;    // 64-pix half

    float acc[8][4];
#pragma unroll
    for (int i = 0; i < 8; i++)
#pragma unroll
        for (int j = 0; j < 4; j++) acc[i][j] = 0.f;

    for (int kc = 0; kc < 256; kc += 32) {
        // W tiles
        {
            const int rowi = t >> 2, seg = t & 3;
            cpa16(smaddr(whi + rowi * 80 + seg * 16),
                  g_whi + (size_t)(o0 + rowi) * 256 + kc + seg * 8);
            cpa16(smaddr(wlo + rowi * 80 + seg * 16),
                  g_wlo + (size_t)(o0 + rowi) * 256 + kc + seg * 8);
        }
        // x tiles (pre-split hi/lo fp16, direct cp.async)
#pragma unroll
        for (int i = 0; i < 2; i++) {
            const int idx = t + i * 256;
            const int row = idx >> 4, ck = idx & 15;
            const size_t src = ((size_t)b * CCH + kc + row) * NN + p0 + ck * 8;
            cpa16(smaddr(xhi + row * 272 + ck * 16), g_xhi + src);
            cpa16(smaddr(xlo + row * 272 + ck * 16), g_xlo + src);
        }
        cpa_commit();
        cpa_wait0();
        __syncthreads();

        unsigned awh[2][4], awl[2][4];
#pragma unroll
        for (int ks = 0; ks < 2; ks++) {
            const int woff = (ob * 16 + (lane & 15)) * 80 + ks * 32 + ((lane >> 4) << 4);
            ldsm_x4(awh[ks][0], awh[ks][1], awh[ks][2], awh[ks][3], smaddr(whi + woff));
            ldsm_x4(awl[ks][0], awl[ks][1], awl[ks][2], awl[ks][3], smaddr(wlo + woff));
        }
#pragma unroll
        for (int ks = 0; ks < 2; ks++) {
#pragma unroll
            for (int ng = 0; ng < 4; ng++) {
                unsigned bh0, bh1, bh2, bh3, bl0, bl1, bl2, bl3;
                const int xoff = (ks * 16 + (lane & 15)) * 272
                               + ph2 * 128 + ng * 32 + ((lane >> 4) << 4);
                ldsm_x4t(bh0, bh1, bh2, bh3, smaddr(xhi + xoff));
                ldsm_x4t(bl0, bl1, bl2, bl3, smaddr(xlo + xoff));
                mma_f16(acc[ng * 2],     awh[ks], bh0, bh1);
                mma_f16(acc[ng * 2],     awl[ks], bh0, bh1);
                mma_f16(acc[ng * 2],     awh[ks], bl0, bl1);
                mma_f16(acc[ng * 2 + 1], awh[ks], bh2, bh3);
                mma_f16(acc[ng * 2 + 1], awl[ks], bh2, bh3);
                mma_f16(acc[ng * 2 + 1], awh[ks], bl2, bl3);
            }
        }
        __syncthreads();
    }

    // ---- epilogue: bias, stage fp32, re-read transposed, write outputs ----
    float* stg = (float*)sm;   // [64][132]
    const int r0o = ob * 16 + (lane >> 2);
    const float b0 = g_bias[o0 + r0o], b1 = g_bias[o0 + r0o + 8];
#pragma unroll
    for (int j = 0; j < 8; j++) {
        const int pcol = ph2 * 64 + j * 8 + 2 * (lane & 3);
        float2 v0, v1;
        v0.x = acc[j][0] + b0; v0.y = acc[j][1] + b0;
        v1.x = acc[j][2] + b1; v1.y = acc[j][3] + b1;
        *(float2*)&stg[r0o * 132 + pcol]       = v0;
        *(float2*)&stg[(r0o + 8) * 132 + pcol] = v1;
    }
    __syncthreads();

    const int p  = t >> 1, hf = t & 1;
    const int pg = p0 + p;
    if (o0 == 0) {
        unsigned uh[16], ul[16];
#pragma unroll
        for (int i = 0; i < 16; i++) {
            float a = stg[(hf * 32 + 2 * i) * 132 + p];
            float c = stg[(hf * 32 + 2 * i + 1) * 132 + p];
            half2 h = __floats2half2_rn(a, c);
            float2 hfv = __half22float2(h);
            half2 l = __floats2half2_rn(a - hfv.x, c - hfv.y);
            uh[i] = *(unsigned*)&h;
            ul[i] = *(unsigned*)&l;
        }
        __half* dh = (hf ? g_khi : g_qhi) + ((size_t)b * NN + pg) * CQ;
        __half* dl = (hf ? g_klo : g_qlo) + ((size_t)b * NN + pg) * CQ;
#pragma unroll
        for (int i = 0; i < 4; i++) {
            ((uint4*)dh)[i] = make_uint4(uh[4*i], uh[4*i+1], uh[4*i+2], uh[4*i+3]);
            ((uint4*)dl)[i] = make_uint4(ul[4*i], ul[4*i+1], ul[4*i+2], ul[4*i+3]);
        }
    } else {
        unsigned uh[16];
#pragma unroll
        for (int i = 0; i < 16; i++) {
            float a = stg[(hf * 32 + 2 * i) * 132 + p];
            float c = stg[(hf * 32 + 2 * i + 1) * 132 + p];
            uh[i] = pack2(a, c);
        }
        __half* dv = g_vh + ((size_t)b * NN + pg) * CCH + (o0 - 64) + hf * 32;
#pragma unroll
        for (int i = 0; i < 4; i++)
            ((uint4*)dv)[i] = make_uint4(uh[4*i], uh[4*i+1], uh[4*i+2], uh[4*i+3]);
    }
}

// ---------------------------------------------------------------------------
// Kernel 2: flash attention (double-buffered cp.async, 2 syncs/tile).
// Loop: wait0 -> syncA (PV done + tile visible) -> issue prefetch -> S ->
//       barw -> P write -> syncB -> PV.
// ---------------------------------------------------------------------------
#define A_BUF   44032
#define A_PH    88064
#define A_RSX   97280
#define A_SCB   97792
#define ATTN_SMEM 98048

__global__ __launch_bounds__(256, 2) void attn_kernel()
{
    extern __shared__ char smd[];
    __half* ph  = (__half*)(smd + A_PH);
    float*  rsx = (float*)(smd + A_RSX);
    float*  scb = (float*)(smd + A_SCB);

    const int b    = blockIdx.y;
    const int m0   = blockIdx.x * 64;
    const int t    = threadIdx.x;
    const int lane = t & 31;
    const int wrp  = t >> 5;
    const int band = wrp & 3;
    const int ch   = wrp >> 2;
    const int bid  = band + 1;
    const int qg   = wrp & 1;
    const int cq   = wrp >> 1;

    const int row = t >> 2, c4 = t & 3;
    const int r0 = band * 16 + (lane >> 2), r1 = r0 + 8;

    {
        char* qa = smd + A_BUF + 10240;
        *((uint4*)(qa + row * 80) + c4) =
            *((const uint4*)(g_qhi + ((size_t)b * NN + m0 + row) * CQ) + c4);
        *((uint4*)(qa + 5120 + row * 80) + c4) =
            *((const uint4*)(g_qlo + ((size_t)b * NN + m0 + row) * CQ) + c4);

        cpa16(smaddr(smd + row * 80 + c4 * 16),
              g_khi + ((size_t)b * NN + row) * CQ + c4 * 8);
        cpa16(smaddr(smd + 5120 + row * 80 + c4 * 16),
              g_klo + ((size_t)b * NN + row) * CQ + c4 * 8);
        const __half* vsrc = g_vh + (size_t)b * NN * CCH;
#pragma unroll
        for (int i = 0; i < 8; i++) {
            const int idx = t + i * 256;
            const int vr = idx >> 5, vc = idx & 31;
            cpa16(smaddr(smd + 10240 + vr * 528 + vc * 16), vsrc + vr * CCH + vc * 8);
        }
        cpa_commit();
    }
    __syncthreads();

    unsigned qh[2][4], ql[2][4];
    {
        char* qa = smd + A_BUF + 10240;
        const int aoff = (band * 16 + (lane & 15)) * 80 + ((lane >> 4) << 4);
#pragma unroll
        for (int ks = 0; ks < 2; ks++) {
            ldsm_x4(qh[ks][0], qh[ks][1], qh[ks][2], qh[ks][3],
                    smaddr(qa + aoff + ks * 32));
            ldsm_x4(ql[ks][0], ql[ks][1], ql[ks][2], ql[ks][3],
                    smaddr(qa + 5120 + aoff + ks * 32));
        }
    }

    float acc[16][4];
#pragma unroll
    for (int g = 0; g < 16; g++)
#pragma unroll
        for (int j = 0; j < 4; j++) acc[g][j] = 0.f;
    float rmax0 = -INFINITY, rmax1 = -INFINITY, rsum0 = 0.f, rsum1 = 0.f;

    for (int nt = 0; nt < 64; nt++) {
        char* buf = smd + (nt & 1) * A_BUF;
        char* kh  = buf;
        char* kl  = buf + 5120;
        char* vb  = buf + 10240;

        cpa_wait0();
        __syncthreads();   // A: tile nt visible + all warps done PV of nt-1

        // ---- issue prefetch of tile nt+1 (overlaps S/softmax/PV below) ----
        if (nt < 63) {
            char* nb = smd + ((nt + 1) & 1) * A_BUF;
            const int n1 = (nt + 1) * 64;
            cpa16(smaddr(nb + row * 80 + c4 * 16),
                  g_khi + ((size_t)b * NN + n1 + row) * CQ + c4 * 8);
            cpa16(smaddr(nb + 5120 + row * 80 + c4 * 16),
                  g_klo + ((size_t)b * NN + n1 + row) * CQ + c4 * 8);
            const __half* vsrc = g_vh + ((size_t)b * NN + n1) * CCH;
#pragma unroll
            for (int i = 0; i < 8; i++) {
                const int idx = t + i * 256;
                const int vr = idx >> 5, vc = idx & 31;
                cpa16(smaddr(nb + 10240 + vr * 528 + vc * 16),
                      vsrc + vr * CCH + vc * 8);
            }
            cpa_commit();
        }

        // ---- S = Q.K^T for OWN 32-col half (hi/lo split) ----
        float sacc[4][4];
#pragma unroll
        for (int n = 0; n < 4; n++)
#pragma unroll
            for (int j = 0; j < 4; j++) sacc[n][j] = 0.f;
#pragma unroll
        for (int np = 0; np < 2; np++) {
#pragma unroll
            for (int ks = 0; ks < 2; ks++) {
                unsigned bh0, bh1, bh2, bh3, bl0, bl1, bl2, bl3;
                const int roff = (ch * 32 + np * 16 + ((lane >> 4) << 3) + (lane & 7)) * 80
                               + ks * 32 + (((lane >> 3) & 1) << 4);
                ldsm_x4(bh0, bh1, bh2, bh3, smaddr(kh + roff));
                ldsm_x4(bl0, bl1, bl2, bl3, smaddr(kl + roff));
                mma_f16(sacc[np * 2],     qh[ks], bh0, bh1);
                mma_f16(sacc[np * 2],     ql[ks], bh0, bh1);
                mma_f16(sacc[np * 2],     qh[ks], bl0, bl1);
                mma_f16(sacc[np * 2 + 1], qh[ks], bh2, bh3);
                mma_f16(sacc[np * 2 + 1], ql[ks], bh2, bh3);
                mma_f16(sacc[np * 2 + 1], qh[ks], bl2, bl3);
            }
        }

        float tm0 = fmaxf(fmaxf(sacc[0][0], sacc[0][1]), fmaxf(sacc[1][0], sacc[1][1]));
        float tm1 = fmaxf(fmaxf(sacc[0][2], sacc[0][3]), fmaxf(sacc[1][2], sacc[1][3]));
        tm0 = fmaxf(tm0, fmaxf(fmaxf(sacc[2][0], sacc[2][1]), fmaxf(sacc[3][0], sacc[3][1])));
        tm1 = fmaxf(tm1, fmaxf(fmaxf(sacc[2][2], sacc[2][3]), fmaxf(sacc[3][2], sacc[3][3])));
        tm0 = fmaxf(tm0, __shfl_xor_sync(0xffffffffu, tm0, 1));
        tm0 = fmaxf(tm0, __shfl_xor_sync(0xffffffffu, tm0, 2));
        tm1 = fmaxf(tm1, __shfl_xor_sync(0xffffffffu, tm1, 1));
        tm1 = fmaxf(tm1, __shfl_xor_sync(0xffffffffu, tm1, 2));
        if ((lane & 3) == 0) { rsx[ch * 64 + r0] = tm0; rsx[ch * 64 + r1] = tm1; }
        barw(bid);
        tm0 = fmaxf(tm0, rsx[(ch ^ 1) * 64 + r0]);
        tm1 = fmaxf(tm1, rsx[(ch ^ 1) * 64 + r1]);

        const float nm0 = fmaxf(rmax0, tm0), nm1 = fmaxf(rmax1, tm1);
        const float sc0 = exp2f(rmax0 - nm0), sc1 = exp2f(rmax1 - nm1);
        rmax0 = nm0; rmax1 = nm1;
        rsum0 *= sc0; rsum1 *= sc1;
        if (ch == 0 && (lane & 3) == 0) { scb[r0] = sc0; scb[r1] = sc1; }

        unsigned pr0[4], pr1[4];
#pragma unroll
        for (int nj = 0; nj < 4; nj++) {
            pr0[nj] = ex2h2(sacc[nj][0] - nm0, sacc[nj][1] - nm0);
            pr1[nj] = ex2h2(sacc[nj][2] - nm1, sacc[nj][3] - nm1);
            const int col = ch * 32 + nj * 8 + 2 * (lane & 3);
            *(half2*)(ph + r0 * 72 + col) = hu(pr0[nj]);
            *(half2*)(ph + r1 * 72 + col) = hu(pr1[nj]);
        }
        {
            float2 f0 = __half22float2(__hadd2(__hadd2(hu(pr0[0]), hu(pr0[1])),
                                               __hadd2(hu(pr0[2]), hu(pr0[3]))));
            float2 f1 = __half22float2(__hadd2(__hadd2(hu(pr1[0]), hu(pr1[1])),
                                               __hadd2(hu(pr1[2]), hu(pr1[3]))));
            rsum0 += f0.x + f0.y;
            rsum1 += f1.x + f1.y;
        }
        __syncthreads();   // B: P + scb ready block-wide

        // ---- PV: warp = 32q (qg) x 64c (cq) ----
        {
            const int rb = qg * 32 + (lane >> 2);
            const float s0 = scb[rb],      s1 = scb[rb + 8];
            const float s2 = scb[rb + 16], s3 = scb[rb + 24];
            const bool skip = __all_sync(0xffffffffu,
                (s0 == 1.f) && (s1 == 1.f) && (s2 == 1.f) && (s3 == 1.f));
            if (!skip) {
#pragma unroll
                for (int nj = 0; nj < 8; nj++) {
                    acc[nj][0] *= s0; acc[nj][1] *= s0;
                    acc[nj][2] *= s1; acc[nj][3] *= s1;
                    acc[8 + nj][0] *= s2; acc[8 + nj][1] *= s2;
                    acc[8 + nj][2] *= s3; acc[8 + nj][3] *= s3;
                }
            }
#pragma unroll
            for (int ks = 0; ks < 4; ks++) {
                unsigned pf0[4], pf1[4];
                const int pcol = ks * 32 + ((lane >> 4) << 4);
                ldsm_x4(pf0[0], pf0[1], pf0[2], pf0[3],
                    smaddr((char*)ph + (qg * 32 + (lane & 15)) * 144 + pcol));
                ldsm_x4(pf1[0], pf1[1], pf1[2], pf1[3],
                    smaddr((char*)ph + (qg * 32 + 16 + (lane & 15)) * 144 + pcol));
                const int vrow = (ks * 16 + (lane & 15)) * 528
                               + cq * 128 + ((lane >> 4) << 4);
#pragma unroll
                for (int cc = 0; cc < 4; cc++) {
                    unsigned v0, v1, v2, v3;
                    ldsm_x4t(v0, v1, v2, v3, smaddr(vb + vrow + cc * 32));
                    mma_f16(acc[cc * 2],         pf0, v0, v1);
                    mma_f16(acc[cc * 2 + 1],     pf0, v2, v3);
                    mma_f16(acc[8 + cc * 2],     pf1, v0, v1);
                    mma_f16(acc[8 + cc * 2 + 1], pf1, v2, v3);
                }
            }
        }
        // (no trailing sync: next iteration's syncA covers buffer reuse)
    }

    rsum0 += __shfl_xor_sync(0xffffffffu, rsum0, 1);
    rsum0 += __shfl_xor_sync(0xffffffffu, rsum0, 2);
    rsum1 += __shfl_xor_sync(0xffffffffu, rsum1, 1);
    rsum1 += __shfl_xor_sync(0xffffffffu, rsum1, 2);
    if ((lane & 3) == 0) { rsx[ch * 64 + r0] = rsum0; rsx[ch * 64 + r1] = rsum1; }
    __syncthreads();
    if (ch == 0 && (lane & 3) == 0) {
        scb[r0] = 1.f / (rsum0 + rsx[64 + r0]);
        scb[r1] = 1.f / (rsum1 + rsx[64 + r1]);
    }
    __syncthreads();

    const int rb = qg * 32 + (lane >> 2);
    const float i0 = scb[rb],      i1 = scb[rb + 8];
    const float i2 = scb[rb + 16], i3 = scb[rb + 24];
#pragma unroll
    for (int nj = 0; nj < 8; nj++) {
        const int col = cq * 64 + nj * 8 + 2 * (lane & 3);
        *(half2*)(g_cat + ((size_t)b * NN + m0 + rb) * 512 + col) =
            __floats2half2_rn(acc[nj][0] * i0, acc[nj][1] * i0);
        *(half2*)(g_cat + ((size_t)b * NN + m0 + rb + 8) * 512 + col) =
            __floats2half2_rn(acc[nj][2] * i1, acc[nj][3] * i1);
        *(half2*)(g_cat + ((size_t)b * NN + m0 + rb + 16) * 512 + col) =
            __floats2half2_rn(acc[8 + nj][0] * i2, acc[8 + nj][1] * i2);
        *(half2*)(g_cat + ((size_t)b * NN + m0 + rb + 24) * 512 + col) =
            __floats2half2_rn(acc[8 + nj][2] * i3, acc[8 + nj][3] * i3);
    }
}

// ---------------------------------------------------------------------------
// Kernel 3: output projection via mma
// ---------------------------------------------------------------------------
__global__ __launch_bounds__(256) void outproj_kernel(
    const float* __restrict__ bo, float* __restrict__ y)
{
    __shared__ __align__(16) __half As[64 * 72];
    __shared__ __align__(16) __half Bs[128 * 72];

    const int b  = blockIdx.z;
    const int o0 = blockIdx.y * 64;
    const int m0 = blockIdx.x * 128;
    const int t  = threadIdx.x;
    const int lane = t & 31, wrp = t >> 5;
    const int ob = (wrp & 3) * 16;
    const int mh = (wrp >> 2) * 64;

    float acc[8][4];
#pragma unroll
    for (int i = 0; i < 8; i++)
#pragma unroll
        for (int j = 0; j < 4; j++) acc[i][j] = 0.f;

    for (int k0 = 0; k0 < 512; k0 += 64) {
#pragma unroll
        for (int i = 0; i < 2; i++) {
            const int idx = t + i * 256;
            const int rowi = idx >> 3, c16 = idx & 7;
            ((uint4*)As)[rowi * 9 + c16] =
                *((const uint4*)(g_woh + (size_t)(o0 + rowi) * 512 + k0) + c16);
        }
#pragma unroll
        for (int i = 0; i < 4; i++) {
            const int idx = t + i * 256;
            const int rowi = idx >> 3, c16 = idx & 7;
            ((uint4*)Bs)[rowi * 9 + c16] =
                *((const uint4*)(g_cat + ((size_t)b * NN + m0 + rowi) * 512 + k0) + c16);
        }
        __syncthreads();

        unsigned int af[4][4];
#pragma unroll
        for (int k4 = 0; k4 < 4; k4++) {
            unsigned int a = smaddr(As + (ob + (lane & 15)) * 72 + k4 * 16 + (lane >> 4) * 8);
            ldsm_x4(af[k4][0], af[k4][1], af[k4][2], af[k4][3], a);
        }
#pragma unroll
        for (int pr = 0; pr < 4; pr++) {
#pragma unroll
            for (int k4 = 0; k4 < 4; k4++) {
                unsigned int b0, b1, b2, b3;
                unsigned int a = smaddr(Bs + (mh + pr * 16 + (lane >> 4) * 8 + (lane & 7)) * 72
                                           + k4 * 16 + ((lane >> 3) & 1) * 8);
                ldsm_x4(b0, b1, b2, b3, a);
                mma_f16(acc[pr * 2],     af[k4], b0, b1);
                mma_f16(acc[pr * 2 + 1], af[k4], b2, b3);
            }
        }
        __syncthreads();
    }

    const int orow = o0 + ob + (lane >> 2);
    const float bi0 = bo[orow], bi1 = bo[orow + 8];
#pragma unroll
    for (int chn = 0; chn < 8; chn++) {
        const int m = m0 + mh + chn * 8 + (lane & 3) * 2;
        float2 v0, v1;
        v0.x = acc[chn][0] + bi0; v0.y = acc[chn][1] + bi0;
        v1.x = acc[chn][2] + bi1; v1.y = acc[chn][3] + bi1;
        *(float2*)(y + ((size_t)b * CCH + orow)     * NN + m) = v0;
        *(float2*)(y + ((size_t)b * CCH + orow + 8) * NN + m) = v1;
    }
}

// ---------------------------------------------------------------------------
extern "C" void kernel_launch(void* const* d_in, const int* in_sizes, int n_in,
                              void* d_out, int out_size)
{
    const float* x  = (const float*)d_in[0];
    const float* Wq = (const float*)d_in[1];
    const float* bq = (const float*)d_in[2];
    const float* Wk = (const float*)d_in[3];
    const float* bk = (const float*)d_in[4];
    const float* Wv = (const float*)d_in[5];
    const float* bv = (const float*)d_in[6];
    const float* Wo = (const float*)d_in[7];
    const float* bo = (const float*)d_in[8];
    float* y = (float*)d_out;

    cudaFuncSetAttribute(attn_kernel,
                         cudaFuncAttributeMaxDynamicSharedMemorySize,
                         ATTN_SMEM);

    wconv_kernel<<<512, 256>>>(Wo);
    wsplit_kernel<<<320, 256>>>(Wq, bq, Wk, bk, Wv, bv);
    xpose_kernel<<<dim3(128, 8, BB), dim3(32, 8)>>>(x);
    qkv_mma_kernel<<<dim3(32, 5, BB), 256>>>();
    attn_kernel<<<dim3(64, BB), 256, ATTN_SMEM>>>();
    outproj_kernel<<<dim3(32, 4, BB), 256>>>(bo, y);
}

// round 12
// speedup vs baseline: 4.5637x; 1.0296x over previous
#include <cuda_runtime.h>
#include <cuda_fp16.h>
#include <cstdint>
#include <math.h>

#define BB  4
#define CCH 256
#define CQ  32
#define NN  4096
#define LOG2E 1.4426950408889634f

// Scratch (device globals: no allocation allowed)
__device__ __half g_qhi[BB * NN * CQ];         // q * log2e, hi
__device__ __half g_qlo[BB * NN * CQ];         // q * log2e, lo
__device__ __half g_khi[BB * NN * CQ];
__device__ __half g_klo[BB * NN * CQ];
__device__ __half g_vh[BB * NN * CCH];         // [b][n][256] fp16
__device__ __half g_cat[BB * NN * 2 * CCH];    // [b][n][512]: [0:256)=attn, [256:512)=x^T
__device__ __half g_woh[CCH * 2 * CCH];        // Wo fp16 [o][512]
__device__ __half g_whi[320 * CCH];            // fused QKV weight hi (q rows * log2e)
__device__ __half g_wlo[320 * CCH];            // fused QKV weight lo
__device__ float  g_bias[320];                 // fused QKV bias (q rows * log2e)
__device__ __half g_xhi[BB * CCH * NN];        // x hi fp16, [b][c][n]
__device__ __half g_xlo[BB * CCH * NN];        // x lo fp16, [b][c][n]

// ---------------- PTX helpers ----------------
__device__ __forceinline__ unsigned int smaddr(const void* p) {
    return (unsigned int)__cvta_generic_to_shared(p);
}
__device__ __forceinline__ void ldsm_x4(unsigned int& r0, unsigned int& r1,
                                        unsigned int& r2, unsigned int& r3,
                                        unsigned int a) {
    asm volatile("ldmatrix.sync.aligned.m8n8.x4.shared.b16 {%0,%1,%2,%3},[%4];\n"
                 : "=r"(r0), "=r"(r1), "=r"(r2), "=r"(r3) : "r"(a));
}
__device__ __forceinline__ void ldsm_x4t(unsigned int& r0, unsigned int& r1,
                                         unsigned int& r2, unsigned int& r3,
                                         unsigned int a) {
    asm volatile("ldmatrix.sync.aligned.m8n8.x4.trans.shared.b16 {%0,%1,%2,%3},[%4];\n"
                 : "=r"(r0), "=r"(r1), "=r"(r2), "=r"(r3) : "r"(a));
}
__device__ __forceinline__ void mma_f16(float* d, const unsigned int* a,
                                        unsigned int b0, unsigned int b1) {
    asm volatile("mma.sync.aligned.m16n8k16.row.col.f32.f16.f16.f32 "
                 "{%0,%1,%2,%3},{%4,%5,%6,%7},{%8,%9},{%0,%1,%2,%3};\n"
                 : "+f"(d[0]), "+f"(d[1]), "+f"(d[2]), "+f"(d[3])
                 : "r"(a[0]), "r"(a[1]), "r"(a[2]), "r"(a[3]), "r"(b0), "r"(b1));
}
__device__ __forceinline__ unsigned int ex2h2(float a, float b) {
    half2 h = __floats2half2_rn(a, b);
    unsigned int x = *(unsigned int*)&h, r;
    asm volatile("ex2.approx.f16x2 %0, %1;\n" : "=r"(r) : "r"(x));
    return r;
}
__device__ __forceinline__ half2 hu(unsigned int x) { return *(half2*)&x; }
__device__ __forceinline__ unsigned int pack2(float a, float b) {
    half2 h = __floats2half2_rn(a, b);
    return *(unsigned int*)&h;
}
__device__ __forceinline__ void barw(int id) {
    asm volatile("bar.sync %0, 64;\n" :: "r"(id));
}
__device__ __forceinline__ void cpa16(unsigned int dst, const void* src) {
    asm volatile("cp.async.cg.shared.global [%0], [%1], 16;\n" :: "r"(dst), "l"(src));
}
__device__ __forceinline__ void cpa_commit() {
    asm volatile("cp.async.commit_group;\n");
}
__device__ __forceinline__ void cpa_wait0() {
    asm volatile("cp.async.wait_group 0;\n");
}
__device__ __forceinline__ void cpa_wait1() {
    asm volatile("cp.async.wait_group 1;\n");
}

// ---------------------------------------------------------------------------
// Kernel 0a: Wo -> fp16
// ---------------------------------------------------------------------------
__global__ void wconv_kernel(const float* __restrict__ Wo) {
    int i = blockIdx.x * blockDim.x + threadIdx.x;
    g_woh[i] = __float2half(Wo[i]);
}

// ---------------------------------------------------------------------------
// Kernel 0b: split fused QKV weight to hi/lo fp16 (+ bias). q rows * log2e.
// ---------------------------------------------------------------------------
__global__ void wsplit_kernel(
    const float* __restrict__ Wq, const float* __restrict__ bq,
    const float* __restrict__ Wk, const float* __restrict__ bk,
    const float* __restrict__ Wv, const float* __restrict__ bv)
{
    int i = blockIdx.x * 256 + threadIdx.x;   // 81920 exact (320 blocks)
    int rowi = i >> 8, col = i & 255;
    float w;
    if (rowi < 32)      w = Wq[rowi * 256 + col] * LOG2E;
    else if (rowi < 64) w = Wk[(rowi - 32) * 256 + col];
    else                w = Wv[(rowi - 64) * 256 + col];
    __half h = __float2half_rn(w);
    g_whi[i] = h;
    g_wlo[i] = __float2half_rn(w - __half2float(h));
    if (i < 320) {
        float bb;
        if (i < 32)      bb = bq[i] * LOG2E;
        else if (i < 64) bb = bk[i - 32];
        else             bb = bv[i - 64];
        g_bias[i] = bb;
    }
}

// ---------------------------------------------------------------------------
// Kernel 0c: x -> cat (transposed fp16) AND x -> hi/lo fp16 (same layout)
// ---------------------------------------------------------------------------
__global__ void xpose_kernel(const float* __restrict__ x) {
    __shared__ float ts[32][33];
    const int b = blockIdx.z, n0 = blockIdx.x * 32, c0 = blockIdx.y * 32;
    const int txi = threadIdx.x, tyi = threadIdx.y;
#pragma unroll
    for (int i = 0; i < 4; i++) {
        int c = c0 + tyi + i * 8;
        const size_t off = ((size_t)b * CCH + c) * NN + n0 + txi;
        float v = x[off];
        ts[tyi + i * 8][txi] = v;
        __half h = __float2half_rn(v);
        g_xhi[off] = h;
        g_xlo[off] = __float2half_rn(v - __half2float(h));
    }
    __syncthreads();
#pragma unroll
    for (int i = 0; i < 4; i++) {
        int n = n0 + tyi + i * 8;
        g_cat[((size_t)b * NN + n) * 512 + 256 + c0 + txi] =
            __float2half(ts[txi][tyi + i * 8]);
    }
}

// ---------------------------------------------------------------------------
// Kernel 1: QKV projection via tensor cores, double-buffered cp.async.
// Per-buffer layout (27648 B): xhi[32][136h] 8704 | xlo 8704 | whi 5120 | wlo 5120
// Dynamic smem = 2 buffers = 55296 B. Epilogue stg fp32 [64][132] aliases.
// ---------------------------------------------------------------------------
#define QB 27648
#define QKV_SMEM 55296

__global__ __launch_bounds__(256) void qkv_mma_kernel()
{
    extern __shared__ __align__(16) char smq[];

    const int b  = blockIdx.z;
    const int o0 = blockIdx.y * 64;
    const int p0 = blockIdx.x * 128;
    const int t  = threadIdx.x;
    const int lane = t & 31, wrp = t >> 5;
    const int ob  = wrp & 3;     // 16-row out band
    const int ph2 = wrp >> 2;    // 64-pix half

    float acc[8][4];
#pragma unroll
    for (int i = 0; i < 8; i++)
#pragma unroll
        for (int j = 0; j < 4; j++) acc[i][j] = 0.f;

    // issue chunk 0 into buf0
    {
        const int rowi = t >> 2, seg = t & 3;
        cpa16(smaddr(smq + 17408 + rowi * 80 + seg * 16),
              g_whi + (size_t)(o0 + rowi) * 256 + seg * 8);
        cpa16(smaddr(smq + 22528 + rowi * 80 + seg * 16),
              g_wlo + (size_t)(o0 + rowi) * 256 + seg * 8);
#pragma unroll
        for (int i = 0; i < 2; i++) {
            const int idx = t + i * 256;
            const int row = idx >> 4, ck = idx & 15;
            const size_t src = ((size_t)b * CCH + row) * NN + p0 + ck * 8;
            cpa16(smaddr(smq + row * 272 + ck * 16), g_xhi + src);
            cpa16(smaddr(smq + 8704 + row * 272 + ck * 16), g_xlo + src);
        }
        cpa_commit();
    }

    for (int kci = 0; kci < 8; kci++) {
        char* buf = smq + (kci & 1) * QB;
        char* xhi = buf;
        char* xlo = buf + 8704;
        char* whi = buf + 17408;
        char* wlo = buf + 22528;

        if (kci < 7) {
            char* nb = smq + ((kci + 1) & 1) * QB;
            const int kc1 = (kci + 1) * 32;
            const int rowi = t >> 2, seg = t & 3;
            cpa16(smaddr(nb + 17408 + rowi * 80 + seg * 16),
                  g_whi + (size_t)(o0 + rowi) * 256 + kc1 + seg * 8);
            cpa16(smaddr(nb + 22528 + rowi * 80 + seg * 16),
                  g_wlo + (size_t)(o0 + rowi) * 256 + kc1 + seg * 8);
#pragma unroll
            for (int i = 0; i < 2; i++) {
                const int idx = t + i * 256;
                const int row = idx >> 4, ck = idx & 15;
                const size_t src = ((size_t)b * CCH + kc1 + row) * NN + p0 + ck * 8;
                cpa16(smaddr(nb + row * 272 + ck * 16), g_xhi + src);
                cpa16(smaddr(nb + 8704 + row * 272 + ck * 16), g_xlo + src);
            }
            cpa_commit();
            cpa_wait1();
        } else {
            cpa_wait0();
        }
        __syncthreads();

        unsigned awh[2][4], awl[2][4];
#pragma unroll
        for (int ks = 0; ks < 2; ks++) {
            const int woff = (ob * 16 + (lane & 15)) * 80 + ks * 32 + ((lane >> 4) << 4);
            ldsm_x4(awh[ks][0], awh[ks][1], awh[ks][2], awh[ks][3], smaddr(whi + woff));
            ldsm_x4(awl[ks][0], awl[ks][1], awl[ks][2], awl[ks][3], smaddr(wlo + woff));
        }
#pragma unroll
        for (int ks = 0; ks < 2; ks++) {
#pragma unroll
            for (int ng = 0; ng < 4; ng++) {
                unsigned bh0, bh1, bh2, bh3, bl0, bl1, bl2, bl3;
                const int xoff = (ks * 16 + (lane & 15)) * 272
                               + ph2 * 128 + ng * 32 + ((lane >> 4) << 4);
                ldsm_x4t(bh0, bh1, bh2, bh3, smaddr(xhi + xoff));
                ldsm_x4t(bl0, bl1, bl2, bl3, smaddr(xlo + xoff));
                mma_f16(acc[ng * 2],     awh[ks], bh0, bh1);
                mma_f16(acc[ng * 2],     awl[ks], bh0, bh1);
                mma_f16(acc[ng * 2],     awh[ks], bl0, bl1);
                mma_f16(acc[ng * 2 + 1], awh[ks], bh2, bh3);
                mma_f16(acc[ng * 2 + 1], awl[ks], bh2, bh3);
                mma_f16(acc[ng * 2 + 1], awh[ks], bl2, bl3);
            }
        }
        __syncthreads();
    }

    // ---- epilogue: bias, stage fp32, re-read transposed, write outputs ----
    float* stg = (float*)smq;   // [64][132]
    const int r0o = ob * 16 + (lane >> 2);
    const float b0 = g_bias[o0 + r0o], b1 = g_bias[o0 + r0o + 8];
#pragma unroll
    for (int j = 0; j < 8; j++) {
        const int pcol = ph2 * 64 + j * 8 + 2 * (lane & 3);
        float2 v0, v1;
        v0.x = acc[j][0] + b0; v0.y = acc[j][1] + b0;
        v1.x = acc[j][2] + b1; v1.y = acc[j][3] + b1;
        *(float2*)&stg[r0o * 132 + pcol]       = v0;
        *(float2*)&stg[(r0o + 8) * 132 + pcol] = v1;
    }
    __syncthreads();

    const int p  = t >> 1, hf = t & 1;
    const int pg = p0 + p;
    if (o0 == 0) {
        unsigned uh[16], ul[16];
#pragma unroll
        for (int i = 0; i < 16; i++) {
            float a = stg[(hf * 32 + 2 * i) * 132 + p];
            float c = stg[(hf * 32 + 2 * i + 1) * 132 + p];
            half2 h = __floats2half2_rn(a, c);
            float2 hfv = __half22float2(h);
            half2 l = __floats2half2_rn(a - hfv.x, c - hfv.y);
            uh[i] = *(unsigned*)&h;
            ul[i] = *(unsigned*)&l;
        }
        __half* dh = (hf ? g_khi : g_qhi) + ((size_t)b * NN + pg) * CQ;
        __half* dl = (hf ? g_klo : g_qlo) + ((size_t)b * NN + pg) * CQ;
#pragma unroll
        for (int i = 0; i < 4; i++) {
            ((uint4*)dh)[i] = make_uint4(uh[4*i], uh[4*i+1], uh[4*i+2], uh[4*i+3]);
            ((uint4*)dl)[i] = make_uint4(ul[4*i], ul[4*i+1], ul[4*i+2], ul[4*i+3]);
        }
    } else {
        unsigned uh[16];
#pragma unroll
        for (int i = 0; i < 16; i++) {
            float a = stg[(hf * 32 + 2 * i) * 132 + p];
            float c = stg[(hf * 32 + 2 * i + 1) * 132 + p];
            uh[i] = pack2(a, c);
        }
        __half* dv = g_vh + ((size_t)b * NN + pg) * CCH + (o0 - 64) + hf * 32;
#pragma unroll
        for (int i = 0; i < 4; i++)
            ((uint4*)dv)[i] = make_uint4(uh[4*i], uh[4*i+1], uh[4*i+2], uh[4*i+3]);
    }
}

// ---------------------------------------------------------------------------
// Kernel 2: flash attention (R11: double-buffered cp.async, 2 syncs/tile).
// ---------------------------------------------------------------------------
#define A_BUF   44032
#define A_PH    88064
#define A_RSX   97280
#define A_SCB   97792
#define ATTN_SMEM 98048

__global__ __launch_bounds__(256, 2) void attn_kernel()
{
    extern __shared__ char smd[];
    __half* ph  = (__half*)(smd + A_PH);
    float*  rsx = (float*)(smd + A_RSX);
    float*  scb = (float*)(smd + A_SCB);

    const int b    = blockIdx.y;
    const int m0   = blockIdx.x * 64;
    const int t    = threadIdx.x;
    const int lane = t & 31;
    const int wrp  = t >> 5;
    const int band = wrp & 3;
    const int ch   = wrp >> 2;
    const int bid  = band + 1;
    const int qg   = wrp & 1;
    const int cq   = wrp >> 1;

    const int row = t >> 2, c4 = t & 3;
    const int r0 = band * 16 + (lane >> 2), r1 = r0 + 8;

    {
        char* qa = smd + A_BUF + 10240;
        *((uint4*)(qa + row * 80) + c4) =
            *((const uint4*)(g_qhi + ((size_t)b * NN + m0 + row) * CQ) + c4);
        *((uint4*)(qa + 5120 + row * 80) + c4) =
            *((const uint4*)(g_qlo + ((size_t)b * NN + m0 + row) * CQ) + c4);

        cpa16(smaddr(smd + row * 80 + c4 * 16),
              g_khi + ((size_t)b * NN + row) * CQ + c4 * 8);
        cpa16(smaddr(smd + 5120 + row * 80 + c4 * 16),
              g_klo + ((size_t)b * NN + row) * CQ + c4 * 8);
        const __half* vsrc = g_vh + (size_t)b * NN * CCH;
#pragma unroll
        for (int i = 0; i < 8; i++) {
            const int idx = t + i * 256;
            const int vr = idx >> 5, vc = idx & 31;
            cpa16(smaddr(smd + 10240 + vr * 528 + vc * 16), vsrc + vr * CCH + vc * 8);
        }
        cpa_commit();
    }
    __syncthreads();

    unsigned qh[2][4], ql[2][4];
    {
        char* qa = smd + A_BUF + 10240;
        const int aoff = (band * 16 + (lane & 15)) * 80 + ((lane >> 4) << 4);
#pragma unroll
        for (int ks = 0; ks < 2; ks++) {
            ldsm_x4(qh[ks][0], qh[ks][1], qh[ks][2], qh[ks][3],
                    smaddr(qa + aoff + ks * 32));
            ldsm_x4(ql[ks][0], ql[ks][1], ql[ks][2], ql[ks][3],
                    smaddr(qa + 5120 + aoff + ks * 32));
        }
    }

    float acc[16][4];
#pragma unroll
    for (int g = 0; g < 16; g++)
#pragma unroll
        for (int j = 0; j < 4; j++) acc[g][j] = 0.f;
    float rmax0 = -INFINITY, rmax1 = -INFINITY, rsum0 = 0.f, rsum1 = 0.f;

    for (int nt = 0; nt < 64; nt++) {
        char* buf = smd + (nt & 1) * A_BUF;
        char* kh  = buf;
        char* kl  = buf + 5120;
        char* vb  = buf + 10240;

        cpa_wait0();
        __syncthreads();   // A: tile nt visible + all warps done PV of nt-1

        if (nt < 63) {
            char* nb = smd + ((nt + 1) & 1) * A_BUF;
            const int n1 = (nt + 1) * 64;
            cpa16(smaddr(nb + row * 80 + c4 * 16),
                  g_khi + ((size_t)b * NN + n1 + row) * CQ + c4 * 8);
            cpa16(smaddr(nb + 5120 + row * 80 + c4 * 16),
                  g_klo + ((size_t)b * NN + n1 + row) * CQ + c4 * 8);
            const __half* vsrc = g_vh + ((size_t)b * NN + n1) * CCH;
#pragma unroll
            for (int i = 0; i < 8; i++) {
                const int idx = t + i * 256;
                const int vr = idx >> 5, vc = idx & 31;
                cpa16(smaddr(nb + 10240 + vr * 528 + vc * 16),
                      vsrc + vr * CCH + vc * 8);
            }
            cpa_commit();
        }

        float sacc[4][4];
#pragma unroll
        for (int n = 0; n < 4; n++)
#pragma unroll
            for (int j = 0; j < 4; j++) sacc[n][j] = 0.f;
#pragma unroll
        for (int np = 0; np < 2; np++) {
#pragma unroll
            for (int ks = 0; ks < 2; ks++) {
                unsigned bh0, bh1, bh2, bh3, bl0, bl1, bl2, bl3;
                const int roff = (ch * 32 + np * 16 + ((lane >> 4) << 3) + (lane & 7)) * 80
                               + ks * 32 + (((lane >> 3) & 1) << 4);
                ldsm_x4(bh0, bh1, bh2, bh3, smaddr(kh + roff));
                ldsm_x4(bl0, bl1, bl2, bl3, smaddr(kl + roff));
                mma_f16(sacc[np * 2],     qh[ks], bh0, bh1);
                mma_f16(sacc[np * 2],     ql[ks], bh0, bh1);
                mma_f16(sacc[np * 2],     qh[ks], bl0, bl1);
                mma_f16(sacc[np * 2 + 1], qh[ks], bh2, bh3);
                mma_f16(sacc[np * 2 + 1], ql[ks], bh2, bh3);
                mma_f16(sacc[np * 2 + 1], qh[ks], bl2, bl3);
            }
        }

        float tm0 = fmaxf(fmaxf(sacc[0][0], sacc[0][1]), fmaxf(sacc[1][0], sacc[1][1]));
        float tm1 = fmaxf(fmaxf(sacc[0][2], sacc[0][3]), fmaxf(sacc[1][2], sacc[1][3]));
        tm0 = fmaxf(tm0, fmaxf(fmaxf(sacc[2][0], sacc[2][1]), fmaxf(sacc[3][0], sacc[3][1])));
        tm1 = fmaxf(tm1, fmaxf(fmaxf(sacc[2][2], sacc[2][3]), fmaxf(sacc[3][2], sacc[3][3])));
        tm0 = fmaxf(tm0, __shfl_xor_sync(0xffffffffu, tm0, 1));
        tm0 = fmaxf(tm0, __shfl_xor_sync(0xffffffffu, tm0, 2));
        tm1 = fmaxf(tm1, __shfl_xor_sync(0xffffffffu, tm1, 1));
        tm1 = fmaxf(tm1, __shfl_xor_sync(0xffffffffu, tm1, 2));
        if ((lane & 3) == 0) { rsx[ch * 64 + r0] = tm0; rsx[ch * 64 + r1] = tm1; }
        barw(bid);
        tm0 = fmaxf(tm0, rsx[(ch ^ 1) * 64 + r0]);
        tm1 = fmaxf(tm1, rsx[(ch ^ 1) * 64 + r1]);

        const float nm0 = fmaxf(rmax0, tm0), nm1 = fmaxf(rmax1, tm1);
        const float sc0 = exp2f(rmax0 - nm0), sc1 = exp2f(rmax1 - nm1);
        rmax0 = nm0; rmax1 = nm1;
        rsum0 *= sc0; rsum1 *= sc1;
        if (ch == 0 && (lane & 3) == 0) { scb[r0] = sc0; scb[r1] = sc1; }

        unsigned pr0[4], pr1[4];
#pragma unroll
        for (int nj = 0; nj < 4; nj++) {
            pr0[nj] = ex2h2(sacc[nj][0] - nm0, sacc[nj][1] - nm0);
            pr1[nj] = ex2h2(sacc[nj][2] - nm1, sacc[nj][3] - nm1);
            const int col = ch * 32 + nj * 8 + 2 * (lane & 3);
            *(half2*)(ph + r0 * 72 + col) = hu(pr0[nj]);
            *(half2*)(ph + r1 * 72 + col) = hu(pr1[nj]);
        }
        {
            float2 f0 = __half22float2(__hadd2(__hadd2(hu(pr0[0]), hu(pr0[1])),
                                               __hadd2(hu(pr0[2]), hu(pr0[3]))));
            float2 f1 = __half22float2(__hadd2(__hadd2(hu(pr1[0]), hu(pr1[1])),
                                               __hadd2(hu(pr1[2]), hu(pr1[3]))));
            rsum0 += f0.x + f0.y;
            rsum1 += f1.x + f1.y;
        }
        __syncthreads();   // B: P + scb ready block-wide

        {
            const int rb = qg * 32 + (lane >> 2);
            const float s0 = scb[rb],      s1 = scb[rb + 8];
            const float s2 = scb[rb + 16], s3 = scb[rb + 24];
            const bool skip = __all_sync(0xffffffffu,
                (s0 == 1.f) && (s1 == 1.f) && (s2 == 1.f) && (s3 == 1.f));
            if (!skip) {
#pragma unroll
                for (int nj = 0; nj < 8; nj++) {
                    acc[nj][0] *= s0; acc[nj][1] *= s0;
                    acc[nj][2] *= s1; acc[nj][3] *= s1;
                    acc[8 + nj][0] *= s2; acc[8 + nj][1] *= s2;
                    acc[8 + nj][2] *= s3; acc[8 + nj][3] *= s3;
                }
            }
#pragma unroll
            for (int ks = 0; ks < 4; ks++) {
                unsigned pf0[4], pf1[4];
                const int pcol = ks * 32 + ((lane >> 4) << 4);
                ldsm_x4(pf0[0], pf0[1], pf0[2], pf0[3],
                    smaddr((char*)ph + (qg * 32 + (lane & 15)) * 144 + pcol));
                ldsm_x4(pf1[0], pf1[1], pf1[2], pf1[3],
                    smaddr((char*)ph + (qg * 32 + 16 + (lane & 15)) * 144 + pcol));
                const int vrow = (ks * 16 + (lane & 15)) * 528
                               + cq * 128 + ((lane >> 4) << 4);
#pragma unroll
                for (int cc = 0; cc < 4; cc++) {
                    unsigned v0, v1, v2, v3;
                    ldsm_x4t(v0, v1, v2, v3, smaddr(vb + vrow + cc * 32));
                    mma_f16(acc[cc * 2],         pf0, v0, v1);
                    mma_f16(acc[cc * 2 + 1],     pf0, v2, v3);
                    mma_f16(acc[8 + cc * 2],     pf1, v0, v1);
                    mma_f16(acc[8 + cc * 2 + 1], pf1, v2, v3);
                }
            }
        }
    }

    rsum0 += __shfl_xor_sync(0xffffffffu, rsum0, 1);
    rsum0 += __shfl_xor_sync(0xffffffffu, rsum0, 2);
    rsum1 += __shfl_xor_sync(0xffffffffu, rsum1, 1);
    rsum1 += __shfl_xor_sync(0xffffffffu, rsum1, 2);
    if ((lane & 3) == 0) { rsx[ch * 64 + r0] = rsum0; rsx[ch * 64 + r1] = rsum1; }
    __syncthreads();
    if (ch == 0 && (lane & 3) == 0) {
        scb[r0] = 1.f / (rsum0 + rsx[64 + r0]);
        scb[r1] = 1.f / (rsum1 + rsx[64 + r1]);
    }
    __syncthreads();

    const int rb = qg * 32 + (lane >> 2);
    const float i0 = scb[rb],      i1 = scb[rb + 8];
    const float i2 = scb[rb + 16], i3 = scb[rb + 24];
#pragma unroll
    for (int nj = 0; nj < 8; nj++) {
        const int col = cq * 64 + nj * 8 + 2 * (lane & 3);
        *(half2*)(g_cat + ((size_t)b * NN + m0 + rb) * 512 + col) =
            __floats2half2_rn(acc[nj][0] * i0, acc[nj][1] * i0);
        *(half2*)(g_cat + ((size_t)b * NN + m0 + rb + 8) * 512 + col) =
            __floats2half2_rn(acc[nj][2] * i1, acc[nj][3] * i1);
        *(half2*)(g_cat + ((size_t)b * NN + m0 + rb + 16) * 512 + col) =
            __floats2half2_rn(acc[8 + nj][0] * i2, acc[8 + nj][1] * i2);
        *(half2*)(g_cat + ((size_t)b * NN + m0 + rb + 24) * 512 + col) =
            __floats2half2_rn(acc[8 + nj][2] * i3, acc[8 + nj][3] * i3);
    }
}

// ---------------------------------------------------------------------------
// Kernel 3: output projection via mma, double-buffered cp.async.
// Per-buffer (27648 B): As[64][72h] 9216 | Bs[128][72h] 18432. Dyn smem 55296.
// ---------------------------------------------------------------------------
#define OB 27648
#define OUT_SMEM 55296

__global__ __launch_bounds__(256) void outproj_kernel(
    const float* __restrict__ bo, float* __restrict__ y)
{
    extern __shared__ __align__(16) char smo[];

    const int b  = blockIdx.z;
    const int o0 = blockIdx.y * 64;
    const int m0 = blockIdx.x * 128;
    const int t  = threadIdx.x;
    const int lane = t & 31, wrp = t >> 5;
    const int ob = (wrp & 3) * 16;
    const int mh = (wrp >> 2) * 64;

    float acc[8][4];
#pragma unroll
    for (int i = 0; i < 8; i++)
#pragma unroll
        for (int j = 0; j < 4; j++) acc[i][j] = 0.f;

    // issue chunk 0 into buf0
    {
#pragma unroll
        for (int i = 0; i < 2; i++) {
            const int idx = t + i * 256;
            const int rowi = idx >> 3, c16 = idx & 7;
            cpa16(smaddr(smo + rowi * 144 + c16 * 16),
                  g_woh + (size_t)(o0 + rowi) * 512 + c16 * 8);
        }
#pragma unroll
        for (int i = 0; i < 4; i++) {
            const int idx = t + i * 256;
            const int rowi = idx >> 3, c16 = idx & 7;
            cpa16(smaddr(smo + 9216 + rowi * 144 + c16 * 16),
                  g_cat + ((size_t)b * NN + m0 + rowi) * 512 + c16 * 8);
        }
        cpa_commit();
    }

    for (int kci = 0; kci < 8; kci++) {
        char* buf = smo + (kci & 1) * OB;
        __half* As = (__half*)buf;
        __half* Bs = (__half*)(buf + 9216);

        if (kci < 7) {
            char* nb = smo + ((kci + 1) & 1) * OB;
            const int k1 = (kci + 1) * 64;
#pragma unroll
            for (int i = 0; i < 2; i++) {
                const int idx = t + i * 256;
                const int rowi = idx >> 3, c16 = idx & 7;
                cpa16(smaddr(nb + rowi * 144 + c16 * 16),
                      g_woh + (size_t)(o0 + rowi) * 512 + k1 + c16 * 8);
            }
#pragma unroll
            for (int i = 0; i < 4; i++) {
                const int idx = t + i * 256;
                const int rowi = idx >> 3, c16 = idx & 7;
                cpa16(smaddr(nb + 9216 + rowi * 144 + c16 * 16),
                      g_cat + ((size_t)b * NN + m0 + rowi) * 512 + k1 + c16 * 8);
            }
            cpa_commit();
            cpa_wait1();
        } else {
            cpa_wait0();
        }
        __syncthreads();

        unsigned int af[4][4];
#pragma unroll
        for (int k4 = 0; k4 < 4; k4++) {
            unsigned int a = smaddr(As + (ob + (lane & 15)) * 72 + k4 * 16 + (lane >> 4) * 8);
            ldsm_x4(af[k4][0], af[k4][1], af[k4][2], af[k4][3], a);
        }
#pragma unroll
        for (int pr = 0; pr < 4; pr++) {
#pragma unroll
            for (int k4 = 0; k4 < 4; k4++) {
                unsigned int b0, b1, b2, b3;
                unsigned int a = smaddr(Bs + (mh + pr * 16 + (lane >> 4) * 8 + (lane & 7)) * 72
                                           + k4 * 16 + ((lane >> 3) & 1) * 8);
                ldsm_x4(b0, b1, b2, b3, a);
                mma_f16(acc[pr * 2],     af[k4], b0, b1);
                mma_f16(acc[pr * 2 + 1], af[k4], b2, b3);
            }
        }
        __syncthreads();
    }

    const int orow = o0 + ob + (lane >> 2);
    const float bi0 = bo[orow], bi1 = bo[orow + 8];
#pragma unroll
    for (int chn = 0; chn < 8; chn++) {
        const int m = m0 + mh + chn * 8 + (lane & 3) * 2;
        float2 v0, v1;
        v0.x = acc[chn][0] + bi0; v0.y = acc[chn][1] + bi0;
        v1.x = acc[chn][2] + bi1; v1.y = acc[chn][3] + bi1;
        *(float2*)(y + ((size_t)b * CCH + orow)     * NN + m) = v0;
        *(float2*)(y + ((size_t)b * CCH + orow + 8) * NN + m) = v1;
    }
}

// ---------------------------------------------------------------------------
extern "C" void kernel_launch(void* const* d_in, const int* in_sizes, int n_in,
                              void* d_out, int out_size)
{
    const float* x  = (const float*)d_in[0];
    const float* Wq = (const float*)d_in[1];
    const float* bq = (const float*)d_in[2];
    const float* Wk = (const float*)d_in[3];
    const float* bk = (const float*)d_in[4];
    const float* Wv = (const float*)d_in[5];
    const float* bv = (const float*)d_in[6];
    const float* Wo = (const float*)d_in[7];
    const float* bo = (const float*)d_in[8];
    float* y = (float*)d_out;

    cudaFuncSetAttribute(attn_kernel,
                         cudaFuncAttributeMaxDynamicSharedMemorySize, ATTN_SMEM);
    cudaFuncSetAttribute(qkv_mma_kernel,
                         cudaFuncAttributeMaxDynamicSharedMemorySize, QKV_SMEM);
    cudaFuncSetAttribute(outproj_kernel,
                         cudaFuncAttributeMaxDynamicSharedMemorySize, OUT_SMEM);

    wconv_kernel<<<512, 256>>>(Wo);
    wsplit_kernel<<<320, 256>>>(Wq, bq, Wk, bk, Wv, bv);
    xpose_kernel<<<dim3(128, 8, BB), dim3(32, 8)>>>(x);
    qkv_mma_kernel<<<dim3(32, 5, BB), 256, QKV_SMEM>>>();
    attn_kernel<<<dim3(64, BB), 256, ATTN_SMEM>>>();
    outproj_kernel<<<dim3(32, 4, BB), 256, OUT_SMEM>>>(bo, y);
}

// round 14
// speedup vs baseline: 4.6329x; 1.0152x over previous
#include <cuda_runtime.h>
#include <cuda_fp16.h>
#include <cstdint>
#include <math.h>

#define BB  4
#define CCH 256
#define CQ  32
#define NN  4096
#define LOG2E 1.4426950408889634f

// Scratch (device globals: no allocation allowed)
__device__ __half g_qhi[BB * NN * CQ];         // q * log2e, hi
__device__ __half g_qlo[BB * NN * CQ];         // q * log2e, lo
__device__ __half g_khi[BB * NN * CQ];
__device__ __half g_klo[BB * NN * CQ];
__device__ __half g_vh[BB * NN * CCH];         // [b][n][256] fp16
__device__ __half g_cat[BB * NN * 2 * CCH];    // [b][n][512]: [0:256)=attn, [256:512)=x^T
__device__ __half g_woh[CCH * 2 * CCH];        // Wo fp16 [o][512]
__device__ __half g_whi[320 * CCH];            // fused QKV weight hi (q rows * log2e)
__device__ __half g_wlo[320 * CCH];            // fused QKV weight lo
__device__ float  g_bias[320];                 // fused QKV bias (q rows * log2e)
__device__ __half g_xhi[BB * CCH * NN];        // x hi fp16, [b][c][n]
__device__ __half g_xlo[BB * CCH * NN];        // x lo fp16, [b][c][n]

// ---------------- PTX helpers ----------------
__device__ __forceinline__ unsigned int smaddr(const void* p) {
    return (unsigned int)__cvta_generic_to_shared(p);
}
__device__ __forceinline__ void ldsm_x4(unsigned int& r0, unsigned int& r1,
                                        unsigned int& r2, unsigned int& r3,
                                        unsigned int a) {
    asm volatile("ldmatrix.sync.aligned.m8n8.x4.shared.b16 {%0,%1,%2,%3},[%4];\n"
                 : "=r"(r0), "=r"(r1), "=r"(r2), "=r"(r3) : "r"(a));
}
__device__ __forceinline__ void ldsm_x4t(unsigned int& r0, unsigned int& r1,
                                         unsigned int& r2, unsigned int& r3,
                                         unsigned int a) {
    asm volatile("ldmatrix.sync.aligned.m8n8.x4.trans.shared.b16 {%0,%1,%2,%3},[%4];\n"
                 : "=r"(r0), "=r"(r1), "=r"(r2), "=r"(r3) : "r"(a));
}
__device__ __forceinline__ void mma_f16(float* d, const unsigned int* a,
                                        unsigned int b0, unsigned int b1) {
    asm volatile("mma.sync.aligned.m16n8k16.row.col.f32.f16.f16.f32 "
                 "{%0,%1,%2,%3},{%4,%5,%6,%7},{%8,%9},{%0,%1,%2,%3};\n"
                 : "+f"(d[0]), "+f"(d[1]), "+f"(d[2]), "+f"(d[3])
                 : "r"(a[0]), "r"(a[1]), "r"(a[2]), "r"(a[3]), "r"(b0), "r"(b1));
}
__device__ __forceinline__ unsigned int ex2h2(float a, float b) {
    half2 h = __floats2half2_rn(a, b);
    unsigned int x = *(unsigned int*)&h, r;
    asm volatile("ex2.approx.f16x2 %0, %1;\n" : "=r"(r) : "r"(x));
    return r;
}
__device__ __forceinline__ half2 hu(unsigned int x) { return *(half2*)&x; }
__device__ __forceinline__ unsigned int pack2(float a, float b) {
    half2 h = __floats2half2_rn(a, b);
    return *(unsigned int*)&h;
}
__device__ __forceinline__ void barw(int id) {
    asm volatile("bar.sync %0, 64;\n" :: "r"(id));
}
__device__ __forceinline__ void cpa16(unsigned int dst, const void* src) {
    asm volatile("cp.async.cg.shared.global [%0], [%1], 16;\n" :: "r"(dst), "l"(src));
}
__device__ __forceinline__ void cpa_commit() {
    asm volatile("cp.async.commit_group;\n");
}
__device__ __forceinline__ void cpa_wait0() {
    asm volatile("cp.async.wait_group 0;\n");
}

// ---------------------------------------------------------------------------
// Kernel 0a: fused weight prep. blocks [0,512): Wo->fp16; [512,832): QKV split.
// ---------------------------------------------------------------------------
__global__ void wprep_kernel(
    const float* __restrict__ Wo,
    const float* __restrict__ Wq, const float* __restrict__ bq,
    const float* __restrict__ Wk, const float* __restrict__ bk,
    const float* __restrict__ Wv, const float* __restrict__ bv)
{
    if (blockIdx.x < 512) {
        int i = blockIdx.x * 256 + threadIdx.x;
        g_woh[i] = __float2half(Wo[i]);
    } else {
        int i = (blockIdx.x - 512) * 256 + threadIdx.x;   // 81920 exact
        int rowi = i >> 8, col = i & 255;
        float w;
        if (rowi < 32)      w = Wq[rowi * 256 + col] * LOG2E;
        else if (rowi < 64) w = Wk[(rowi - 32) * 256 + col];
        else                w = Wv[(rowi - 64) * 256 + col];
        __half h = __float2half_rn(w);
        g_whi[i] = h;
        g_wlo[i] = __float2half_rn(w - __half2float(h));
        if (i < 320) {
            float bb;
            if (i < 32)      bb = bq[i] * LOG2E;
            else if (i < 64) bb = bk[i - 32];
            else             bb = bv[i - 64];
            g_bias[i] = bb;
        }
    }
}

// ---------------------------------------------------------------------------
// Kernel 0b: x -> cat (transposed fp16) AND x -> hi/lo fp16 (same layout)
// ---------------------------------------------------------------------------
__global__ void xpose_kernel(const float* __restrict__ x) {
    __shared__ float ts[32][33];
    const int b = blockIdx.z, n0 = blockIdx.x * 32, c0 = blockIdx.y * 32;
    const int txi = threadIdx.x, tyi = threadIdx.y;
#pragma unroll
    for (int i = 0; i < 4; i++) {
        int c = c0 + tyi + i * 8;
        const size_t off = ((size_t)b * CCH + c) * NN + n0 + txi;
        float v = x[off];
        ts[tyi + i * 8][txi] = v;
        __half h = __float2half_rn(v);
        g_xhi[off] = h;
        g_xlo[off] = __float2half_rn(v - __half2float(h));
    }
    __syncthreads();
#pragma unroll
    for (int i = 0; i < 4; i++) {
        int n = n0 + tyi + i * 8;
        g_cat[((size_t)b * NN + n) * 512 + 256 + c0 + txi] =
            __float2half(ts[txi][tyi + i * 8]);
    }
}

// ---------------------------------------------------------------------------
// Kernel 1: QKV projection via tensor cores, double-buffered, 1 sync/chunk.
// Per-buffer (27648 B): xhi[32][136h] 8704 | xlo 8704 | whi 5120 | wlo 5120
// Dynamic smem = 55296 B. Epilogue stg fp32 [64][132] aliases.
// ---------------------------------------------------------------------------
#define QB 27648
#define QKV_SMEM 55296

__global__ __launch_bounds__(256) void qkv_mma_kernel()
{
    extern __shared__ __align__(16) char smq[];

    const int b  = blockIdx.z;
    const int o0 = blockIdx.y * 64;
    const int p0 = blockIdx.x * 128;
    const int t  = threadIdx.x;
    const int lane = t & 31, wrp = t >> 5;
    const int ob  = wrp & 3;     // 16-row out band
    const int ph2 = wrp >> 2;    // 64-pix half

    float acc[8][4];
#pragma unroll
    for (int i = 0; i < 8; i++)
#pragma unroll
        for (int j = 0; j < 4; j++) acc[i][j] = 0.f;

    // issue chunk 0 into buf0
    {
        const int rowi = t >> 2, seg = t & 3;
        cpa16(smaddr(smq + 17408 + rowi * 80 + seg * 16),
              g_whi + (size_t)(o0 + rowi) * 256 + seg * 8);
        cpa16(smaddr(smq + 22528 + rowi * 80 + seg * 16),
              g_wlo + (size_t)(o0 + rowi) * 256 + seg * 8);
#pragma unroll
        for (int i = 0; i < 2; i++) {
            const int idx = t + i * 256;
            const int row = idx >> 4, ck = idx & 15;
            const size_t src = ((size_t)b * CCH + row) * NN + p0 + ck * 8;
            cpa16(smaddr(smq + row * 272 + ck * 16), g_xhi + src);
            cpa16(smaddr(smq + 8704 + row * 272 + ck * 16), g_xlo + src);
        }
        cpa_commit();
    }

    for (int kci = 0; kci < 8; kci++) {
        char* buf = smq + (kci & 1) * QB;
        char* xhi = buf;
        char* xlo = buf + 8704;
        char* whi = buf + 17408;
        char* wlo = buf + 22528;

        cpa_wait0();       // chunk kci complete (only group in flight)
        __syncthreads();   // + all warps done computing chunk kci-1

        if (kci < 7) {     // issue chunk kci+1 (overlaps compute below)
            char* nb = smq + ((kci + 1) & 1) * QB;
            const int kc1 = (kci + 1) * 32;
            const int rowi = t >> 2, seg = t & 3;
            cpa16(smaddr(nb + 17408 + rowi * 80 + seg * 16),
                  g_whi + (size_t)(o0 + rowi) * 256 + kc1 + seg * 8);
            cpa16(smaddr(nb + 22528 + rowi * 80 + seg * 16),
                  g_wlo + (size_t)(o0 + rowi) * 256 + kc1 + seg * 8);
#pragma unroll
            for (int i = 0; i < 2; i++) {
                const int idx = t + i * 256;
                const int row = idx >> 4, ck = idx & 15;
                const size_t src = ((size_t)b * CCH + kc1 + row) * NN + p0 + ck * 8;
                cpa16(smaddr(nb + row * 272 + ck * 16), g_xhi + src);
                cpa16(smaddr(nb + 8704 + row * 272 + ck * 16), g_xlo + src);
            }
            cpa_commit();
        }

        unsigned awh[2][4], awl[2][4];
#pragma unroll
        for (int ks = 0; ks < 2; ks++) {
            const int woff = (ob * 16 + (lane & 15)) * 80 + ks * 32 + ((lane >> 4) << 4);
            ldsm_x4(awh[ks][0], awh[ks][1], awh[ks][2], awh[ks][3], smaddr(whi + woff));
            ldsm_x4(awl[ks][0], awl[ks][1], awl[ks][2], awl[ks][3], smaddr(wlo + woff));
        }
#pragma unroll
        for (int ks = 0; ks < 2; ks++) {
#pragma unroll
            for (int ng = 0; ng < 4; ng++) {
                unsigned bh0, bh1, bh2, bh3, bl0, bl1, bl2, bl3;
                const int xoff = (ks * 16 + (lane & 15)) * 272
                               + ph2 * 128 + ng * 32 + ((lane >> 4) << 4);
                ldsm_x4t(bh0, bh1, bh2, bh3, smaddr(xhi + xoff));
                ldsm_x4t(bl0, bl1, bl2, bl3, smaddr(xlo + xoff));
                mma_f16(acc[ng * 2],     awh[ks], bh0, bh1);
                mma_f16(acc[ng * 2],     awl[ks], bh0, bh1);
                mma_f16(acc[ng * 2],     awh[ks], bl0, bl1);
                mma_f16(acc[ng * 2 + 1], awh[ks], bh2, bh3);
                mma_f16(acc[ng * 2 + 1], awl[ks], bh2, bh3);
                mma_f16(acc[ng * 2 + 1], awh[ks], bl2, bl3);
            }
        }
        // no trailing sync: next iteration's leading sync covers buffer reuse
    }
    __syncthreads();   // all compute done before epilogue aliases the buffers

    // ---- epilogue: bias, stage fp32, re-read transposed, write outputs ----
    float* stg = (float*)smq;   // [64][132]
    const int r0o = ob * 16 + (lane >> 2);
    const float b0 = g_bias[o0 + r0o], b1 = g_bias[o0 + r0o + 8];
#pragma unroll
    for (int j = 0; j < 8; j++) {
        const int pcol = ph2 * 64 + j * 8 + 2 * (lane & 3);
        float2 v0, v1;
        v0.x = acc[j][0] + b0; v0.y = acc[j][1] + b0;
        v1.x = acc[j][2] + b1; v1.y = acc[j][3] + b1;
        *(float2*)&stg[r0o * 132 + pcol]       = v0;
        *(float2*)&stg[(r0o + 8) * 132 + pcol] = v1;
    }
    __syncthreads();

    const int p  = t >> 1, hf = t & 1;
    const int pg = p0 + p;
    if (o0 == 0) {
        unsigned uh[16], ul[16];
#pragma unroll
        for (int i = 0; i < 16; i++) {
            float a = stg[(hf * 32 + 2 * i) * 132 + p];
            float c = stg[(hf * 32 + 2 * i + 1) * 132 + p];
            half2 h = __floats2half2_rn(a, c);
            float2 hfv = __half22float2(h);
            half2 l = __floats2half2_rn(a - hfv.x, c - hfv.y);
            uh[i] = *(unsigned*)&h;
            ul[i] = *(unsigned*)&l;
        }
        __half* dh = (hf ? g_khi : g_qhi) + ((size_t)b * NN + pg) * CQ;
        __half* dl = (hf ? g_klo : g_qlo) + ((size_t)b * NN + pg) * CQ;
#pragma unroll
        for (int i = 0; i < 4; i++) {
            ((uint4*)dh)[i] = make_uint4(uh[4*i], uh[4*i+1], uh[4*i+2], uh[4*i+3]);
            ((uint4*)dl)[i] = make_uint4(ul[4*i], ul[4*i+1], ul[4*i+2], ul[4*i+3]);
        }
    } else {
        unsigned uh[16];
#pragma unroll
        for (int i = 0; i < 16; i++) {
            float a = stg[(hf * 32 + 2 * i) * 132 + p];
            float c = stg[(hf * 32 + 2 * i + 1) * 132 + p];
            uh[i] = pack2(a, c);
        }
        __half* dv = g_vh + ((size_t)b * NN + pg) * CCH + (o0 - 64) + hf * 32;
#pragma unroll
        for (int i = 0; i < 4; i++)
            ((uint4*)dv)[i] = make_uint4(uh[4*i], uh[4*i+1], uh[4*i+2], uh[4*i+3]);
    }
}

// ---------------------------------------------------------------------------
// Kernel 2: flash attention (R11: double-buffered cp.async, 2 syncs/tile).
// ---------------------------------------------------------------------------
#define A_BUF   44032
#define A_PH    88064
#define A_RSX   97280
#define A_SCB   97792
#define ATTN_SMEM 98048

__global__ __launch_bounds__(256, 2) void attn_kernel()
{
    extern __shared__ char smd[];
    __half* ph  = (__half*)(smd + A_PH);
    float*  rsx = (float*)(smd + A_RSX);
    float*  scb = (float*)(smd + A_SCB);

    const int b    = blockIdx.y;
    const int m0   = blockIdx.x * 64;
    const int t    = threadIdx.x;
    const int lane = t & 31;
    const int wrp  = t >> 5;
    const int band = wrp & 3;
    const int ch   = wrp >> 2;
    const int bid  = band + 1;
    const int qg   = wrp & 1;
    const int cq   = wrp >> 1;

    const int row = t >> 2, c4 = t & 3;
    const int r0 = band * 16 + (lane >> 2), r1 = r0 + 8;

    {
        char* qa = smd + A_BUF + 10240;
        *((uint4*)(qa + row * 80) + c4) =
            *((const uint4*)(g_qhi + ((size_t)b * NN + m0 + row) * CQ) + c4);
        *((uint4*)(qa + 5120 + row * 80) + c4) =
            *((const uint4*)(g_qlo + ((size_t)b * NN + m0 + row) * CQ) + c4);

        cpa16(smaddr(smd + row * 80 + c4 * 16),
              g_khi + ((size_t)b * NN + row) * CQ + c4 * 8);
        cpa16(smaddr(smd + 5120 + row * 80 + c4 * 16),
              g_klo + ((size_t)b * NN + row) * CQ + c4 * 8);
        const __half* vsrc = g_vh + (size_t)b * NN * CCH;
#pragma unroll
        for (int i = 0; i < 8; i++) {
            const int idx = t + i * 256;
            const int vr = idx >> 5, vc = idx & 31;
            cpa16(smaddr(smd + 10240 + vr * 528 + vc * 16), vsrc + vr * CCH + vc * 8);
        }
        cpa_commit();
    }
    __syncthreads();

    unsigned qh[2][4], ql[2][4];
    {
        char* qa = smd + A_BUF + 10240;
        const int aoff = (band * 16 + (lane & 15)) * 80 + ((lane >> 4) << 4);
#pragma unroll
        for (int ks = 0; ks < 2; ks++) {
            ldsm_x4(qh[ks][0], qh[ks][1], qh[ks][2], qh[ks][3],
                    smaddr(qa + aoff + ks * 32));
            ldsm_x4(ql[ks][0], ql[ks][1], ql[ks][2], ql[ks][3],
                    smaddr(qa + 5120 + aoff + ks * 32));
        }
    }

    float acc[16][4];
#pragma unroll
    for (int g = 0; g < 16; g++)
#pragma unroll
        for (int j = 0; j < 4; j++) acc[g][j] = 0.f;
    float rmax0 = -INFINITY, rmax1 = -INFINITY, rsum0 = 0.f, rsum1 = 0.f;

    for (int nt = 0; nt < 64; nt++) {
        char* buf = smd + (nt & 1) * A_BUF;
        char* kh  = buf;
        char* kl  = buf + 5120;
        char* vb  = buf + 10240;

        cpa_wait0();
        __syncthreads();   // A: tile nt visible + all warps done PV of nt-1

        if (nt < 63) {
            char* nb = smd + ((nt + 1) & 1) * A_BUF;
            const int n1 = (nt + 1) * 64;
            cpa16(smaddr(nb + row * 80 + c4 * 16),
                  g_khi + ((size_t)b * NN + n1 + row) * CQ + c4 * 8);
            cpa16(smaddr(nb + 5120 + row * 80 + c4 * 16),
                  g_klo + ((size_t)b * NN + n1 + row) * CQ + c4 * 8);
            const __half* vsrc = g_vh + ((size_t)b * NN + n1) * CCH;
#pragma unroll
            for (int i = 0; i < 8; i++) {
                const int idx = t + i * 256;
                const int vr = idx >> 5, vc = idx & 31;
                cpa16(smaddr(nb + 10240 + vr * 528 + vc * 16),
                      vsrc + vr * CCH + vc * 8);
            }
            cpa_commit();
        }

        float sacc[4][4];
#pragma unroll
        for (int n = 0; n < 4; n++)
#pragma unroll
            for (int j = 0; j < 4; j++) sacc[n][j] = 0.f;
#pragma unroll
        for (int np = 0; np < 2; np++) {
#pragma unroll
            for (int ks = 0; ks < 2; ks++) {
                unsigned bh0, bh1, bh2, bh3, bl0, bl1, bl2, bl3;
                const int roff = (ch * 32 + np * 16 + ((lane >> 4) << 3) + (lane & 7)) * 80
                               + ks * 32 + (((lane >> 3) & 1) << 4);
                ldsm_x4(bh0, bh1, bh2, bh3, smaddr(kh + roff));
                ldsm_x4(bl0, bl1, bl2, bl3, smaddr(kl + roff));
                mma_f16(sacc[np * 2],     qh[ks], bh0, bh1);
                mma_f16(sacc[np * 2],     ql[ks], bh0, bh1);
                mma_f16(sacc[np * 2],     qh[ks], bl0, bl1);
                mma_f16(sacc[np * 2 + 1], qh[ks], bh2, bh3);
                mma_f16(sacc[np * 2 + 1], ql[ks], bh2, bh3);
                mma_f16(sacc[np * 2 + 1], qh[ks], bl2, bl3);
            }
        }

        float tm0 = fmaxf(fmaxf(sacc[0][0], sacc[0][1]), fmaxf(sacc[1][0], sacc[1][1]));
        float tm1 = fmaxf(fmaxf(sacc[0][2], sacc[0][3]), fmaxf(sacc[1][2], sacc[1][3]));
        tm0 = fmaxf(tm0, fmaxf(fmaxf(sacc[2][0], sacc[2][1]), fmaxf(sacc[3][0], sacc[3][1])));
        tm1 = fmaxf(tm1, fmaxf(fmaxf(sacc[2][2], sacc[2][3]), fmaxf(sacc[3][2], sacc[3][3])));
        tm0 = fmaxf(tm0, __shfl_xor_sync(0xffffffffu, tm0, 1));
        tm0 = fmaxf(tm0, __shfl_xor_sync(0xffffffffu, tm0, 2));
        tm1 = fmaxf(tm1, __shfl_xor_sync(0xffffffffu, tm1, 1));
        tm1 = fmaxf(tm1, __shfl_xor_sync(0xffffffffu, tm1, 2));
        if ((lane & 3) == 0) { rsx[ch * 64 + r0] = tm0; rsx[ch * 64 + r1] = tm1; }
        barw(bid);
        tm0 = fmaxf(tm0, rsx[(ch ^ 1) * 64 + r0]);
        tm1 = fmaxf(tm1, rsx[(ch ^ 1) * 64 + r1]);

        const float nm0 = fmaxf(rmax0, tm0), nm1 = fmaxf(rmax1, tm1);
        const float sc0 = exp2f(rmax0 - nm0), sc1 = exp2f(rmax1 - nm1);
        rmax0 = nm0; rmax1 = nm1;
        rsum0 *= sc0; rsum1 *= sc1;
        if (ch == 0 && (lane & 3) == 0) { scb[r0] = sc0; scb[r1] = sc1; }

        unsigned pr0[4], pr1[4];
#pragma unroll
        for (int nj = 0; nj < 4; nj++) {
            pr0[nj] = ex2h2(sacc[nj][0] - nm0, sacc[nj][1] - nm0);
            pr1[nj] = ex2h2(sacc[nj][2] - nm1, sacc[nj][3] - nm1);
            const int col = ch * 32 + nj * 8 + 2 * (lane & 3);
            *(half2*)(ph + r0 * 72 + col) = hu(pr0[nj]);
            *(half2*)(ph + r1 * 72 + col) = hu(pr1[nj]);
        }
        {
            float2 f0 = __half22float2(__hadd2(__hadd2(hu(pr0[0]), hu(pr0[1])),
                                               __hadd2(hu(pr0[2]), hu(pr0[3]))));
            float2 f1 = __half22float2(__hadd2(__hadd2(hu(pr1[0]), hu(pr1[1])),
                                               __hadd2(hu(pr1[2]), hu(pr1[3]))));
            rsum0 += f0.x + f0.y;
            rsum1 += f1.x + f1.y;
        }
        __syncthreads();   // B: P + scb ready block-wide

        {
            const int rb = qg * 32 + (lane >> 2);
            const float s0 = scb[rb],      s1 = scb[rb + 8];
            const float s2 = scb[rb + 16], s3 = scb[rb + 24];
            const bool skip = __all_sync(0xffffffffu,
                (s0 == 1.f) && (s1 == 1.f) && (s2 == 1.f) && (s3 == 1.f));
            if (!skip) {
#pragma unroll
                for (int nj = 0; nj < 8; nj++) {
                    acc[nj][0] *= s0; acc[nj][1] *= s0;
                    acc[nj][2] *= s1; acc[nj][3] *= s1;
                    acc[8 + nj][0] *= s2; acc[8 + nj][1] *= s2;
                    acc[8 + nj][2] *= s3; acc[8 + nj][3] *= s3;
                }
            }
#pragma unroll
            for (int ks = 0; ks < 4; ks++) {
                unsigned pf0[4], pf1[4];
                const int pcol = ks * 32 + ((lane >> 4) << 4);
                ldsm_x4(pf0[0], pf0[1], pf0[2], pf0[3],
                    smaddr((char*)ph + (qg * 32 + (lane & 15)) * 144 + pcol));
                ldsm_x4(pf1[0], pf1[1], pf1[2], pf1[3],
                    smaddr((char*)ph + (qg * 32 + 16 + (lane & 15)) * 144 + pcol));
                const int vrow = (ks * 16 + (lane & 15)) * 528
                               + cq * 128 + ((lane >> 4) << 4);
#pragma unroll
                for (int cc = 0; cc < 4; cc++) {
                    unsigned v0, v1, v2, v3;
                    ldsm_x4t(v0, v1, v2, v3, smaddr(vb + vrow + cc * 32));
                    mma_f16(acc[cc * 2],         pf0, v0, v1);
                    mma_f16(acc[cc * 2 + 1],     pf0, v2, v3);
                    mma_f16(acc[8 + cc * 2],     pf1, v0, v1);
                    mma_f16(acc[8 + cc * 2 + 1], pf1, v2, v3);
                }
            }
        }
    }

    rsum0 += __shfl_xor_sync(0xffffffffu, rsum0, 1);
    rsum0 += __shfl_xor_sync(0xffffffffu, rsum0, 2);
    rsum1 += __shfl_xor_sync(0xffffffffu, rsum1, 1);
    rsum1 += __shfl_xor_sync(0xffffffffu, rsum1, 2);
    if ((lane & 3) == 0) { rsx[ch * 64 + r0] = rsum0; rsx[ch * 64 + r1] = rsum1; }
    __syncthreads();
    if (ch == 0 && (lane & 3) == 0) {
        scb[r0] = 1.f / (rsum0 + rsx[64 + r0]);
        scb[r1] = 1.f / (rsum1 + rsx[64 + r1]);
    }
    __syncthreads();

    const int rb = qg * 32 + (lane >> 2);
    const float i0 = scb[rb],      i1 = scb[rb + 8];
    const float i2 = scb[rb + 16], i3 = scb[rb + 24];
#pragma unroll
    for (int nj = 0; nj < 8; nj++) {
        const int col = cq * 64 + nj * 8 + 2 * (lane & 3);
        *(half2*)(g_cat + ((size_t)b * NN + m0 + rb) * 512 + col) =
            __floats2half2_rn(acc[nj][0] * i0, acc[nj][1] * i0);
        *(half2*)(g_cat + ((size_t)b * NN + m0 + rb + 8) * 512 + col) =
            __floats2half2_rn(acc[nj][2] * i1, acc[nj][3] * i1);
        *(half2*)(g_cat + ((size_t)b * NN + m0 + rb + 16) * 512 + col) =
            __floats2half2_rn(acc[8 + nj][0] * i2, acc[8 + nj][1] * i2);
        *(half2*)(g_cat + ((size_t)b * NN + m0 + rb + 24) * 512 + col) =
            __floats2half2_rn(acc[8 + nj][2] * i3, acc[8 + nj][3] * i3);
    }
}

// ---------------------------------------------------------------------------
// Kernel 3: output projection via mma, double-buffered, 1 sync/chunk.
// Per-buffer (27648 B): As[64][72h] 9216 | Bs[128][72h] 18432. Dyn smem 55296.
// ---------------------------------------------------------------------------
#define OB 27648
#define OUT_SMEM 55296

__global__ __launch_bounds__(256) void outproj_kernel(
    const float* __restrict__ bo, float* __restrict__ y)
{
    extern __shared__ __align__(16) char smo[];

    const int b  = blockIdx.z;
    const int o0 = blockIdx.y * 64;
    const int m0 = blockIdx.x * 128;
    const int t  = threadIdx.x;
    const int lane = t & 31, wrp = t >> 5;
    const int ob = (wrp & 3) * 16;
    const int mh = (wrp >> 2) * 64;

    float acc[8][4];
#pragma unroll
    for (int i = 0; i < 8; i++)
#pragma unroll
        for (int j = 0; j < 4; j++) acc[i][j] = 0.f;

    // issue chunk 0 into buf0
    {
#pragma unroll
        for (int i = 0; i < 2; i++) {
            const int idx = t + i * 256;
            const int rowi = idx >> 3, c16 = idx & 7;
            cpa16(smaddr(smo + rowi * 144 + c16 * 16),
                  g_woh + (size_t)(o0 + rowi) * 512 + c16 * 8);
        }
#pragma unroll
        for (int i = 0; i < 4; i++) {
            const int idx = t + i * 256;
            const int rowi = idx >> 3, c16 = idx & 7;
            cpa16(smaddr(smo + 9216 + rowi * 144 + c16 * 16),
                  g_cat + ((size_t)b * NN + m0 + rowi) * 512 + c16 * 8);
        }
        cpa_commit();
    }

    for (int kci = 0; kci < 8; kci++) {
        char* buf = smo + (kci & 1) * OB;
        __half* As = (__half*)buf;
        __half* Bs = (__half*)(buf + 9216);

        cpa_wait0();
        __syncthreads();

        if (kci < 7) {
            char* nb = smo + ((kci + 1) & 1) * OB;
            const int k1 = (kci + 1) * 64;
#pragma unroll
            for (int i = 0; i < 2; i++) {
                const int idx = t + i * 256;
                const int rowi = idx >> 3, c16 = idx & 7;
                cpa16(smaddr(nb + rowi * 144 + c16 * 16),
                      g_woh + (size_t)(o0 + rowi) * 512 + k1 + c16 * 8);
            }
#pragma unroll
            for (int i = 0; i < 4; i++) {
                const int idx = t + i * 256;
                const int rowi = idx >> 3, c16 = idx & 7;
                cpa16(smaddr(nb + 9216 + rowi * 144 + c16 * 16),
                      g_cat + ((size_t)b * NN + m0 + rowi) * 512 + k1 + c16 * 8);
            }
            cpa_commit();
        }

        unsigned int af[4][4];
#pragma unroll
        for (int k4 = 0; k4 < 4; k4++) {
            unsigned int a = smaddr(As + (ob + (lane & 15)) * 72 + k4 * 16 + (lane >> 4) * 8);
            ldsm_x4(af[k4][0], af[k4][1], af[k4][2], af[k4][3], a);
        }
#pragma unroll
        for (int pr = 0; pr < 4; pr++) {
#pragma unroll
            for (int k4 = 0; k4 < 4; k4++) {
                unsigned int b0, b1, b2, b3;
                unsigned int a = smaddr(Bs + (mh + pr * 16 + (lane >> 4) * 8 + (lane & 7)) * 72
                                           + k4 * 16 + ((lane >> 3) & 1) * 8);
                ldsm_x4(b0, b1, b2, b3, a);
                mma_f16(acc[pr * 2],     af[k4], b0, b1);
                mma_f16(acc[pr * 2 + 1], af[k4], b2, b3);
            }
        }
        // no trailing sync: next iteration's leading sync covers buffer reuse
    }

    const int orow = o0 + ob + (lane >> 2);
    const float bi0 = bo[orow], bi1 = bo[orow + 8];
#pragma unroll
    for (int chn = 0; chn < 8; chn++) {
        const int m = m0 + mh + chn * 8 + (lane & 3) * 2;
        float2 v0, v1;
        v0.x = acc[chn][0] + bi0; v0.y = acc[chn][1] + bi0;
        v1.x = acc[chn][2] + bi1; v1.y = acc[chn][3] + bi1;
        *(float2*)(y + ((size_t)b * CCH + orow)     * NN + m) = v0;
        *(float2*)(y + ((size_t)b * CCH + orow + 8) * NN + m) = v1;
    }
}

// ---------------------------------------------------------------------------
extern "C" void kernel_launch(void* const* d_in, const int* in_sizes, int n_in,
                              void* d_out, int out_size)
{
    const float* x  = (const float*)d_in[0];
    const float* Wq = (const float*)d_in[1];
    const float* bq = (const float*)d_in[2];
    const float* Wk = (const float*)d_in[3];
    const float* bk = (const float*)d_in[4];
    const float* Wv = (const float*)d_in[5];
    const float* bv = (const float*)d_in[6];
    const float* Wo = (const float*)d_in[7];
    const float* bo = (const float*)d_in[8];
    float* y = (float*)d_out;

    cudaFuncSetAttribute(attn_kernel,
                         cudaFuncAttributeMaxDynamicSharedMemorySize, ATTN_SMEM);
    cudaFuncSetAttribute(qkv_mma_kernel,
                         cudaFuncAttributeMaxDynamicSharedMemorySize, QKV_SMEM);
    cudaFuncSetAttribute(outproj_kernel,
                         cudaFuncAttributeMaxDynamicSharedMemorySize, OUT_SMEM);

    wprep_kernel<<<832, 256>>>(Wo, Wq, bq, Wk, bk, Wv, bv);
    xpose_kernel<<<dim3(128, 8, BB), dim3(32, 8)>>>(x);
    qkv_mma_kernel<<<dim3(32, 5, BB), 256, QKV_SMEM>>>();
    attn_kernel<<<dim3(64, BB), 256, ATTN_SMEM>>>();
    outproj_kernel<<<dim3(32, 4, BB), 256, OUT_SMEM>>>(bo, y);
}